// round 1
// baseline (speedup 1.0000x reference)
#include <cuda_runtime.h>
#include <cuda_bf16.h>
#include <cstdint>

// Problem constants (fixed by the reference)
#define B_ 2
#define T_ 2048
#define C_ 1024
#define H_ 16
#define D_ 64
#define M_ROWS (B_ * T_)     // 4096
#define N_QKV  (3 * C_)      // 3072

// Scratch (allocation-free rule: __device__ globals)
__device__ float g_qkv[(size_t)M_ROWS * N_QKV];   // [B*T, 3C]
__device__ float g_att[(size_t)M_ROWS * C_];      // [B*T, C]

// ---------------------------------------------------------------------------
// Tiled SGEMM + bias: C[M,N] = A[M,K] @ B[K,N] + bias[N]
// BM=BN=128, BK=8, 256 threads, 8x8 microtile per thread.
// Assumes M%128==0, N%128==0, K%8==0 (true for all three calls).
// ---------------------------------------------------------------------------
#define BM 128
#define BN 128
#define BKK 8

__global__ __launch_bounds__(256)
void sgemm_bias(const float* __restrict__ A, const float* __restrict__ B,
                const float* __restrict__ bias, float* __restrict__ C,
                int M, int N, int K)
{
    __shared__ __align__(16) float As[BKK][BM];
    __shared__ __align__(16) float Bs[BKK][BN];

    const int tid = threadIdx.x;
    const int tx  = tid & 15;        // 0..15 (N dir)
    const int ty  = tid >> 4;        // 0..15 (M dir)
    const int rowBase = blockIdx.y * BM;
    const int colBase = blockIdx.x * BN;

    // A load: each thread one float4. 128 rows x 8 cols = 256 float4.
    const int aRow = tid >> 1;            // 0..127
    const int aCol = (tid & 1) * 4;       // 0 or 4
    // B load: 8 rows x 128 cols = 256 float4.
    const int bRow = tid >> 5;            // 0..7
    const int bCol = (tid & 31) * 4;      // 0..124

    float acc[8][8];
#pragma unroll
    for (int i = 0; i < 8; i++)
#pragma unroll
        for (int j = 0; j < 8; j++) acc[i][j] = 0.f;

    for (int k0 = 0; k0 < K; k0 += BKK) {
        float4 a4 = *(const float4*)(A + (size_t)(rowBase + aRow) * K + k0 + aCol);
        As[aCol + 0][aRow] = a4.x;
        As[aCol + 1][aRow] = a4.y;
        As[aCol + 2][aRow] = a4.z;
        As[aCol + 3][aRow] = a4.w;
        *(float4*)(&Bs[bRow][bCol]) =
            *(const float4*)(B + (size_t)(k0 + bRow) * N + colBase + bCol);
        __syncthreads();

#pragma unroll
        for (int kk = 0; kk < BKK; kk++) {
            float a[8], b[8];
#pragma unroll
            for (int i = 0; i < 4; i++) {
                ((float4*)a)[0] = *(const float4*)(&As[kk][ty * 8]);
                ((float4*)a)[1] = *(const float4*)(&As[kk][ty * 8 + 4]);
                ((float4*)b)[0] = *(const float4*)(&Bs[kk][tx * 8]);
                ((float4*)b)[1] = *(const float4*)(&Bs[kk][tx * 8 + 4]);
                break;
            }
#pragma unroll
            for (int i = 0; i < 8; i++)
#pragma unroll
                for (int j = 0; j < 8; j++)
                    acc[i][j] = fmaf(a[i], b[j], acc[i][j]);
        }
        __syncthreads();
    }

#pragma unroll
    for (int i = 0; i < 8; i++) {
        const int r = rowBase + ty * 8 + i;
#pragma unroll
        for (int j = 0; j < 8; j += 4) {
            const int c = colBase + tx * 8 + j;
            float4 o;
            o.x = acc[i][j + 0] + bias[c + 0];
            o.y = acc[i][j + 1] + bias[c + 1];
            o.z = acc[i][j + 2] + bias[c + 2];
            o.w = acc[i][j + 3] + bias[c + 3];
            *(float4*)(C + (size_t)r * N + c) = o;
        }
    }
}

// ---------------------------------------------------------------------------
// Causal attention with streaming online softmax.
// 1 thread = 1 query row. Block = 128 query rows of one (b,h).
// K/V staged in 64x64 smem tiles; broadcast LDS reads (all lanes same row j).
// ---------------------------------------------------------------------------
__global__ __launch_bounds__(128)
void attn_kernel(const float* __restrict__ qkv, float* __restrict__ out)
{
    __shared__ __align__(16) float Ks[64][64];
    __shared__ __align__(16) float Vs[64][64];

    const int b = blockIdx.z;
    const int h = blockIdx.y;
    const int qrow = blockIdx.x * 128 + threadIdx.x;   // 0..T-1 within batch
    const int tid = threadIdx.x;

    const float* base = qkv + (size_t)b * T_ * (3 * C_);

    // Load q row into registers
    float q[D_];
    {
        const float* qp = base + (size_t)qrow * (3 * C_) + h * D_;
#pragma unroll
        for (int d = 0; d < D_; d += 4) {
            float4 v = *(const float4*)(qp + d);
            q[d] = v.x; q[d + 1] = v.y; q[d + 2] = v.z; q[d + 3] = v.w;
        }
    }

    float m = -1e30f, l = 0.f;
    float acc[D_];
#pragma unroll
    for (int d = 0; d < D_; d++) acc[d] = 0.f;

    const int ntiles = blockIdx.x * 2 + 2;   // tiles of 64 keys covering [0, qmax]

    for (int kt = 0; kt < ntiles; kt++) {
        // Cooperative load of K and V 64x64 tiles (1024 float4 each / 128 thr)
#pragma unroll
        for (int it = 0; it < 8; it++) {
            int idx = it * 128 + tid;       // 0..1023
            int r   = idx >> 4;             // 0..63
            int c4  = (idx & 15) * 4;       // 0..60
            const float* kp = base + (size_t)(kt * 64 + r) * (3 * C_) + C_ + h * D_ + c4;
            *(float4*)(&Ks[r][c4]) = *(const float4*)kp;
            *(float4*)(&Vs[r][c4]) = *(const float4*)(kp + C_);
        }
        __syncthreads();

        int jmax = qrow - kt * 64 + 1;
        if (jmax > 64) jmax = 64;

        for (int j = 0; j < jmax; j++) {
            float s = 0.f;
#pragma unroll
            for (int d = 0; d < D_; d++) s = fmaf(q[d], Ks[j][d], s);
            s *= 0.125f;   // 1/sqrt(64)

            if (s > m) {
                float rsc = __expf(m - s);
                l *= rsc;
#pragma unroll
                for (int d = 0; d < D_; d++) acc[d] *= rsc;
                m = s;
            }
            float p = __expf(s - m);
            l += p;
#pragma unroll
            for (int d = 0; d < D_; d++) acc[d] = fmaf(p, Vs[j][d], acc[d]);
        }
        __syncthreads();
    }

    const float inv = 1.f / l;
    float* op = out + (size_t)(b * T_ + qrow) * C_ + h * D_;
#pragma unroll
    for (int d = 0; d < D_; d += 4) {
        float4 o;
        o.x = acc[d] * inv; o.y = acc[d + 1] * inv;
        o.z = acc[d + 2] * inv; o.w = acc[d + 3] * inv;
        *(float4*)(op + d) = o;
    }
}

// ---------------------------------------------------------------------------
// Launch: QKV GEMM -> attention -> proj GEMM
// ---------------------------------------------------------------------------
extern "C" void kernel_launch(void* const* d_in, const int* in_sizes, int n_in,
                              void* d_out, int out_size)
{
    const float* x      = (const float*)d_in[0];
    const float* w_qkv  = (const float*)d_in[1];
    const float* b_qkv  = (const float*)d_in[2];
    const float* w_proj = (const float*)d_in[3];
    const float* b_proj = (const float*)d_in[4];
    float* out = (float*)d_out;

    float* qkv_buf = nullptr;
    float* att_buf = nullptr;
    cudaGetSymbolAddress((void**)&qkv_buf, g_qkv);
    cudaGetSymbolAddress((void**)&att_buf, g_att);

    // 1) QKV projection: [4096,1024] @ [1024,3072] + b
    {
        dim3 grid(N_QKV / BN, M_ROWS / BM);
        sgemm_bias<<<grid, 256>>>(x, w_qkv, b_qkv, qkv_buf, M_ROWS, N_QKV, C_);
    }

    // 2) Causal attention
    {
        dim3 grid(T_ / 128, H_, B_);
        attn_kernel<<<grid, 128>>>(qkv_buf, att_buf);
    }

    // 3) Output projection: [4096,1024] @ [1024,1024] + b
    {
        dim3 grid(C_ / BN, M_ROWS / BM);
        sgemm_bias<<<grid, 256>>>(att_buf, w_proj, b_proj, out, M_ROWS, C_, C_);
    }
}

// round 3
// speedup vs baseline: 1.3339x; 1.3339x over previous
#include <cuda_runtime.h>
#include <cuda_bf16.h>
#include <cstdint>

// ---------------------------------------------------------------------------
// Problem constants
// ---------------------------------------------------------------------------
#define B_ 2
#define T_ 2048
#define C_ 1024
#define H_ 16
#define D_ 64
#define M_ROWS (B_ * T_)     // 4096
#define N_QKV  (3 * C_)      // 3072

// Scratch (__device__ globals; allocation-free rule)
__device__ float g_qkv[(size_t)M_ROWS * N_QKV];            // [B*T, 3C]
__device__ float g_att[(size_t)M_ROWS * C_];               // [B*T, C]
__device__ __nv_bfloat16 g_xhi[(size_t)M_ROWS * C_];       // activations hi
__device__ __nv_bfloat16 g_xlo[(size_t)M_ROWS * C_];       // activations lo
__device__ __nv_bfloat16 g_wthi[(size_t)N_QKV * C_];       // W^T hi [N,K]
__device__ __nv_bfloat16 g_wtlo[(size_t)N_QKV * C_];       // W^T lo [N,K]

// ---------------------------------------------------------------------------
// Warp MMA helpers (sm_80+ baseline: no arch-'a' features needed)
// ---------------------------------------------------------------------------
__device__ __forceinline__ uint32_t smem_to_u32(const void* p) {
    uint32_t a;
    asm("{ .reg .u64 t; cvta.to.shared.u64 t, %1; cvt.u32.u64 %0, t; }"
        : "=r"(a) : "l"(p));
    return a;
}

__device__ __forceinline__ void ldsm_x4(uint32_t (&r)[4], uint32_t addr) {
    asm volatile("ldmatrix.sync.aligned.m8n8.x4.shared.b16 {%0,%1,%2,%3}, [%4];"
                 : "=r"(r[0]), "=r"(r[1]), "=r"(r[2]), "=r"(r[3]) : "r"(addr));
}

__device__ __forceinline__ void mma16816(float (&d)[4],
                                         const uint32_t (&a)[4],
                                         const uint32_t b0, const uint32_t b1) {
    asm volatile(
        "mma.sync.aligned.m16n8k16.row.col.f32.bf16.bf16.f32 "
        "{%0,%1,%2,%3}, {%4,%5,%6,%7}, {%8,%9}, {%0,%1,%2,%3};"
        : "+f"(d[0]), "+f"(d[1]), "+f"(d[2]), "+f"(d[3])
        : "r"(a[0]), "r"(a[1]), "r"(a[2]), "r"(a[3]), "r"(b0), "r"(b1));
}

// XOR swizzle for 128-byte smem rows (conflict-free ldmatrix)
__device__ __forceinline__ uint32_t swz(uint32_t off) {
    return off ^ ((off >> 3) & 0x70);
}

// ---------------------------------------------------------------------------
// Prepass 1: split fp32 -> (bf16 hi, bf16 lo).  4 elems / thread.
// ---------------------------------------------------------------------------
__global__ __launch_bounds__(256)
void cvt_split(const float* __restrict__ src,
               __nv_bfloat16* __restrict__ hi, __nv_bfloat16* __restrict__ lo, int n4)
{
    int i = blockIdx.x * 256 + threadIdx.x;
    if (i >= n4) return;
    float4 v = ((const float4*)src)[i];
    __nv_bfloat162 h01 = __floats2bfloat162_rn(v.x, v.y);
    __nv_bfloat162 h23 = __floats2bfloat162_rn(v.z, v.w);
    float rx = v.x - __bfloat162float(h01.x);
    float ry = v.y - __bfloat162float(h01.y);
    float rz = v.z - __bfloat162float(h23.x);
    float rw = v.w - __bfloat162float(h23.y);
    __nv_bfloat162 l01 = __floats2bfloat162_rn(rx, ry);
    __nv_bfloat162 l23 = __floats2bfloat162_rn(rz, rw);
    ((__nv_bfloat162*)hi)[i * 2 + 0] = h01;
    ((__nv_bfloat162*)hi)[i * 2 + 1] = h23;
    ((__nv_bfloat162*)lo)[i * 2 + 0] = l01;
    ((__nv_bfloat162*)lo)[i * 2 + 1] = l23;
}

// ---------------------------------------------------------------------------
// Prepass 2: W [K,N] fp32 -> W^T hi/lo [N,K] bf16, 32x32 smem tile transpose.
// ---------------------------------------------------------------------------
__global__ __launch_bounds__(256)
void wsplit_transpose(const float* __restrict__ W,
                      __nv_bfloat16* __restrict__ Thi, __nv_bfloat16* __restrict__ Tlo,
                      int K, int N)
{
    __shared__ float tile[32][33];
    const int tx = threadIdx.x & 31;
    const int ty = threadIdx.x >> 5;
    const int k0 = blockIdx.y * 32;
    const int n0 = blockIdx.x * 32;
#pragma unroll
    for (int r = ty; r < 32; r += 8)
        tile[r][tx] = W[(size_t)(k0 + r) * N + n0 + tx];
    __syncthreads();
#pragma unroll
    for (int r = ty; r < 32; r += 8) {
        float v = tile[tx][r];
        __nv_bfloat16 h = __float2bfloat16(v);
        __nv_bfloat16 l = __float2bfloat16(v - __bfloat162float(h));
        size_t o = (size_t)(n0 + r) * K + k0 + tx;
        Thi[o] = h;
        Tlo[o] = l;
    }
}

// ---------------------------------------------------------------------------
// HMMA GEMM, split-bf16 x3:  C[M,N] = A[M,K] @ (Bt[N,K])^T + bias
// CTA tile 128x128, 8 warps of 64x32, BK=64 (128B rows, XOR swizzle).
// ---------------------------------------------------------------------------
#define SM_AHI 0
#define SM_ALO 16384
#define SM_BHI 32768
#define SM_BLO 49152
#define SM_TOTAL 65536

__global__ __launch_bounds__(256)
void gemm_bf16x3(const __nv_bfloat16* __restrict__ Ahi, const __nv_bfloat16* __restrict__ Alo,
                 const __nv_bfloat16* __restrict__ Bhi, const __nv_bfloat16* __restrict__ Blo,
                 const float* __restrict__ bias, float* __restrict__ Cout,
                 int M, int N, int K)
{
    extern __shared__ char smem[];
    const uint32_t sb = smem_to_u32(smem);

    const int tid  = threadIdx.x;
    const int wid  = tid >> 5;
    const int lane = tid & 31;
    const int rowBase = blockIdx.y * 128;
    const int colBase = blockIdx.x * 128;

    const int warp_m = wid & 1;        // 0..1 -> 64-row halves
    const int warp_n = wid >> 1;       // 0..3 -> 32-col quarters

    float acc[4][4][4];                // [mi][nj][reg]
#pragma unroll
    for (int i = 0; i < 4; i++)
#pragma unroll
        for (int j = 0; j < 4; j++)
#pragma unroll
            for (int r = 0; r < 4; r++) acc[i][j][r] = 0.f;

    // ldmatrix smem addresses (per-lane, fixed row/col pattern per k-step)
    // A: lanes 0-15 -> rows +0..15 @ kseg0(16B); lanes 16-31 -> same rows @ +16B
    const int a_r  = warp_m * 64 + (lane & 15);
    const int a_cb = (lane >> 4) << 4;
    // B: g=lane>>3: m0=n0-7@k0, m1=n0-7@k8, m2=n8-15@k0, m3=n8-15@k8
    const int g    = lane >> 3;
    const int b_r  = warp_n * 32 + ((g >> 1) << 3) + (lane & 7);
    const int b_cb = (g & 1) << 4;

    const int nChunks = K / 64;
    for (int ch = 0; ch < nChunks; ch++) {
        const int k0 = ch * 64;
        // Cooperative load: 4 tiles of 128 rows x 128B, swizzled.
#pragma unroll
        for (int it = 0; it < 4; it++) {
            int idx = it * 256 + tid;          // 0..1023
            int r   = idx >> 3;                // row 0..127
            int cb  = (idx & 7) << 4;          // 0..112
            uint32_t sw = swz((uint32_t)(r * 128 + cb));
            const char* pa = (const char*)(Ahi + (size_t)(rowBase + r) * K + k0) + cb;
            const char* pb = (const char*)(Alo + (size_t)(rowBase + r) * K + k0) + cb;
            const char* pc = (const char*)(Bhi + (size_t)(colBase + r) * K + k0) + cb;
            const char* pd = (const char*)(Blo + (size_t)(colBase + r) * K + k0) + cb;
            *(uint4*)(smem + SM_AHI + sw) = *(const uint4*)pa;
            *(uint4*)(smem + SM_ALO + sw) = *(const uint4*)pb;
            *(uint4*)(smem + SM_BHI + sw) = *(const uint4*)pc;
            *(uint4*)(smem + SM_BLO + sw) = *(const uint4*)pd;
        }
        __syncthreads();

#pragma unroll
        for (int ks = 0; ks < 4; ks++) {
            const int kb = ks * 32;
            uint32_t ah[4][4], al[4][4];
#pragma unroll
            for (int mi = 0; mi < 4; mi++) {
                uint32_t off = swz((uint32_t)((a_r + mi * 16) * 128 + kb + a_cb));
                ldsm_x4(ah[mi], sb + SM_AHI + off);
                ldsm_x4(al[mi], sb + SM_ALO + off);
            }
            uint32_t bh[2][4], bl[2][4];
#pragma unroll
            for (int nt = 0; nt < 2; nt++) {
                uint32_t off = swz((uint32_t)((b_r + nt * 16) * 128 + kb + b_cb));
                ldsm_x4(bh[nt], sb + SM_BHI + off);
                ldsm_x4(bl[nt], sb + SM_BLO + off);
            }
#pragma unroll
            for (int mi = 0; mi < 4; mi++)
#pragma unroll
                for (int nj = 0; nj < 4; nj++) {
                    const uint32_t* bhj = &bh[nj >> 1][(nj & 1) * 2];
                    const uint32_t* blj = &bl[nj >> 1][(nj & 1) * 2];
                    mma16816(acc[mi][nj], ah[mi], bhj[0], bhj[1]);
                    mma16816(acc[mi][nj], ah[mi], blj[0], blj[1]);
                    mma16816(acc[mi][nj], al[mi], bhj[0], bhj[1]);
                }
        }
        __syncthreads();
    }

    // Epilogue: acc[mi][nj] tile (m16n8): reg0/1 -> row lane>>2, reg2/3 -> +8,
    // cols (lane&3)*2, +1.
    const int er = rowBase + warp_m * 64 + (lane >> 2);
    const int ec = colBase + warp_n * 32 + (lane & 3) * 2;
#pragma unroll
    for (int mi = 0; mi < 4; mi++) {
#pragma unroll
        for (int nj = 0; nj < 4; nj++) {
            const int c = ec + nj * 8;
            const float bx = __ldg(bias + c);
            const float by = __ldg(bias + c + 1);
            float2 v0 = { acc[mi][nj][0] + bx, acc[mi][nj][1] + by };
            float2 v1 = { acc[mi][nj][2] + bx, acc[mi][nj][3] + by };
            *(float2*)(Cout + (size_t)(er + mi * 16) * N + c) = v0;
            *(float2*)(Cout + (size_t)(er + mi * 16 + 8) * N + c) = v1;
        }
    }
}

// ---------------------------------------------------------------------------
// Causal attention, streaming online softmax (proven R0 kernel).
// ---------------------------------------------------------------------------
__global__ __launch_bounds__(128)
void attn_kernel(const float* __restrict__ qkv, float* __restrict__ out)
{
    __shared__ __align__(16) float Ks[64][64];
    __shared__ __align__(16) float Vs[64][64];

    const int b = blockIdx.z;
    const int h = blockIdx.y;
    const int qrow = blockIdx.x * 128 + threadIdx.x;
    const int tid = threadIdx.x;

    const float* base = qkv + (size_t)b * T_ * (3 * C_);

    float q[D_];
    {
        const float* qp = base + (size_t)qrow * (3 * C_) + h * D_;
#pragma unroll
        for (int d = 0; d < D_; d += 4) {
            float4 v = *(const float4*)(qp + d);
            q[d] = v.x; q[d + 1] = v.y; q[d + 2] = v.z; q[d + 3] = v.w;
        }
    }

    float m = -1e30f, l = 0.f;
    float acc[D_];
#pragma unroll
    for (int d = 0; d < D_; d++) acc[d] = 0.f;

    const int ntiles = blockIdx.x * 2 + 2;

    for (int kt = 0; kt < ntiles; kt++) {
#pragma unroll
        for (int it = 0; it < 8; it++) {
            int idx = it * 128 + tid;
            int r   = idx >> 4;
            int c4  = (idx & 15) * 4;
            const float* kp = base + (size_t)(kt * 64 + r) * (3 * C_) + C_ + h * D_ + c4;
            *(float4*)(&Ks[r][c4]) = *(const float4*)kp;
            *(float4*)(&Vs[r][c4]) = *(const float4*)(kp + C_);
        }
        __syncthreads();

        int jmax = qrow - kt * 64 + 1;
        if (jmax > 64) jmax = 64;

        for (int j = 0; j < jmax; j++) {
            float s = 0.f;
#pragma unroll
            for (int d = 0; d < D_; d++) s = fmaf(q[d], Ks[j][d], s);
            s *= 0.125f;

            if (s > m) {
                float rsc = __expf(m - s);
                l *= rsc;
#pragma unroll
                for (int d = 0; d < D_; d++) acc[d] *= rsc;
                m = s;
            }
            float p = __expf(s - m);
            l += p;
#pragma unroll
            for (int d = 0; d < D_; d++) acc[d] = fmaf(p, Vs[j][d], acc[d]);
        }
        __syncthreads();
    }

    const float inv = 1.f / l;
    float* op = out + (size_t)(b * T_ + qrow) * C_ + h * D_;
#pragma unroll
    for (int d = 0; d < D_; d += 4) {
        float4 o;
        o.x = acc[d] * inv; o.y = acc[d + 1] * inv;
        o.z = acc[d + 2] * inv; o.w = acc[d + 3] * inv;
        *(float4*)(op + d) = o;
    }
}

// ---------------------------------------------------------------------------
// Launch sequence
// ---------------------------------------------------------------------------
extern "C" void kernel_launch(void* const* d_in, const int* in_sizes, int n_in,
                              void* d_out, int out_size)
{
    const float* x      = (const float*)d_in[0];
    const float* w_qkv  = (const float*)d_in[1];
    const float* b_qkv  = (const float*)d_in[2];
    const float* w_proj = (const float*)d_in[3];
    const float* b_proj = (const float*)d_in[4];
    float* out = (float*)d_out;

    float *qkv_buf, *att_buf;
    __nv_bfloat16 *xhi, *xlo, *wthi, *wtlo;
    cudaGetSymbolAddress((void**)&qkv_buf, g_qkv);
    cudaGetSymbolAddress((void**)&att_buf, g_att);
    cudaGetSymbolAddress((void**)&xhi, g_xhi);
    cudaGetSymbolAddress((void**)&xlo, g_xlo);
    cudaGetSymbolAddress((void**)&wthi, g_wthi);
    cudaGetSymbolAddress((void**)&wtlo, g_wtlo);

    cudaFuncSetAttribute(gemm_bf16x3, cudaFuncAttributeMaxDynamicSharedMemorySize, SM_TOTAL);

    // 1) split x -> bf16 hi/lo
    {
        int n4 = (M_ROWS * C_) / 4;
        cvt_split<<<(n4 + 255) / 256, 256>>>(x, xhi, xlo, n4);
    }
    // 2) transpose+split w_qkv: [1024,3072] -> [3072,1024]
    {
        dim3 grid(N_QKV / 32, C_ / 32);
        wsplit_transpose<<<grid, 256>>>(w_qkv, wthi, wtlo, C_, N_QKV);
    }
    // 3) QKV GEMM (HMMA)
    {
        dim3 grid(N_QKV / 128, M_ROWS / 128);
        gemm_bf16x3<<<grid, 256, SM_TOTAL>>>(xhi, xlo, wthi, wtlo, b_qkv, qkv_buf,
                                             M_ROWS, N_QKV, C_);
    }
    // 4) attention
    {
        dim3 grid(T_ / 128, H_, B_);
        attn_kernel<<<grid, 128>>>(qkv_buf, att_buf);
    }
    // 5) split att -> bf16 hi/lo (reuse x buffers)
    {
        int n4 = (M_ROWS * C_) / 4;
        cvt_split<<<(n4 + 255) / 256, 256>>>(att_buf, xhi, xlo, n4);
    }
    // 6) transpose+split w_proj: [1024,1024] -> [1024,1024]
    {
        dim3 grid(C_ / 32, C_ / 32);
        wsplit_transpose<<<grid, 256>>>(w_proj, wthi, wtlo, C_, C_);
    }
    // 7) proj GEMM (HMMA)
    {
        dim3 grid(C_ / 128, M_ROWS / 128);
        gemm_bf16x3<<<grid, 256, SM_TOTAL>>>(xhi, xlo, wthi, wtlo, b_proj, out,
                                             M_ROWS, C_, C_);
    }
}

// round 4
// speedup vs baseline: 2.9803x; 2.2344x over previous
#include <cuda_runtime.h>
#include <cuda_bf16.h>
#include <cstdint>

// ---------------------------------------------------------------------------
// Problem constants
// ---------------------------------------------------------------------------
#define B_ 2
#define T_ 2048
#define C_ 1024
#define H_ 16
#define D_ 64
#define M_ROWS (B_ * T_)     // 4096
#define N_QKV  (3 * C_)      // 3072

// scale*log2(e) folded into Q: (1/8) * 1.4426950408889634
#define QS 0.18033688011112042f

// Scratch (__device__ globals; allocation-free rule)
__device__ float g_qkv[(size_t)M_ROWS * N_QKV];            // [B*T, 3C] fp32
__device__ float g_att[(size_t)M_ROWS * C_];               // [B*T, C]  fp32
__device__ __nv_bfloat16 g_xhi[(size_t)M_ROWS * C_];
__device__ __nv_bfloat16 g_xlo[(size_t)M_ROWS * C_];
__device__ __nv_bfloat16 g_wthi[(size_t)N_QKV * C_];
__device__ __nv_bfloat16 g_wtlo[(size_t)N_QKV * C_];
// per-head bf16 hi/lo [B,H,T,D]
__device__ __nv_bfloat16 g_qh[(size_t)B_ * H_ * T_ * D_];
__device__ __nv_bfloat16 g_ql[(size_t)B_ * H_ * T_ * D_];
__device__ __nv_bfloat16 g_kh[(size_t)B_ * H_ * T_ * D_];
__device__ __nv_bfloat16 g_kl[(size_t)B_ * H_ * T_ * D_];
__device__ __nv_bfloat16 g_vh[(size_t)B_ * H_ * T_ * D_];
__device__ __nv_bfloat16 g_vl[(size_t)B_ * H_ * T_ * D_];

// ---------------------------------------------------------------------------
// Warp MMA helpers (sm_80+ baseline: no arch-'a' features)
// ---------------------------------------------------------------------------
__device__ __forceinline__ uint32_t smem_to_u32(const void* p) {
    uint32_t a;
    asm("{ .reg .u64 t; cvta.to.shared.u64 t, %1; cvt.u32.u64 %0, t; }"
        : "=r"(a) : "l"(p));
    return a;
}
__device__ __forceinline__ void ldsm_x4(uint32_t (&r)[4], uint32_t addr) {
    asm volatile("ldmatrix.sync.aligned.m8n8.x4.shared.b16 {%0,%1,%2,%3}, [%4];"
                 : "=r"(r[0]), "=r"(r[1]), "=r"(r[2]), "=r"(r[3]) : "r"(addr));
}
__device__ __forceinline__ void ldsm_x4_t(uint32_t (&r)[4], uint32_t addr) {
    asm volatile("ldmatrix.sync.aligned.m8n8.x4.trans.shared.b16 {%0,%1,%2,%3}, [%4];"
                 : "=r"(r[0]), "=r"(r[1]), "=r"(r[2]), "=r"(r[3]) : "r"(addr));
}
__device__ __forceinline__ void mma16816(float (&d)[4],
                                         const uint32_t (&a)[4],
                                         const uint32_t b0, const uint32_t b1) {
    asm volatile(
        "mma.sync.aligned.m16n8k16.row.col.f32.bf16.bf16.f32 "
        "{%0,%1,%2,%3}, {%4,%5,%6,%7}, {%8,%9}, {%0,%1,%2,%3};"
        : "+f"(d[0]), "+f"(d[1]), "+f"(d[2]), "+f"(d[3])
        : "r"(a[0]), "r"(a[1]), "r"(a[2]), "r"(a[3]), "r"(b0), "r"(b1));
}
__device__ __forceinline__ uint32_t swz(uint32_t off) {
    return off ^ ((off >> 3) & 0x70);
}
__device__ __forceinline__ float ex2(float x) {
    float y; asm("ex2.approx.ftz.f32 %0, %1;" : "=f"(y) : "f"(x)); return y;
}

// ---------------------------------------------------------------------------
// Prepass 1: split fp32 -> (bf16 hi, bf16 lo)
// ---------------------------------------------------------------------------
__global__ __launch_bounds__(256)
void cvt_split(const float* __restrict__ src,
               __nv_bfloat16* __restrict__ hi, __nv_bfloat16* __restrict__ lo, int n4)
{
    int i = blockIdx.x * 256 + threadIdx.x;
    if (i >= n4) return;
    float4 v = ((const float4*)src)[i];
    __nv_bfloat162 h01 = __floats2bfloat162_rn(v.x, v.y);
    __nv_bfloat162 h23 = __floats2bfloat162_rn(v.z, v.w);
    __nv_bfloat162 l01 = __floats2bfloat162_rn(v.x - __bfloat162float(h01.x),
                                               v.y - __bfloat162float(h01.y));
    __nv_bfloat162 l23 = __floats2bfloat162_rn(v.z - __bfloat162float(h23.x),
                                               v.w - __bfloat162float(h23.y));
    ((__nv_bfloat162*)hi)[i * 2 + 0] = h01;
    ((__nv_bfloat162*)hi)[i * 2 + 1] = h23;
    ((__nv_bfloat162*)lo)[i * 2 + 0] = l01;
    ((__nv_bfloat162*)lo)[i * 2 + 1] = l23;
}

// ---------------------------------------------------------------------------
// Prepass 2: W [K,N] fp32 -> W^T hi/lo [N,K] bf16
// ---------------------------------------------------------------------------
__global__ __launch_bounds__(256)
void wsplit_transpose(const float* __restrict__ W,
                      __nv_bfloat16* __restrict__ Thi, __nv_bfloat16* __restrict__ Tlo,
                      int K, int N)
{
    __shared__ float tile[32][33];
    const int tx = threadIdx.x & 31;
    const int ty = threadIdx.x >> 5;
    const int k0 = blockIdx.y * 32;
    const int n0 = blockIdx.x * 32;
#pragma unroll
    for (int r = ty; r < 32; r += 8)
        tile[r][tx] = W[(size_t)(k0 + r) * N + n0 + tx];
    __syncthreads();
#pragma unroll
    for (int r = ty; r < 32; r += 8) {
        float v = tile[tx][r];
        __nv_bfloat16 h = __float2bfloat16(v);
        __nv_bfloat16 l = __float2bfloat16(v - __bfloat162float(h));
        size_t o = (size_t)(n0 + r) * K + k0 + tx;
        Thi[o] = h;
        Tlo[o] = l;
    }
}

// ---------------------------------------------------------------------------
// qkv fp32 [B*T, 3C] -> per-head bf16 hi/lo [B,H,T,D]; Q pre-scaled by QS.
// ---------------------------------------------------------------------------
__global__ __launch_bounds__(256)
void cvt_qkv(const float* __restrict__ qkv,
             __nv_bfloat16* __restrict__ qh, __nv_bfloat16* __restrict__ ql,
             __nv_bfloat16* __restrict__ kh, __nv_bfloat16* __restrict__ kl,
             __nv_bfloat16* __restrict__ vh, __nv_bfloat16* __restrict__ vl)
{
    int gid = blockIdx.x * 256 + threadIdx.x;      // one per 4 channels
    const int CH4 = N_QKV / 4;                     // 768
    int row = gid / CH4;                           // b*T + t
    int c4  = (gid - row * CH4) * 4;
    int sec = c4 >> 10;
    int hc  = c4 & 1023;
    int h = hc >> 6, d = hc & 63;
    int b = row >> 11, t = row & 2047;

    float4 v = *(const float4*)(qkv + (size_t)row * N_QKV + c4);
    __nv_bfloat16 *hp, *lp;
    if (sec == 0) {
        v.x *= QS; v.y *= QS; v.z *= QS; v.w *= QS;
        hp = qh; lp = ql;
    } else if (sec == 1) { hp = kh; lp = kl; }
    else                 { hp = vh; lp = vl; }

    size_t dst = (((size_t)b * H_ + h) * T_ + t) * D_ + d;
    __nv_bfloat162 h01 = __floats2bfloat162_rn(v.x, v.y);
    __nv_bfloat162 h23 = __floats2bfloat162_rn(v.z, v.w);
    __nv_bfloat162 l01 = __floats2bfloat162_rn(v.x - __bfloat162float(h01.x),
                                               v.y - __bfloat162float(h01.y));
    __nv_bfloat162 l23 = __floats2bfloat162_rn(v.z - __bfloat162float(h23.x),
                                               v.w - __bfloat162float(h23.y));
    *(__nv_bfloat162*)(hp + dst)     = h01;
    *(__nv_bfloat162*)(hp + dst + 2) = h23;
    *(__nv_bfloat162*)(lp + dst)     = l01;
    *(__nv_bfloat162*)(lp + dst + 2) = l23;
}

// ---------------------------------------------------------------------------
// HMMA GEMM, split-bf16 x3 (unchanged from R3)
// ---------------------------------------------------------------------------
#define SM_AHI 0
#define SM_ALO 16384
#define SM_BHI 32768
#define SM_BLO 49152
#define SM_TOTAL 65536

__global__ __launch_bounds__(256)
void gemm_bf16x3(const __nv_bfloat16* __restrict__ Ahi, const __nv_bfloat16* __restrict__ Alo,
                 const __nv_bfloat16* __restrict__ Bhi, const __nv_bfloat16* __restrict__ Blo,
                 const float* __restrict__ bias, float* __restrict__ Cout,
                 int M, int N, int K)
{
    extern __shared__ char smem[];
    const uint32_t sb = smem_to_u32(smem);

    const int tid  = threadIdx.x;
    const int wid  = tid >> 5;
    const int lane = tid & 31;
    const int rowBase = blockIdx.y * 128;
    const int colBase = blockIdx.x * 128;

    const int warp_m = wid & 1;
    const int warp_n = wid >> 1;

    float acc[4][4][4];
#pragma unroll
    for (int i = 0; i < 4; i++)
#pragma unroll
        for (int j = 0; j < 4; j++)
#pragma unroll
            for (int r = 0; r < 4; r++) acc[i][j][r] = 0.f;

    const int a_r  = warp_m * 64 + (lane & 15);
    const int a_cb = (lane >> 4) << 4;
    const int g    = lane >> 3;
    const int b_r  = warp_n * 32 + ((g >> 1) << 3) + (lane & 7);
    const int b_cb = (g & 1) << 4;

    const int nChunks = K / 64;
    for (int ch = 0; ch < nChunks; ch++) {
        const int k0 = ch * 64;
#pragma unroll
        for (int it = 0; it < 4; it++) {
            int idx = it * 256 + tid;
            int r   = idx >> 3;
            int cb  = (idx & 7) << 4;
            uint32_t sw = swz((uint32_t)(r * 128 + cb));
            const char* pa = (const char*)(Ahi + (size_t)(rowBase + r) * K + k0) + cb;
            const char* pb = (const char*)(Alo + (size_t)(rowBase + r) * K + k0) + cb;
            const char* pc = (const char*)(Bhi + (size_t)(colBase + r) * K + k0) + cb;
            const char* pd = (const char*)(Blo + (size_t)(colBase + r) * K + k0) + cb;
            *(uint4*)(smem + SM_AHI + sw) = *(const uint4*)pa;
            *(uint4*)(smem + SM_ALO + sw) = *(const uint4*)pb;
            *(uint4*)(smem + SM_BHI + sw) = *(const uint4*)pc;
            *(uint4*)(smem + SM_BLO + sw) = *(const uint4*)pd;
        }
        __syncthreads();

#pragma unroll
        for (int ks = 0; ks < 4; ks++) {
            const int kb = ks * 32;
            uint32_t ah[4][4], al[4][4];
#pragma unroll
            for (int mi = 0; mi < 4; mi++) {
                uint32_t off = swz((uint32_t)((a_r + mi * 16) * 128 + kb + a_cb));
                ldsm_x4(ah[mi], sb + SM_AHI + off);
                ldsm_x4(al[mi], sb + SM_ALO + off);
            }
            uint32_t bh[2][4], bl[2][4];
#pragma unroll
            for (int nt = 0; nt < 2; nt++) {
                uint32_t off = swz((uint32_t)((b_r + nt * 16) * 128 + kb + b_cb));
                ldsm_x4(bh[nt], sb + SM_BHI + off);
                ldsm_x4(bl[nt], sb + SM_BLO + off);
            }
#pragma unroll
            for (int mi = 0; mi < 4; mi++)
#pragma unroll
                for (int nj = 0; nj < 4; nj++) {
                    const uint32_t* bhj = &bh[nj >> 1][(nj & 1) * 2];
                    const uint32_t* blj = &bl[nj >> 1][(nj & 1) * 2];
                    mma16816(acc[mi][nj], ah[mi], bhj[0], bhj[1]);
                    mma16816(acc[mi][nj], ah[mi], blj[0], blj[1]);
                    mma16816(acc[mi][nj], al[mi], bhj[0], bhj[1]);
                }
        }
        __syncthreads();
    }

    const int er = rowBase + warp_m * 64 + (lane >> 2);
    const int ec = colBase + warp_n * 32 + (lane & 3) * 2;
#pragma unroll
    for (int mi = 0; mi < 4; mi++) {
#pragma unroll
        for (int nj = 0; nj < 4; nj++) {
            const int c = ec + nj * 8;
            const float bx = __ldg(bias + c);
            const float by = __ldg(bias + c + 1);
            float2 v0 = { acc[mi][nj][0] + bx, acc[mi][nj][1] + by };
            float2 v1 = { acc[mi][nj][2] + bx, acc[mi][nj][3] + by };
            *(float2*)(Cout + (size_t)(er + mi * 16) * N + c) = v0;
            *(float2*)(Cout + (size_t)(er + mi * 16 + 8) * N + c) = v1;
        }
    }
}

// ---------------------------------------------------------------------------
// Flash attention (HMMA, split-bf16 x3 for S and O).
// CTA = (qt, h, b): 128 q-rows, 4 warps x 32 rows. K/V tiles of 64 keys.
// Q pre-scaled by 0.125*log2(e): softmax in exp2 domain.
// ---------------------------------------------------------------------------
#define FA_QHI 0
#define FA_QLO 16384
#define FA_KHI 32768
#define FA_KLO 40960
#define FA_VHI 49152
#define FA_VLO 57344
#define FA_TOTAL 65536

__global__ __launch_bounds__(128)
void flash_attn(const __nv_bfloat16* __restrict__ qh, const __nv_bfloat16* __restrict__ ql,
                const __nv_bfloat16* __restrict__ kh, const __nv_bfloat16* __restrict__ kl,
                const __nv_bfloat16* __restrict__ vh, const __nv_bfloat16* __restrict__ vl,
                float* __restrict__ out)
{
    extern __shared__ char smem[];
    const uint32_t sb = smem_to_u32(smem);
    const int tid = threadIdx.x, wid = tid >> 5, lane = tid & 31;
    const int h = blockIdx.y, b = blockIdx.z;
    const int qt = gridDim.x - 1 - blockIdx.x;    // big tiles first

    const size_t hoff = ((size_t)b * H_ + h) * T_ * D_;
    const char* qh_p = (const char*)(qh + hoff + (size_t)qt * 128 * D_);
    const char* ql_p = (const char*)(ql + hoff + (size_t)qt * 128 * D_);
    const char* kh_p = (const char*)(kh + hoff);
    const char* kl_p = (const char*)(kl + hoff);
    const char* vh_p = (const char*)(vh + hoff);
    const char* vl_p = (const char*)(vl + hoff);

    // Load Q tiles (128 rows x 128B, hi+lo)
#pragma unroll
    for (int it = 0; it < 8; it++) {
        int idx = it * 128 + tid;
        int r = idx >> 3, cb = (idx & 7) << 4;
        uint32_t sw = swz((uint32_t)(r * 128 + cb));
        *(uint4*)(smem + FA_QHI + sw) = *(const uint4*)(qh_p + r * 128 + cb);
        *(uint4*)(smem + FA_QLO + sw) = *(const uint4*)(ql_p + r * 128 + cb);
    }

    float o[2][8][4];
#pragma unroll
    for (int mi = 0; mi < 2; mi++)
#pragma unroll
        for (int nj = 0; nj < 8; nj++)
#pragma unroll
            for (int r = 0; r < 4; r++) o[mi][nj][r] = 0.f;
    float ms[4] = { -1e30f, -1e30f, -1e30f, -1e30f };
    float ls[4] = { 0.f, 0.f, 0.f, 0.f };

    const int a_r  = wid * 32 + (lane & 15);
    const int a_cb = (lane >> 4) << 4;
    const int g    = lane >> 3;
    const int b_r  = ((g >> 1) << 3) + (lane & 7);
    const int b_cb = (g & 1) << 4;
    const int vrow = ((lane >> 3) & 1) * 8 + (lane & 7);
    const int vcb  = ((lane >> 4) & 1) * 16;

    const int nkt = 2 * qt + 2;
    for (int kt = 0; kt < nkt; kt++) {
        __syncthreads();     // Q ready / previous consumers done
        // Load K/V tiles (64 rows x 128B x 4 tiles)
#pragma unroll
        for (int it = 0; it < 4; it++) {
            int idx = it * 128 + tid;            // 0..511
            int r = idx >> 3, cb = (idx & 7) << 4;
            uint32_t sw = swz((uint32_t)(r * 128 + cb));
            size_t go = (size_t)(kt * 64 + r) * 128 + cb;   // bytes
            *(uint4*)(smem + FA_KHI + sw) = *(const uint4*)(kh_p + go);
            *(uint4*)(smem + FA_KLO + sw) = *(const uint4*)(kl_p + go);
            *(uint4*)(smem + FA_VHI + sw) = *(const uint4*)(vh_p + go);
            *(uint4*)(smem + FA_VLO + sw) = *(const uint4*)(vl_p + go);
        }
        __syncthreads();

        // ---- S = Q K^T (split x3) ----
        float s[2][8][4];
#pragma unroll
        for (int mi = 0; mi < 2; mi++)
#pragma unroll
            for (int nj = 0; nj < 8; nj++)
#pragma unroll
                for (int r = 0; r < 4; r++) s[mi][nj][r] = 0.f;

#pragma unroll
        for (int ks = 0; ks < 4; ks++) {
            uint32_t qhf[2][4], qlf[2][4];
#pragma unroll
            for (int mi = 0; mi < 2; mi++) {
                uint32_t off = swz((uint32_t)((a_r + mi * 16) * 128 + ks * 32 + a_cb));
                ldsm_x4(qhf[mi], sb + FA_QHI + off);
                ldsm_x4(qlf[mi], sb + FA_QLO + off);
            }
            uint32_t kbh[4][4], kbl[4][4];
#pragma unroll
            for (int nt = 0; nt < 4; nt++) {
                uint32_t off = swz((uint32_t)((b_r + nt * 16) * 128 + ks * 32 + b_cb));
                ldsm_x4(kbh[nt], sb + FA_KHI + off);
                ldsm_x4(kbl[nt], sb + FA_KLO + off);
            }
#pragma unroll
            for (int mi = 0; mi < 2; mi++)
#pragma unroll
                for (int nj = 0; nj < 8; nj++) {
                    const uint32_t* bhj = &kbh[nj >> 1][(nj & 1) * 2];
                    const uint32_t* blj = &kbl[nj >> 1][(nj & 1) * 2];
                    mma16816(s[mi][nj], qhf[mi], bhj[0], bhj[1]);
                    mma16816(s[mi][nj], qhf[mi], blj[0], blj[1]);
                    mma16816(s[mi][nj], qlf[mi], bhj[0], bhj[1]);
                }
        }

        // ---- causal mask (only needed on last two key tiles) ----
        if (kt >= 2 * qt) {
            const int row0 = qt * 128 + wid * 32 + (lane >> 2);
            const int colb = kt * 64 + (lane & 3) * 2;
#pragma unroll
            for (int mi = 0; mi < 2; mi++) {
                const int r0 = row0 + mi * 16, r1 = r0 + 8;
#pragma unroll
                for (int nj = 0; nj < 8; nj++) {
                    const int c0 = colb + nj * 8, c1 = c0 + 1;
                    if (c0 > r0) s[mi][nj][0] = -1e30f;
                    if (c1 > r0) s[mi][nj][1] = -1e30f;
                    if (c0 > r1) s[mi][nj][2] = -1e30f;
                    if (c1 > r1) s[mi][nj][3] = -1e30f;
                }
            }
        }

        // ---- online softmax + pack P (split hi/lo) ----
        uint32_t ph[2][4][4], pl[2][4][4];
#pragma unroll
        for (int mi = 0; mi < 2; mi++) {
#pragma unroll
            for (int half = 0; half < 2; half++) {
                const int si = mi * 2 + half;
                float mx = -1e30f;
#pragma unroll
                for (int nj = 0; nj < 8; nj++)
                    mx = fmaxf(mx, fmaxf(s[mi][nj][half * 2], s[mi][nj][half * 2 + 1]));
                mx = fmaxf(mx, __shfl_xor_sync(0xffffffffu, mx, 1));
                mx = fmaxf(mx, __shfl_xor_sync(0xffffffffu, mx, 2));
                const float mnew = fmaxf(ms[si], mx);
                const float alpha = ex2(ms[si] - mnew);
                ms[si] = mnew;
                float rs = 0.f;
#pragma unroll
                for (int nj = 0; nj < 8; nj++) {
                    float p0 = ex2(s[mi][nj][half * 2]     - mnew);
                    float p1 = ex2(s[mi][nj][half * 2 + 1] - mnew);
                    s[mi][nj][half * 2]     = p0;
                    s[mi][nj][half * 2 + 1] = p1;
                    rs += p0 + p1;
                }
                rs += __shfl_xor_sync(0xffffffffu, rs, 1);
                rs += __shfl_xor_sync(0xffffffffu, rs, 2);
                ls[si] = ls[si] * alpha + rs;
#pragma unroll
                for (int nj = 0; nj < 8; nj++) {
                    o[mi][nj][half * 2]     *= alpha;
                    o[mi][nj][half * 2 + 1] *= alpha;
                }
            }
            // C-frag -> A-frag repack (FA2 trick), split into hi/lo
#pragma unroll
            for (int ks = 0; ks < 4; ks++) {
#pragma unroll
                for (int rr = 0; rr < 4; rr++) {
                    const int nj = 2 * ks + (rr >> 1);
                    const int r0 = (rr & 1) * 2;
                    float v0 = s[mi][nj][r0], v1 = s[mi][nj][r0 + 1];
                    __nv_bfloat162 hh = __floats2bfloat162_rn(v0, v1);
                    __nv_bfloat162 ll = __floats2bfloat162_rn(
                        v0 - __bfloat162float(hh.x), v1 - __bfloat162float(hh.y));
                    ph[mi][ks][rr] = *(uint32_t*)&hh;
                    pl[mi][ks][rr] = *(uint32_t*)&ll;
                }
            }
        }

        // ---- O += P V (split x3), V via ldmatrix.trans ----
#pragma unroll
        for (int ks = 0; ks < 4; ks++) {
#pragma unroll
            for (int nd = 0; nd < 4; nd++) {
                uint32_t vhf[4], vlf[4];
                uint32_t off = swz((uint32_t)((ks * 16 + vrow) * 128 + nd * 32 + vcb));
                ldsm_x4_t(vhf, sb + FA_VHI + off);
                ldsm_x4_t(vlf, sb + FA_VLO + off);
#pragma unroll
                for (int mi = 0; mi < 2; mi++) {
                    mma16816(o[mi][nd * 2],     ph[mi][ks], vhf[0], vhf[1]);
                    mma16816(o[mi][nd * 2],     pl[mi][ks], vhf[0], vhf[1]);
                    mma16816(o[mi][nd * 2],     ph[mi][ks], vlf[0], vlf[1]);
                    mma16816(o[mi][nd * 2 + 1], ph[mi][ks], vhf[2], vhf[3]);
                    mma16816(o[mi][nd * 2 + 1], pl[mi][ks], vhf[2], vhf[3]);
                    mma16816(o[mi][nd * 2 + 1], ph[mi][ks], vlf[2], vlf[3]);
                }
            }
        }
    }

    // ---- epilogue: O / l -> g_att [B*T, C] ----
    float inv[4];
#pragma unroll
    for (int si = 0; si < 4; si++) inv[si] = 1.f / ls[si];
    const int er0 = qt * 128 + wid * 32 + (lane >> 2);
    const int ecb = h * 64 + (lane & 3) * 2;
#pragma unroll
    for (int mi = 0; mi < 2; mi++) {
        const size_t row = (size_t)b * T_ + er0 + mi * 16;
#pragma unroll
        for (int nj = 0; nj < 8; nj++) {
            float2 v0 = { o[mi][nj][0] * inv[mi * 2],     o[mi][nj][1] * inv[mi * 2] };
            float2 v1 = { o[mi][nj][2] * inv[mi * 2 + 1], o[mi][nj][3] * inv[mi * 2 + 1] };
            *(float2*)(out + row * C_ + ecb + nj * 8) = v0;
            *(float2*)(out + (row + 8) * C_ + ecb + nj * 8) = v1;
        }
    }
}

// ---------------------------------------------------------------------------
// Launch sequence
// ---------------------------------------------------------------------------
extern "C" void kernel_launch(void* const* d_in, const int* in_sizes, int n_in,
                              void* d_out, int out_size)
{
    const float* x      = (const float*)d_in[0];
    const float* w_qkv  = (const float*)d_in[1];
    const float* b_qkv  = (const float*)d_in[2];
    const float* w_proj = (const float*)d_in[3];
    const float* b_proj = (const float*)d_in[4];
    float* out = (float*)d_out;

    float *qkv_buf, *att_buf;
    __nv_bfloat16 *xhi, *xlo, *wthi, *wtlo, *qh, *ql, *kh, *kl, *vh, *vl;
    cudaGetSymbolAddress((void**)&qkv_buf, g_qkv);
    cudaGetSymbolAddress((void**)&att_buf, g_att);
    cudaGetSymbolAddress((void**)&xhi, g_xhi);
    cudaGetSymbolAddress((void**)&xlo, g_xlo);
    cudaGetSymbolAddress((void**)&wthi, g_wthi);
    cudaGetSymbolAddress((void**)&wtlo, g_wtlo);
    cudaGetSymbolAddress((void**)&qh, g_qh);
    cudaGetSymbolAddress((void**)&ql, g_ql);
    cudaGetSymbolAddress((void**)&kh, g_kh);
    cudaGetSymbolAddress((void**)&kl, g_kl);
    cudaGetSymbolAddress((void**)&vh, g_vh);
    cudaGetSymbolAddress((void**)&vl, g_vl);

    cudaFuncSetAttribute(gemm_bf16x3, cudaFuncAttributeMaxDynamicSharedMemorySize, SM_TOTAL);
    cudaFuncSetAttribute(flash_attn, cudaFuncAttributeMaxDynamicSharedMemorySize, FA_TOTAL);

    // 1) split x -> bf16 hi/lo
    {
        int n4 = (M_ROWS * C_) / 4;
        cvt_split<<<(n4 + 255) / 256, 256>>>(x, xhi, xlo, n4);
    }
    // 2) transpose+split w_qkv
    {
        dim3 grid(N_QKV / 32, C_ / 32);
        wsplit_transpose<<<grid, 256>>>(w_qkv, wthi, wtlo, C_, N_QKV);
    }
    // 3) QKV GEMM
    {
        dim3 grid(N_QKV / 128, M_ROWS / 128);
        gemm_bf16x3<<<grid, 256, SM_TOTAL>>>(xhi, xlo, wthi, wtlo, b_qkv, qkv_buf,
                                             M_ROWS, N_QKV, C_);
    }
    // 4) qkv -> per-head bf16 hi/lo (Q pre-scaled)
    {
        int nthr = (M_ROWS * N_QKV) / 4;
        cvt_qkv<<<nthr / 256, 256>>>(qkv_buf, qh, ql, kh, kl, vh, vl);
    }
    // 5) flash attention
    {
        dim3 grid(T_ / 128, H_, B_);
        flash_attn<<<grid, 128, FA_TOTAL>>>(qh, ql, kh, kl, vh, vl, att_buf);
    }
    // 6) split att -> bf16 hi/lo
    {
        int n4 = (M_ROWS * C_) / 4;
        cvt_split<<<(n4 + 255) / 256, 256>>>(att_buf, xhi, xlo, n4);
    }
    // 7) transpose+split w_proj
    {
        dim3 grid(C_ / 32, C_ / 32);
        wsplit_transpose<<<grid, 256>>>(w_proj, wthi, wtlo, C_, C_);
    }
    // 8) proj GEMM
    {
        dim3 grid(C_ / 128, M_ROWS / 128);
        gemm_bf16x3<<<grid, 256, SM_TOTAL>>>(xhi, xlo, wthi, wtlo, b_proj, out,
                                             M_ROWS, C_, C_);
    }
}

// round 5
// speedup vs baseline: 3.6202x; 1.2147x over previous
#include <cuda_runtime.h>
#include <cuda_bf16.h>
#include <cstdint>

// ---------------------------------------------------------------------------
// Problem constants
// ---------------------------------------------------------------------------
#define B_ 2
#define T_ 2048
#define C_ 1024
#define H_ 16
#define D_ 64
#define M_ROWS (B_ * T_)     // 4096
#define N_QKV  (3 * C_)      // 3072

// softmax scale * log2(e) folded into Q: (1/8) * 1.4426950408889634
#define QS 0.18033688011112042f

// Scratch (__device__ globals; allocation-free rule)
__device__ __nv_bfloat16 g_xhi[(size_t)M_ROWS * C_];
__device__ __nv_bfloat16 g_xlo[(size_t)M_ROWS * C_];
__device__ __nv_bfloat16 g_wthi[(size_t)N_QKV * C_];
__device__ __nv_bfloat16 g_wtlo[(size_t)N_QKV * C_];
// per-head bf16 hi/lo [B,H,T,D]
__device__ __nv_bfloat16 g_qh[(size_t)B_ * H_ * T_ * D_];
__device__ __nv_bfloat16 g_ql[(size_t)B_ * H_ * T_ * D_];
__device__ __nv_bfloat16 g_kh[(size_t)B_ * H_ * T_ * D_];
__device__ __nv_bfloat16 g_kl[(size_t)B_ * H_ * T_ * D_];
__device__ __nv_bfloat16 g_vh[(size_t)B_ * H_ * T_ * D_];
__device__ __nv_bfloat16 g_vl[(size_t)B_ * H_ * T_ * D_];

// ---------------------------------------------------------------------------
// Warp MMA / async-copy helpers (sm_80+ baseline)
// ---------------------------------------------------------------------------
__device__ __forceinline__ uint32_t smem_to_u32(const void* p) {
    uint32_t a;
    asm("{ .reg .u64 t; cvta.to.shared.u64 t, %1; cvt.u32.u64 %0, t; }"
        : "=r"(a) : "l"(p));
    return a;
}
__device__ __forceinline__ void ldsm_x4(uint32_t (&r)[4], uint32_t addr) {
    asm volatile("ldmatrix.sync.aligned.m8n8.x4.shared.b16 {%0,%1,%2,%3}, [%4];"
                 : "=r"(r[0]), "=r"(r[1]), "=r"(r[2]), "=r"(r[3]) : "r"(addr));
}
__device__ __forceinline__ void ldsm_x4_t(uint32_t (&r)[4], uint32_t addr) {
    asm volatile("ldmatrix.sync.aligned.m8n8.x4.trans.shared.b16 {%0,%1,%2,%3}, [%4];"
                 : "=r"(r[0]), "=r"(r[1]), "=r"(r[2]), "=r"(r[3]) : "r"(addr));
}
__device__ __forceinline__ void mma16816(float (&d)[4],
                                         const uint32_t (&a)[4],
                                         const uint32_t b0, const uint32_t b1) {
    asm volatile(
        "mma.sync.aligned.m16n8k16.row.col.f32.bf16.bf16.f32 "
        "{%0,%1,%2,%3}, {%4,%5,%6,%7}, {%8,%9}, {%0,%1,%2,%3};"
        : "+f"(d[0]), "+f"(d[1]), "+f"(d[2]), "+f"(d[3])
        : "r"(a[0]), "r"(a[1]), "r"(a[2]), "r"(a[3]), "r"(b0), "r"(b1));
}
__device__ __forceinline__ uint32_t swz(uint32_t off) {
    return off ^ ((off >> 3) & 0x70);
}
__device__ __forceinline__ float ex2(float x) {
    float y; asm("ex2.approx.ftz.f32 %0, %1;" : "=f"(y) : "f"(x)); return y;
}
__device__ __forceinline__ void cp16(uint32_t dst, const void* src) {
    asm volatile("cp.async.ca.shared.global [%0], [%1], 16;" :: "r"(dst), "l"(src));
}
__device__ __forceinline__ void cp_commit() {
    asm volatile("cp.async.commit_group;" ::: "memory");
}
template<int N> __device__ __forceinline__ void cp_wait() {
    asm volatile("cp.async.wait_group %0;" :: "n"(N) : "memory");
}

// ---------------------------------------------------------------------------
// Prepass 1: split fp32 -> (bf16 hi, bf16 lo)
// ---------------------------------------------------------------------------
__global__ __launch_bounds__(256)
void cvt_split(const float* __restrict__ src,
               __nv_bfloat16* __restrict__ hi, __nv_bfloat16* __restrict__ lo, int n4)
{
    int i = blockIdx.x * 256 + threadIdx.x;
    if (i >= n4) return;
    float4 v = ((const float4*)src)[i];
    __nv_bfloat162 h01 = __floats2bfloat162_rn(v.x, v.y);
    __nv_bfloat162 h23 = __floats2bfloat162_rn(v.z, v.w);
    __nv_bfloat162 l01 = __floats2bfloat162_rn(v.x - __bfloat162float(h01.x),
                                               v.y - __bfloat162float(h01.y));
    __nv_bfloat162 l23 = __floats2bfloat162_rn(v.z - __bfloat162float(h23.x),
                                               v.w - __bfloat162float(h23.y));
    ((__nv_bfloat162*)hi)[i * 2 + 0] = h01;
    ((__nv_bfloat162*)hi)[i * 2 + 1] = h23;
    ((__nv_bfloat162*)lo)[i * 2 + 0] = l01;
    ((__nv_bfloat162*)lo)[i * 2 + 1] = l23;
}

// ---------------------------------------------------------------------------
// Prepass 2: W [K,N] fp32 -> W^T hi/lo [N,K] bf16
// ---------------------------------------------------------------------------
__global__ __launch_bounds__(256)
void wsplit_transpose(const float* __restrict__ W,
                      __nv_bfloat16* __restrict__ Thi, __nv_bfloat16* __restrict__ Tlo,
                      int K, int N)
{
    __shared__ float tile[32][33];
    const int tx = threadIdx.x & 31;
    const int ty = threadIdx.x >> 5;
    const int k0 = blockIdx.y * 32;
    const int n0 = blockIdx.x * 32;
#pragma unroll
    for (int r = ty; r < 32; r += 8)
        tile[r][tx] = W[(size_t)(k0 + r) * N + n0 + tx];
    __syncthreads();
#pragma unroll
    for (int r = ty; r < 32; r += 8) {
        float v = tile[tx][r];
        __nv_bfloat16 h = __float2bfloat16(v);
        __nv_bfloat16 l = __float2bfloat16(v - __bfloat162float(h));
        size_t o = (size_t)(n0 + r) * K + k0 + tx;
        Thi[o] = h;
        Tlo[o] = l;
    }
}

// ---------------------------------------------------------------------------
// HMMA GEMM, split-bf16 x3, cp.async 2-stage pipeline.
// MODE 0: write fp32 C + bias (final proj).
// MODE 1: write per-head split-bf16 q/k/v (+bias, Q scaled by QS).
// ---------------------------------------------------------------------------
#define SM_AHI 0
#define SM_ALO 16384
#define SM_BHI 32768
#define SM_BLO 49152
#define SM_STAGE 65536
#define SM_TOTAL (2 * SM_STAGE)     // 131072

template<int MODE>
__global__ __launch_bounds__(256)
void gemm_bf16x3(const __nv_bfloat16* __restrict__ Ahi, const __nv_bfloat16* __restrict__ Alo,
                 const __nv_bfloat16* __restrict__ Bhi, const __nv_bfloat16* __restrict__ Blo,
                 const float* __restrict__ bias, float* __restrict__ Cout,
                 __nv_bfloat16* __restrict__ qh, __nv_bfloat16* __restrict__ ql,
                 __nv_bfloat16* __restrict__ kh, __nv_bfloat16* __restrict__ kl,
                 __nv_bfloat16* __restrict__ vh, __nv_bfloat16* __restrict__ vl,
                 int M, int N, int K)
{
    extern __shared__ char smem[];
    const uint32_t sb = smem_to_u32(smem);

    const int tid  = threadIdx.x;
    const int wid  = tid >> 5;
    const int lane = tid & 31;
    const int rowBase = blockIdx.y * 128;
    const int colBase = blockIdx.x * 128;

    const int warp_m = wid & 1;
    const int warp_n = wid >> 1;

    float acc[4][4][4];
#pragma unroll
    for (int i = 0; i < 4; i++)
#pragma unroll
        for (int j = 0; j < 4; j++)
#pragma unroll
            for (int r = 0; r < 4; r++) acc[i][j][r] = 0.f;

    const int a_r  = warp_m * 64 + (lane & 15);
    const int a_cb = (lane >> 4) << 4;
    const int g    = lane >> 3;
    const int b_r  = warp_n * 32 + ((g >> 1) << 3) + (lane & 7);
    const int b_cb = (g & 1) << 4;

    // per-thread load slots (fixed across chunks)
    int ld_r[4], ld_cb[4];
    uint32_t ld_sw[4];
#pragma unroll
    for (int it = 0; it < 4; it++) {
        int idx = it * 256 + tid;
        ld_r[it]  = idx >> 3;
        ld_cb[it] = (idx & 7) << 4;
        ld_sw[it] = swz((uint32_t)(ld_r[it] * 128 + ld_cb[it]));
    }

    auto issue = [&](int ch, int st) {
        const int k0 = ch * 64;
        const uint32_t sbase = sb + st * SM_STAGE;
#pragma unroll
        for (int it = 0; it < 4; it++) {
            const int r = ld_r[it], cb = ld_cb[it];
            const uint32_t sw = ld_sw[it];
            cp16(sbase + SM_AHI + sw, (const char*)(Ahi + (size_t)(rowBase + r) * K + k0) + cb);
            cp16(sbase + SM_ALO + sw, (const char*)(Alo + (size_t)(rowBase + r) * K + k0) + cb);
            cp16(sbase + SM_BHI + sw, (const char*)(Bhi + (size_t)(colBase + r) * K + k0) + cb);
            cp16(sbase + SM_BLO + sw, (const char*)(Blo + (size_t)(colBase + r) * K + k0) + cb);
        }
        cp_commit();
    };

    const int nChunks = K / 64;
    issue(0, 0);

    for (int ch = 0; ch < nChunks; ch++) {
        if (ch + 1 < nChunks) { issue(ch + 1, (ch + 1) & 1); cp_wait<1>(); }
        else                  { cp_wait<0>(); }
        __syncthreads();

        const uint32_t sbase = sb + (ch & 1) * SM_STAGE;
#pragma unroll
        for (int ks = 0; ks < 4; ks++) {
            const int kb = ks * 32;
            uint32_t ah[4][4], al[4][4];
#pragma unroll
            for (int mi = 0; mi < 4; mi++) {
                uint32_t off = swz((uint32_t)((a_r + mi * 16) * 128 + kb + a_cb));
                ldsm_x4(ah[mi], sbase + SM_AHI + off);
                ldsm_x4(al[mi], sbase + SM_ALO + off);
            }
            uint32_t bh[2][4], bl[2][4];
#pragma unroll
            for (int nt = 0; nt < 2; nt++) {
                uint32_t off = swz((uint32_t)((b_r + nt * 16) * 128 + kb + b_cb));
                ldsm_x4(bh[nt], sbase + SM_BHI + off);
                ldsm_x4(bl[nt], sbase + SM_BLO + off);
            }
#pragma unroll
            for (int mi = 0; mi < 4; mi++)
#pragma unroll
                for (int nj = 0; nj < 4; nj++) {
                    const uint32_t* bhj = &bh[nj >> 1][(nj & 1) * 2];
                    const uint32_t* blj = &bl[nj >> 1][(nj & 1) * 2];
                    mma16816(acc[mi][nj], ah[mi], bhj[0], bhj[1]);
                    mma16816(acc[mi][nj], ah[mi], blj[0], blj[1]);
                    mma16816(acc[mi][nj], al[mi], bhj[0], bhj[1]);
                }
        }
        __syncthreads();
    }

    const int er = rowBase + warp_m * 64 + (lane >> 2);
    const int ec = colBase + warp_n * 32 + (lane & 3) * 2;

    if (MODE == 0) {
#pragma unroll
        for (int mi = 0; mi < 4; mi++) {
#pragma unroll
            for (int nj = 0; nj < 4; nj++) {
                const int c = ec + nj * 8;
                const float bx = __ldg(bias + c);
                const float by = __ldg(bias + c + 1);
                float2 v0 = { acc[mi][nj][0] + bx, acc[mi][nj][1] + by };
                float2 v1 = { acc[mi][nj][2] + bx, acc[mi][nj][3] + by };
                *(float2*)(Cout + (size_t)(er + mi * 16) * N + c) = v0;
                *(float2*)(Cout + (size_t)(er + mi * 16 + 8) * N + c) = v1;
            }
        }
    } else {
        // MODE 1: scatter into per-head split-bf16 [B,H,T,D]; Q scaled by QS.
#pragma unroll
        for (int nj = 0; nj < 4; nj++) {
            const int c   = ec + nj * 8;
            const int sec = c >> 10;             // 0=q,1=k,2=v
            const int hh  = (c & 1023) >> 6;
            const int dd  = c & 63;
            const float sc = (sec == 0) ? QS : 1.f;
            const float bx = __ldg(bias + c)     * sc;
            const float by = __ldg(bias + c + 1) * sc;
            __nv_bfloat16* hp = (sec == 0) ? qh : (sec == 1) ? kh : vh;
            __nv_bfloat16* lp = (sec == 0) ? ql : (sec == 1) ? kl : vl;
#pragma unroll
            for (int mi = 0; mi < 4; mi++) {
#pragma unroll
                for (int half = 0; half < 2; half++) {
                    const int r = er + mi * 16 + half * 8;
                    const int bb = r >> 11, tt = r & 2047;
                    const size_t dst = (((size_t)bb * H_ + hh) * T_ + tt) * D_ + dd;
                    float v0 = fmaf(acc[mi][nj][half * 2],     sc, bx);
                    float v1 = fmaf(acc[mi][nj][half * 2 + 1], sc, by);
                    __nv_bfloat162 h2 = __floats2bfloat162_rn(v0, v1);
                    __nv_bfloat162 l2 = __floats2bfloat162_rn(
                        v0 - __bfloat162float(h2.x), v1 - __bfloat162float(h2.y));
                    *(__nv_bfloat162*)(hp + dst) = h2;
                    *(__nv_bfloat162*)(lp + dst) = l2;
                }
            }
        }
    }
}

// ---------------------------------------------------------------------------
// Flash attention (HMMA, split-bf16 x3), cp.async 2-stage K/V pipeline.
// Output: split-bf16 att [B*T, C] (hi/lo) consumed directly by proj GEMM.
// ---------------------------------------------------------------------------
#define FA_QHI 0
#define FA_QLO 16384
#define FA_ST(s) (32768 + (s) * 32768)
#define FA_KHI 0
#define FA_KLO 8192
#define FA_VHI 16384
#define FA_VLO 24576
#define FA_TOTAL (32768 + 2 * 32768)   // 98304

__global__ __launch_bounds__(128)
void flash_attn(const __nv_bfloat16* __restrict__ qh, const __nv_bfloat16* __restrict__ ql,
                const __nv_bfloat16* __restrict__ kh, const __nv_bfloat16* __restrict__ kl,
                const __nv_bfloat16* __restrict__ vh, const __nv_bfloat16* __restrict__ vl,
                __nv_bfloat16* __restrict__ ohi, __nv_bfloat16* __restrict__ olo)
{
    extern __shared__ char smem[];
    const uint32_t sb = smem_to_u32(smem);
    const int tid = threadIdx.x, wid = tid >> 5, lane = tid & 31;
    const int h = blockIdx.y, b = blockIdx.z;
    const int qt = gridDim.x - 1 - blockIdx.x;    // big tiles first

    const size_t hoff = ((size_t)b * H_ + h) * T_ * D_;
    const char* qh_p = (const char*)(qh + hoff + (size_t)qt * 128 * D_);
    const char* ql_p = (const char*)(ql + hoff + (size_t)qt * 128 * D_);
    const char* kh_p = (const char*)(kh + hoff);
    const char* kl_p = (const char*)(kl + hoff);
    const char* vh_p = (const char*)(vh + hoff);
    const char* vl_p = (const char*)(vl + hoff);

    auto issue_kv = [&](int kt, int st) {
        const uint32_t sbase = sb + FA_ST(st);
#pragma unroll
        for (int it = 0; it < 4; it++) {
            int idx = it * 128 + tid;            // 0..511
            int r = idx >> 3, cb = (idx & 7) << 4;
            uint32_t sw = swz((uint32_t)(r * 128 + cb));
            size_t go = (size_t)(kt * 64 + r) * 128 + cb;    // bytes
            cp16(sbase + FA_KHI + sw, kh_p + go);
            cp16(sbase + FA_KLO + sw, kl_p + go);
            cp16(sbase + FA_VHI + sw, vh_p + go);
            cp16(sbase + FA_VLO + sw, vl_p + go);
        }
        cp_commit();
    };

    const int nkt = 2 * qt + 2;
    issue_kv(0, 0);

    // Load Q tiles (regular stores; covered by first __syncthreads)
#pragma unroll
    for (int it = 0; it < 8; it++) {
        int idx = it * 128 + tid;
        int r = idx >> 3, cb = (idx & 7) << 4;
        uint32_t sw = swz((uint32_t)(r * 128 + cb));
        *(uint4*)(smem + FA_QHI + sw) = *(const uint4*)(qh_p + r * 128 + cb);
        *(uint4*)(smem + FA_QLO + sw) = *(const uint4*)(ql_p + r * 128 + cb);
    }

    float o[2][8][4];
#pragma unroll
    for (int mi = 0; mi < 2; mi++)
#pragma unroll
        for (int nj = 0; nj < 8; nj++)
#pragma unroll
            for (int r = 0; r < 4; r++) o[mi][nj][r] = 0.f;
    float ms[4] = { -1e30f, -1e30f, -1e30f, -1e30f };
    float ls[4] = { 0.f, 0.f, 0.f, 0.f };

    const int a_r  = wid * 32 + (lane & 15);
    const int a_cb = (lane >> 4) << 4;
    const int g    = lane >> 3;
    const int b_r  = ((g >> 1) << 3) + (lane & 7);
    const int b_cb = (g & 1) << 4;
    const int vrow = ((lane >> 3) & 1) * 8 + (lane & 7);
    const int vcb  = ((lane >> 4) & 1) * 16;

    for (int kt = 0; kt < nkt; kt++) {
        if (kt + 1 < nkt) { issue_kv(kt + 1, (kt + 1) & 1); cp_wait<1>(); }
        else              { cp_wait<0>(); }
        __syncthreads();

        const uint32_t kv = sb + FA_ST(kt & 1);

        // ---- S = Q K^T (split x3) ----
        float s[2][8][4];
#pragma unroll
        for (int mi = 0; mi < 2; mi++)
#pragma unroll
            for (int nj = 0; nj < 8; nj++)
#pragma unroll
                for (int r = 0; r < 4; r++) s[mi][nj][r] = 0.f;

#pragma unroll
        for (int ks = 0; ks < 4; ks++) {
            uint32_t qhf[2][4], qlf[2][4];
#pragma unroll
            for (int mi = 0; mi < 2; mi++) {
                uint32_t off = swz((uint32_t)((a_r + mi * 16) * 128 + ks * 32 + a_cb));
                ldsm_x4(qhf[mi], sb + FA_QHI + off);
                ldsm_x4(qlf[mi], sb + FA_QLO + off);
            }
            uint32_t kbh[4][4], kbl[4][4];
#pragma unroll
            for (int nt = 0; nt < 4; nt++) {
                uint32_t off = swz((uint32_t)((b_r + nt * 16) * 128 + ks * 32 + b_cb));
                ldsm_x4(kbh[nt], kv + FA_KHI + off);
                ldsm_x4(kbl[nt], kv + FA_KLO + off);
            }
#pragma unroll
            for (int mi = 0; mi < 2; mi++)
#pragma unroll
                for (int nj = 0; nj < 8; nj++) {
                    const uint32_t* bhj = &kbh[nj >> 1][(nj & 1) * 2];
                    const uint32_t* blj = &kbl[nj >> 1][(nj & 1) * 2];
                    mma16816(s[mi][nj], qhf[mi], bhj[0], bhj[1]);
                    mma16816(s[mi][nj], qhf[mi], blj[0], blj[1]);
                    mma16816(s[mi][nj], qlf[mi], bhj[0], bhj[1]);
                }
        }

        // ---- causal mask (last two key tiles only) ----
        if (kt >= 2 * qt) {
            const int row0 = qt * 128 + wid * 32 + (lane >> 2);
            const int colb = kt * 64 + (lane & 3) * 2;
#pragma unroll
            for (int mi = 0; mi < 2; mi++) {
                const int r0 = row0 + mi * 16, r1 = r0 + 8;
#pragma unroll
                for (int nj = 0; nj < 8; nj++) {
                    const int c0 = colb + nj * 8, c1 = c0 + 1;
                    if (c0 > r0) s[mi][nj][0] = -1e30f;
                    if (c1 > r0) s[mi][nj][1] = -1e30f;
                    if (c0 > r1) s[mi][nj][2] = -1e30f;
                    if (c1 > r1) s[mi][nj][3] = -1e30f;
                }
            }
        }

        // ---- online softmax + pack P (split hi/lo) ----
        uint32_t ph[2][4][4], pl[2][4][4];
#pragma unroll
        for (int mi = 0; mi < 2; mi++) {
#pragma unroll
            for (int half = 0; half < 2; half++) {
                const int si = mi * 2 + half;
                float mx = -1e30f;
#pragma unroll
                for (int nj = 0; nj < 8; nj++)
                    mx = fmaxf(mx, fmaxf(s[mi][nj][half * 2], s[mi][nj][half * 2 + 1]));
                mx = fmaxf(mx, __shfl_xor_sync(0xffffffffu, mx, 1));
                mx = fmaxf(mx, __shfl_xor_sync(0xffffffffu, mx, 2));
                const float mnew = fmaxf(ms[si], mx);
                const float alpha = ex2(ms[si] - mnew);
                ms[si] = mnew;
                float rs = 0.f;
#pragma unroll
                for (int nj = 0; nj < 8; nj++) {
                    float p0 = ex2(s[mi][nj][half * 2]     - mnew);
                    float p1 = ex2(s[mi][nj][half * 2 + 1] - mnew);
                    s[mi][nj][half * 2]     = p0;
                    s[mi][nj][half * 2 + 1] = p1;
                    rs += p0 + p1;
                }
                rs += __shfl_xor_sync(0xffffffffu, rs, 1);
                rs += __shfl_xor_sync(0xffffffffu, rs, 2);
                ls[si] = ls[si] * alpha + rs;
#pragma unroll
                for (int nj = 0; nj < 8; nj++) {
                    o[mi][nj][half * 2]     *= alpha;
                    o[mi][nj][half * 2 + 1] *= alpha;
                }
            }
            // C-frag -> A-frag repack, split into hi/lo
#pragma unroll
            for (int ks = 0; ks < 4; ks++) {
#pragma unroll
                for (int rr = 0; rr < 4; rr++) {
                    const int nj = 2 * ks + (rr >> 1);
                    const int r0 = (rr & 1) * 2;
                    float v0 = s[mi][nj][r0], v1 = s[mi][nj][r0 + 1];
                    __nv_bfloat162 hh = __floats2bfloat162_rn(v0, v1);
                    __nv_bfloat162 ll = __floats2bfloat162_rn(
                        v0 - __bfloat162float(hh.x), v1 - __bfloat162float(hh.y));
                    ph[mi][ks][rr] = *(uint32_t*)&hh;
                    pl[mi][ks][rr] = *(uint32_t*)&ll;
                }
            }
        }

        // ---- O += P V (split x3), V via ldmatrix.trans ----
#pragma unroll
        for (int ks = 0; ks < 4; ks++) {
#pragma unroll
            for (int nd = 0; nd < 4; nd++) {
                uint32_t vhf[4], vlf[4];
                uint32_t off = swz((uint32_t)((ks * 16 + vrow) * 128 + nd * 32 + vcb));
                ldsm_x4_t(vhf, kv + FA_VHI + off);
                ldsm_x4_t(vlf, kv + FA_VLO + off);
#pragma unroll
                for (int mi = 0; mi < 2; mi++) {
                    mma16816(o[mi][nd * 2],     ph[mi][ks], vhf[0], vhf[1]);
                    mma16816(o[mi][nd * 2],     pl[mi][ks], vhf[0], vhf[1]);
                    mma16816(o[mi][nd * 2],     ph[mi][ks], vlf[0], vlf[1]);
                    mma16816(o[mi][nd * 2 + 1], ph[mi][ks], vhf[2], vhf[3]);
                    mma16816(o[mi][nd * 2 + 1], pl[mi][ks], vhf[2], vhf[3]);
                    mma16816(o[mi][nd * 2 + 1], ph[mi][ks], vlf[2], vlf[3]);
                }
            }
        }
        __syncthreads();   // protect stage reuse before next prefetch lands
    }

    // ---- epilogue: O / l -> split-bf16 att [B*T, C] ----
    float inv[4];
#pragma unroll
    for (int si = 0; si < 4; si++) inv[si] = 1.f / ls[si];
    const int er0 = qt * 128 + wid * 32 + (lane >> 2);
    const int ecb = h * 64 + (lane & 3) * 2;
#pragma unroll
    for (int mi = 0; mi < 2; mi++) {
        const size_t row = (size_t)b * T_ + er0 + mi * 16;
#pragma unroll
        for (int nj = 0; nj < 8; nj++) {
            float v0 = o[mi][nj][0] * inv[mi * 2];
            float v1 = o[mi][nj][1] * inv[mi * 2];
            float v2 = o[mi][nj][2] * inv[mi * 2 + 1];
            float v3 = o[mi][nj][3] * inv[mi * 2 + 1];
            __nv_bfloat162 h01 = __floats2bfloat162_rn(v0, v1);
            __nv_bfloat162 h23 = __floats2bfloat162_rn(v2, v3);
            __nv_bfloat162 l01 = __floats2bfloat162_rn(v0 - __bfloat162float(h01.x),
                                                       v1 - __bfloat162float(h01.y));
            __nv_bfloat162 l23 = __floats2bfloat162_rn(v2 - __bfloat162float(h23.x),
                                                       v3 - __bfloat162float(h23.y));
            *(__nv_bfloat162*)(ohi + row * C_ + ecb + nj * 8) = h01;
            *(__nv_bfloat162*)(olo + row * C_ + ecb + nj * 8) = l01;
            *(__nv_bfloat162*)(ohi + (row + 8) * C_ + ecb + nj * 8) = h23;
            *(__nv_bfloat162*)(olo + (row + 8) * C_ + ecb + nj * 8) = l23;
        }
    }
}

// ---------------------------------------------------------------------------
// Launch sequence
// ---------------------------------------------------------------------------
extern "C" void kernel_launch(void* const* d_in, const int* in_sizes, int n_in,
                              void* d_out, int out_size)
{
    const float* x      = (const float*)d_in[0];
    const float* w_qkv  = (const float*)d_in[1];
    const float* b_qkv  = (const float*)d_in[2];
    const float* w_proj = (const float*)d_in[3];
    const float* b_proj = (const float*)d_in[4];
    float* out = (float*)d_out;

    __nv_bfloat16 *xhi, *xlo, *wthi, *wtlo, *qh, *ql, *kh, *kl, *vh, *vl;
    cudaGetSymbolAddress((void**)&xhi, g_xhi);
    cudaGetSymbolAddress((void**)&xlo, g_xlo);
    cudaGetSymbolAddress((void**)&wthi, g_wthi);
    cudaGetSymbolAddress((void**)&wtlo, g_wtlo);
    cudaGetSymbolAddress((void**)&qh, g_qh);
    cudaGetSymbolAddress((void**)&ql, g_ql);
    cudaGetSymbolAddress((void**)&kh, g_kh);
    cudaGetSymbolAddress((void**)&kl, g_kl);
    cudaGetSymbolAddress((void**)&vh, g_vh);
    cudaGetSymbolAddress((void**)&vl, g_vl);

    cudaFuncSetAttribute(gemm_bf16x3<0>, cudaFuncAttributeMaxDynamicSharedMemorySize, SM_TOTAL);
    cudaFuncSetAttribute(gemm_bf16x3<1>, cudaFuncAttributeMaxDynamicSharedMemorySize, SM_TOTAL);
    cudaFuncSetAttribute(flash_attn, cudaFuncAttributeMaxDynamicSharedMemorySize, FA_TOTAL);

    // 1) split x -> bf16 hi/lo
    {
        int n4 = (M_ROWS * C_) / 4;
        cvt_split<<<(n4 + 255) / 256, 256>>>(x, xhi, xlo, n4);
    }
    // 2) transpose+split w_qkv
    {
        dim3 grid(N_QKV / 32, C_ / 32);
        wsplit_transpose<<<grid, 256>>>(w_qkv, wthi, wtlo, C_, N_QKV);
    }
    // 3) QKV GEMM -> per-head split-bf16 q/k/v (fused scale+split epilogue)
    {
        dim3 grid(N_QKV / 128, M_ROWS / 128);
        gemm_bf16x3<1><<<grid, 256, SM_TOTAL>>>(xhi, xlo, wthi, wtlo, b_qkv, nullptr,
                                                qh, ql, kh, kl, vh, vl,
                                                M_ROWS, N_QKV, C_);
    }
    // 4) flash attention -> split-bf16 att (reuses xhi/xlo)
    {
        dim3 grid(T_ / 128, H_, B_);
        flash_attn<<<grid, 128, FA_TOTAL>>>(qh, ql, kh, kl, vh, vl, xhi, xlo);
    }
    // 5) transpose+split w_proj
    {
        dim3 grid(C_ / 32, C_ / 32);
        wsplit_transpose<<<grid, 256>>>(w_proj, wthi, wtlo, C_, C_);
    }
    // 6) proj GEMM -> fp32 out
    {
        dim3 grid(C_ / 128, M_ROWS / 128);
        gemm_bf16x3<0><<<grid, 256, SM_TOTAL>>>(xhi, xlo, wthi, wtlo, b_proj, out,
                                                nullptr, nullptr, nullptr, nullptr,
                                                nullptr, nullptr,
                                                M_ROWS, C_, C_);
    }
}

// round 6
// speedup vs baseline: 3.9897x; 1.1021x over previous
#include <cuda_runtime.h>
#include <cuda_bf16.h>
#include <cuda_fp16.h>
#include <cstdint>

// ---------------------------------------------------------------------------
// Problem constants
// ---------------------------------------------------------------------------
#define B_ 2
#define T_ 2048
#define C_ 1024
#define H_ 16
#define D_ 64
#define M_ROWS (B_ * T_)     // 4096
#define N_QKV  (3 * C_)      // 3072

// softmax scale * log2(e) folded into Q: (1/8) * 1.4426950408889634
#define QS 0.18033688011112042f

// Scratch (__device__ globals; allocation-free rule)
__device__ __nv_bfloat16 g_xhi[(size_t)M_ROWS * C_];
__device__ __nv_bfloat16 g_xlo[(size_t)M_ROWS * C_];
__device__ __nv_bfloat16 g_wthi[(size_t)N_QKV * C_];
__device__ __nv_bfloat16 g_wtlo[(size_t)N_QKV * C_];
// per-head 16-bit tensors [B,H,T,D]: q/k split bf16 hi+lo, v plain fp16
__device__ __nv_bfloat16 g_qh[(size_t)B_ * H_ * T_ * D_];
__device__ __nv_bfloat16 g_ql[(size_t)B_ * H_ * T_ * D_];
__device__ __nv_bfloat16 g_kh[(size_t)B_ * H_ * T_ * D_];
__device__ __nv_bfloat16 g_kl[(size_t)B_ * H_ * T_ * D_];
__device__ __half        g_vh[(size_t)B_ * H_ * T_ * D_];

// ---------------------------------------------------------------------------
// Warp MMA / async-copy helpers (sm_80+ baseline)
// ---------------------------------------------------------------------------
__device__ __forceinline__ uint32_t smem_to_u32(const void* p) {
    uint32_t a;
    asm("{ .reg .u64 t; cvta.to.shared.u64 t, %1; cvt.u32.u64 %0, t; }"
        : "=r"(a) : "l"(p));
    return a;
}
__device__ __forceinline__ void ldsm_x4(uint32_t (&r)[4], uint32_t addr) {
    asm volatile("ldmatrix.sync.aligned.m8n8.x4.shared.b16 {%0,%1,%2,%3}, [%4];"
                 : "=r"(r[0]), "=r"(r[1]), "=r"(r[2]), "=r"(r[3]) : "r"(addr));
}
__device__ __forceinline__ void ldsm_x4_t(uint32_t (&r)[4], uint32_t addr) {
    asm volatile("ldmatrix.sync.aligned.m8n8.x4.trans.shared.b16 {%0,%1,%2,%3}, [%4];"
                 : "=r"(r[0]), "=r"(r[1]), "=r"(r[2]), "=r"(r[3]) : "r"(addr));
}
__device__ __forceinline__ void mma16816(float (&d)[4],
                                         const uint32_t (&a)[4],
                                         const uint32_t b0, const uint32_t b1) {
    asm volatile(
        "mma.sync.aligned.m16n8k16.row.col.f32.bf16.bf16.f32 "
        "{%0,%1,%2,%3}, {%4,%5,%6,%7}, {%8,%9}, {%0,%1,%2,%3};"
        : "+f"(d[0]), "+f"(d[1]), "+f"(d[2]), "+f"(d[3])
        : "r"(a[0]), "r"(a[1]), "r"(a[2]), "r"(a[3]), "r"(b0), "r"(b1));
}
__device__ __forceinline__ void mma16816h(float (&d)[4],
                                          const uint32_t (&a)[4],
                                          const uint32_t b0, const uint32_t b1) {
    asm volatile(
        "mma.sync.aligned.m16n8k16.row.col.f32.f16.f16.f32 "
        "{%0,%1,%2,%3}, {%4,%5,%6,%7}, {%8,%9}, {%0,%1,%2,%3};"
        : "+f"(d[0]), "+f"(d[1]), "+f"(d[2]), "+f"(d[3])
        : "r"(a[0]), "r"(a[1]), "r"(a[2]), "r"(a[3]), "r"(b0), "r"(b1));
}
__device__ __forceinline__ uint32_t swz(uint32_t off) {
    return off ^ ((off >> 3) & 0x70);
}
__device__ __forceinline__ float ex2(float x) {
    float y; asm("ex2.approx.ftz.f32 %0, %1;" : "=f"(y) : "f"(x)); return y;
}
__device__ __forceinline__ void cp16(uint32_t dst, const void* src) {
    asm volatile("cp.async.ca.shared.global [%0], [%1], 16;" :: "r"(dst), "l"(src));
}
__device__ __forceinline__ void cp_commit() {
    asm volatile("cp.async.commit_group;" ::: "memory");
}
template<int N> __device__ __forceinline__ void cp_wait() {
    asm volatile("cp.async.wait_group %0;" :: "n"(N) : "memory");
}

// ---------------------------------------------------------------------------
// Prepass 1: split fp32 -> (bf16 hi, bf16 lo)
// ---------------------------------------------------------------------------
__global__ __launch_bounds__(256)
void cvt_split(const float* __restrict__ src,
               __nv_bfloat16* __restrict__ hi, __nv_bfloat16* __restrict__ lo, int n4)
{
    int i = blockIdx.x * 256 + threadIdx.x;
    if (i >= n4) return;
    float4 v = ((const float4*)src)[i];
    __nv_bfloat162 h01 = __floats2bfloat162_rn(v.x, v.y);
    __nv_bfloat162 h23 = __floats2bfloat162_rn(v.z, v.w);
    __nv_bfloat162 l01 = __floats2bfloat162_rn(v.x - __bfloat162float(h01.x),
                                               v.y - __bfloat162float(h01.y));
    __nv_bfloat162 l23 = __floats2bfloat162_rn(v.z - __bfloat162float(h23.x),
                                               v.w - __bfloat162float(h23.y));
    ((__nv_bfloat162*)hi)[i * 2 + 0] = h01;
    ((__nv_bfloat162*)hi)[i * 2 + 1] = h23;
    ((__nv_bfloat162*)lo)[i * 2 + 0] = l01;
    ((__nv_bfloat162*)lo)[i * 2 + 1] = l23;
}

// ---------------------------------------------------------------------------
// Prepass 2: W [K,N] fp32 -> W^T hi/lo [N,K] bf16
// ---------------------------------------------------------------------------
__global__ __launch_bounds__(256)
void wsplit_transpose(const float* __restrict__ W,
                      __nv_bfloat16* __restrict__ Thi, __nv_bfloat16* __restrict__ Tlo,
                      int K, int N)
{
    __shared__ float tile[32][33];
    const int tx = threadIdx.x & 31;
    const int ty = threadIdx.x >> 5;
    const int k0 = blockIdx.y * 32;
    const int n0 = blockIdx.x * 32;
#pragma unroll
    for (int r = ty; r < 32; r += 8)
        tile[r][tx] = W[(size_t)(k0 + r) * N + n0 + tx];
    __syncthreads();
#pragma unroll
    for (int r = ty; r < 32; r += 8) {
        float v = tile[tx][r];
        __nv_bfloat16 h = __float2bfloat16(v);
        __nv_bfloat16 l = __float2bfloat16(v - __bfloat162float(h));
        size_t o = (size_t)(n0 + r) * K + k0 + tx;
        Thi[o] = h;
        Tlo[o] = l;
    }
}

// ---------------------------------------------------------------------------
// HMMA GEMM, split-bf16 x3, cp.async 3-stage pipeline (single sync / chunk).
// MODE 0: write fp32 C + bias (final proj).
// MODE 1: write per-head q/k (split bf16, Q scaled by QS) and v (fp16).
// ---------------------------------------------------------------------------
#define SM_AHI 0
#define SM_ALO 16384
#define SM_BHI 32768
#define SM_BLO 49152
#define SM_STAGE 65536
#define SM_TOTAL (3 * SM_STAGE)     // 196608

template<int MODE>
__global__ __launch_bounds__(256)
void gemm_bf16x3(const __nv_bfloat16* __restrict__ Ahi, const __nv_bfloat16* __restrict__ Alo,
                 const __nv_bfloat16* __restrict__ Bhi, const __nv_bfloat16* __restrict__ Blo,
                 const float* __restrict__ bias, float* __restrict__ Cout,
                 __nv_bfloat16* __restrict__ qh, __nv_bfloat16* __restrict__ ql,
                 __nv_bfloat16* __restrict__ kh, __nv_bfloat16* __restrict__ kl,
                 __half* __restrict__ vh,
                 int M, int N, int K)
{
    extern __shared__ char smem[];
    const uint32_t sb = smem_to_u32(smem);

    const int tid  = threadIdx.x;
    const int wid  = tid >> 5;
    const int lane = tid & 31;
    const int rowBase = blockIdx.y * 128;
    const int colBase = blockIdx.x * 128;

    const int warp_m = wid & 1;
    const int warp_n = wid >> 1;

    float acc[4][4][4];
#pragma unroll
    for (int i = 0; i < 4; i++)
#pragma unroll
        for (int j = 0; j < 4; j++)
#pragma unroll
            for (int r = 0; r < 4; r++) acc[i][j][r] = 0.f;

    const int a_r  = warp_m * 64 + (lane & 15);
    const int a_cb = (lane >> 4) << 4;
    const int g    = lane >> 3;
    const int b_r  = warp_n * 32 + ((g >> 1) << 3) + (lane & 7);
    const int b_cb = (g & 1) << 4;

    int ld_r[4], ld_cb[4];
    uint32_t ld_sw[4];
#pragma unroll
    for (int it = 0; it < 4; it++) {
        int idx = it * 256 + tid;
        ld_r[it]  = idx >> 3;
        ld_cb[it] = (idx & 7) << 4;
        ld_sw[it] = swz((uint32_t)(ld_r[it] * 128 + ld_cb[it]));
    }

    auto issue = [&](int ch, int st) {
        const int k0 = ch * 64;
        const uint32_t sbase = sb + st * SM_STAGE;
#pragma unroll
        for (int it = 0; it < 4; it++) {
            const int r = ld_r[it], cb = ld_cb[it];
            const uint32_t sw = ld_sw[it];
            cp16(sbase + SM_AHI + sw, (const char*)(Ahi + (size_t)(rowBase + r) * K + k0) + cb);
            cp16(sbase + SM_ALO + sw, (const char*)(Alo + (size_t)(rowBase + r) * K + k0) + cb);
            cp16(sbase + SM_BHI + sw, (const char*)(Bhi + (size_t)(colBase + r) * K + k0) + cb);
            cp16(sbase + SM_BLO + sw, (const char*)(Blo + (size_t)(colBase + r) * K + k0) + cb);
        }
        cp_commit();
    };

    const int nChunks = K / 64;
    issue(0, 0);
    issue(1, 1);

    for (int ch = 0; ch < nChunks; ch++) {
        if (ch + 1 < nChunks) cp_wait<1>(); else cp_wait<0>();
        __syncthreads();
        if (ch + 2 < nChunks) issue(ch + 2, (ch + 2) % 3);

        const uint32_t sbase = sb + (ch % 3) * SM_STAGE;
#pragma unroll
        for (int ks = 0; ks < 4; ks++) {
            const int kb = ks * 32;
            uint32_t ah[4][4], al[4][4];
#pragma unroll
            for (int mi = 0; mi < 4; mi++) {
                uint32_t off = swz((uint32_t)((a_r + mi * 16) * 128 + kb + a_cb));
                ldsm_x4(ah[mi], sbase + SM_AHI + off);
                ldsm_x4(al[mi], sbase + SM_ALO + off);
            }
            uint32_t bh[2][4], bl[2][4];
#pragma unroll
            for (int nt = 0; nt < 2; nt++) {
                uint32_t off = swz((uint32_t)((b_r + nt * 16) * 128 + kb + b_cb));
                ldsm_x4(bh[nt], sbase + SM_BHI + off);
                ldsm_x4(bl[nt], sbase + SM_BLO + off);
            }
#pragma unroll
            for (int mi = 0; mi < 4; mi++)
#pragma unroll
                for (int nj = 0; nj < 4; nj++) {
                    const uint32_t* bhj = &bh[nj >> 1][(nj & 1) * 2];
                    const uint32_t* blj = &bl[nj >> 1][(nj & 1) * 2];
                    mma16816(acc[mi][nj], ah[mi], bhj[0], bhj[1]);
                    mma16816(acc[mi][nj], ah[mi], blj[0], blj[1]);
                    mma16816(acc[mi][nj], al[mi], bhj[0], bhj[1]);
                }
        }
    }

    const int er = rowBase + warp_m * 64 + (lane >> 2);
    const int ec = colBase + warp_n * 32 + (lane & 3) * 2;

    if (MODE == 0) {
#pragma unroll
        for (int mi = 0; mi < 4; mi++) {
#pragma unroll
            for (int nj = 0; nj < 4; nj++) {
                const int c = ec + nj * 8;
                const float bx = __ldg(bias + c);
                const float by = __ldg(bias + c + 1);
                float2 v0 = { acc[mi][nj][0] + bx, acc[mi][nj][1] + by };
                float2 v1 = { acc[mi][nj][2] + bx, acc[mi][nj][3] + by };
                *(float2*)(Cout + (size_t)(er + mi * 16) * N + c) = v0;
                *(float2*)(Cout + (size_t)(er + mi * 16 + 8) * N + c) = v1;
            }
        }
    } else {
        // MODE 1: scatter per-head; q/k split bf16 (q scaled), v plain fp16.
#pragma unroll
        for (int nj = 0; nj < 4; nj++) {
            const int c   = ec + nj * 8;
            const int sec = c >> 10;             // 0=q,1=k,2=v
            const int hh  = (c & 1023) >> 6;
            const int dd  = c & 63;
            const float sc = (sec == 0) ? QS : 1.f;
            const float bx = __ldg(bias + c)     * sc;
            const float by = __ldg(bias + c + 1) * sc;
#pragma unroll
            for (int mi = 0; mi < 4; mi++) {
#pragma unroll
                for (int half = 0; half < 2; half++) {
                    const int r = er + mi * 16 + half * 8;
                    const int bb = r >> 11, tt = r & 2047;
                    const size_t dst = (((size_t)bb * H_ + hh) * T_ + tt) * D_ + dd;
                    float v0 = fmaf(acc[mi][nj][half * 2],     sc, bx);
                    float v1 = fmaf(acc[mi][nj][half * 2 + 1], sc, by);
                    if (sec == 2) {
                        *(__half2*)(vh + dst) = __floats2half2_rn(v0, v1);
                    } else {
                        __nv_bfloat16* hp = (sec == 0) ? qh : kh;
                        __nv_bfloat16* lp = (sec == 0) ? ql : kl;
                        __nv_bfloat162 h2 = __floats2bfloat162_rn(v0, v1);
                        __nv_bfloat162 l2 = __floats2bfloat162_rn(
                            v0 - __bfloat162float(h2.x), v1 - __bfloat162float(h2.y));
                        *(__nv_bfloat162*)(hp + dst) = h2;
                        *(__nv_bfloat162*)(lp + dst) = l2;
                    }
                }
            }
        }
    }
}

// ---------------------------------------------------------------------------
// Flash attention: S split-bf16 x3, O = P*V in fp16 (single pair).
// cp.async 3-stage K/V pipeline, single sync per tile.
// Output: split-bf16 att [B*T, C] consumed by proj GEMM.
// ---------------------------------------------------------------------------
#define FA_QHI 0
#define FA_QLO 16384
#define FA_STAGE0 32768
#define FA_STSZ 24576
#define FA_ST(s) (FA_STAGE0 + (s) * FA_STSZ)
#define FA_KHI 0
#define FA_KLO 8192
#define FA_VH  16384
#define FA_TOTAL (FA_STAGE0 + 3 * FA_STSZ)   // 106496

__global__ __launch_bounds__(128)
void flash_attn(const __nv_bfloat16* __restrict__ qh, const __nv_bfloat16* __restrict__ ql,
                const __nv_bfloat16* __restrict__ kh, const __nv_bfloat16* __restrict__ kl,
                const __half* __restrict__ vh,
                __nv_bfloat16* __restrict__ ohi, __nv_bfloat16* __restrict__ olo)
{
    extern __shared__ char smem[];
    const uint32_t sb = smem_to_u32(smem);
    const int tid = threadIdx.x, wid = tid >> 5, lane = tid & 31;
    const int h = blockIdx.y, b = blockIdx.z;
    const int qt = gridDim.x - 1 - blockIdx.x;    // big tiles first

    const size_t hoff = ((size_t)b * H_ + h) * T_ * D_;
    const char* qh_p = (const char*)(qh + hoff + (size_t)qt * 128 * D_);
    const char* ql_p = (const char*)(ql + hoff + (size_t)qt * 128 * D_);
    const char* kh_p = (const char*)(kh + hoff);
    const char* kl_p = (const char*)(kl + hoff);
    const char* vh_p = (const char*)(vh + hoff);

    auto issue_kv = [&](int kt, int st) {
        const uint32_t sbase = sb + FA_ST(st);
#pragma unroll
        for (int it = 0; it < 4; it++) {
            int idx = it * 128 + tid;            // 0..511
            int r = idx >> 3, cb = (idx & 7) << 4;
            uint32_t sw = swz((uint32_t)(r * 128 + cb));
            size_t go = (size_t)(kt * 64 + r) * 128 + cb;    // bytes
            cp16(sbase + FA_KHI + sw, kh_p + go);
            cp16(sbase + FA_KLO + sw, kl_p + go);
            cp16(sbase + FA_VH  + sw, vh_p + go);
        }
        cp_commit();
    };

    const int nkt = 2 * qt + 2;
    issue_kv(0, 0);
    issue_kv(1, 1);

    // Load Q tiles (plain stores; covered by first in-loop barrier)
#pragma unroll
    for (int it = 0; it < 8; it++) {
        int idx = it * 128 + tid;
        int r = idx >> 3, cb = (idx & 7) << 4;
        uint32_t sw = swz((uint32_t)(r * 128 + cb));
        *(uint4*)(smem + FA_QHI + sw) = *(const uint4*)(qh_p + r * 128 + cb);
        *(uint4*)(smem + FA_QLO + sw) = *(const uint4*)(ql_p + r * 128 + cb);
    }

    float o[2][8][4];
#pragma unroll
    for (int mi = 0; mi < 2; mi++)
#pragma unroll
        for (int nj = 0; nj < 8; nj++)
#pragma unroll
            for (int r = 0; r < 4; r++) o[mi][nj][r] = 0.f;
    float ms[4] = { -1e30f, -1e30f, -1e30f, -1e30f };
    float ls[4] = { 0.f, 0.f, 0.f, 0.f };

    const int a_r  = wid * 32 + (lane & 15);
    const int a_cb = (lane >> 4) << 4;
    const int g    = lane >> 3;
    const int b_r  = ((g >> 1) << 3) + (lane & 7);
    const int b_cb = (g & 1) << 4;
    const int vrow = ((lane >> 3) & 1) * 8 + (lane & 7);
    const int vcb  = ((lane >> 4) & 1) * 16;

    for (int kt = 0; kt < nkt; kt++) {
        if (kt + 1 < nkt) cp_wait<1>(); else cp_wait<0>();
        __syncthreads();
        if (kt + 2 < nkt) issue_kv(kt + 2, (kt + 2) % 3);

        const uint32_t kv = sb + FA_ST(kt % 3);

        // ---- S = Q K^T (split x3) ----
        float s[2][8][4];
#pragma unroll
        for (int mi = 0; mi < 2; mi++)
#pragma unroll
            for (int nj = 0; nj < 8; nj++)
#pragma unroll
                for (int r = 0; r < 4; r++) s[mi][nj][r] = 0.f;

#pragma unroll
        for (int ks = 0; ks < 4; ks++) {
            uint32_t qhf[2][4], qlf[2][4];
#pragma unroll
            for (int mi = 0; mi < 2; mi++) {
                uint32_t off = swz((uint32_t)((a_r + mi * 16) * 128 + ks * 32 + a_cb));
                ldsm_x4(qhf[mi], sb + FA_QHI + off);
                ldsm_x4(qlf[mi], sb + FA_QLO + off);
            }
            uint32_t kbh[4][4], kbl[4][4];
#pragma unroll
            for (int nt = 0; nt < 4; nt++) {
                uint32_t off = swz((uint32_t)((b_r + nt * 16) * 128 + ks * 32 + b_cb));
                ldsm_x4(kbh[nt], kv + FA_KHI + off);
                ldsm_x4(kbl[nt], kv + FA_KLO + off);
            }
#pragma unroll
            for (int mi = 0; mi < 2; mi++)
#pragma unroll
                for (int nj = 0; nj < 8; nj++) {
                    const uint32_t* bhj = &kbh[nj >> 1][(nj & 1) * 2];
                    const uint32_t* blj = &kbl[nj >> 1][(nj & 1) * 2];
                    mma16816(s[mi][nj], qhf[mi], bhj[0], bhj[1]);
                    mma16816(s[mi][nj], qhf[mi], blj[0], blj[1]);
                    mma16816(s[mi][nj], qlf[mi], bhj[0], bhj[1]);
                }
        }

        // ---- causal mask (last two key tiles only) ----
        if (kt >= 2 * qt) {
            const int row0 = qt * 128 + wid * 32 + (lane >> 2);
            const int colb = kt * 64 + (lane & 3) * 2;
#pragma unroll
            for (int mi = 0; mi < 2; mi++) {
                const int r0 = row0 + mi * 16, r1 = r0 + 8;
#pragma unroll
                for (int nj = 0; nj < 8; nj++) {
                    const int c0 = colb + nj * 8, c1 = c0 + 1;
                    if (c0 > r0) s[mi][nj][0] = -1e30f;
                    if (c1 > r0) s[mi][nj][1] = -1e30f;
                    if (c0 > r1) s[mi][nj][2] = -1e30f;
                    if (c1 > r1) s[mi][nj][3] = -1e30f;
                }
            }
        }

        // ---- online softmax + pack P (fp16) ----
        uint32_t ph[2][4][4];
#pragma unroll
        for (int mi = 0; mi < 2; mi++) {
#pragma unroll
            for (int half = 0; half < 2; half++) {
                const int si = mi * 2 + half;
                float mx = -1e30f;
#pragma unroll
                for (int nj = 0; nj < 8; nj++)
                    mx = fmaxf(mx, fmaxf(s[mi][nj][half * 2], s[mi][nj][half * 2 + 1]));
                mx = fmaxf(mx, __shfl_xor_sync(0xffffffffu, mx, 1));
                mx = fmaxf(mx, __shfl_xor_sync(0xffffffffu, mx, 2));
                const float mnew = fmaxf(ms[si], mx);
                const float alpha = ex2(ms[si] - mnew);
                ms[si] = mnew;
                float rs = 0.f;
#pragma unroll
                for (int nj = 0; nj < 8; nj++) {
                    float p0 = ex2(s[mi][nj][half * 2]     - mnew);
                    float p1 = ex2(s[mi][nj][half * 2 + 1] - mnew);
                    s[mi][nj][half * 2]     = p0;
                    s[mi][nj][half * 2 + 1] = p1;
                    rs += p0 + p1;
                }
                rs += __shfl_xor_sync(0xffffffffu, rs, 1);
                rs += __shfl_xor_sync(0xffffffffu, rs, 2);
                ls[si] = ls[si] * alpha + rs;
#pragma unroll
                for (int nj = 0; nj < 8; nj++) {
                    o[mi][nj][half * 2]     *= alpha;
                    o[mi][nj][half * 2 + 1] *= alpha;
                }
            }
            // C-frag -> A-frag repack, fp16
#pragma unroll
            for (int ks = 0; ks < 4; ks++) {
#pragma unroll
                for (int rr = 0; rr < 4; rr++) {
                    const int nj = 2 * ks + (rr >> 1);
                    const int r0 = (rr & 1) * 2;
                    __half2 hh = __floats2half2_rn(s[mi][nj][r0], s[mi][nj][r0 + 1]);
                    ph[mi][ks][rr] = *(uint32_t*)&hh;
                }
            }
        }

        // ---- O += P V (fp16), V via ldmatrix.trans ----
#pragma unroll
        for (int ks = 0; ks < 4; ks++) {
#pragma unroll
            for (int nd = 0; nd < 4; nd++) {
                uint32_t vhf[4];
                uint32_t off = swz((uint32_t)((ks * 16 + vrow) * 128 + nd * 32 + vcb));
                ldsm_x4_t(vhf, kv + FA_VH + off);
#pragma unroll
                for (int mi = 0; mi < 2; mi++) {
                    mma16816h(o[mi][nd * 2],     ph[mi][ks], vhf[0], vhf[1]);
                    mma16816h(o[mi][nd * 2 + 1], ph[mi][ks], vhf[2], vhf[3]);
                }
            }
        }
    }

    // ---- epilogue: O / l -> split-bf16 att [B*T, C] ----
    float inv[4];
#pragma unroll
    for (int si = 0; si < 4; si++) inv[si] = 1.f / ls[si];
    const int er0 = qt * 128 + wid * 32 + (lane >> 2);
    const int ecb = h * 64 + (lane & 3) * 2;
#pragma unroll
    for (int mi = 0; mi < 2; mi++) {
        const size_t row = (size_t)b * T_ + er0 + mi * 16;
#pragma unroll
        for (int nj = 0; nj < 8; nj++) {
            float v0 = o[mi][nj][0] * inv[mi * 2];
            float v1 = o[mi][nj][1] * inv[mi * 2];
            float v2 = o[mi][nj][2] * inv[mi * 2 + 1];
            float v3 = o[mi][nj][3] * inv[mi * 2 + 1];
            __nv_bfloat162 h01 = __floats2bfloat162_rn(v0, v1);
            __nv_bfloat162 h23 = __floats2bfloat162_rn(v2, v3);
            __nv_bfloat162 l01 = __floats2bfloat162_rn(v0 - __bfloat162float(h01.x),
                                                       v1 - __bfloat162float(h01.y));
            __nv_bfloat162 l23 = __floats2bfloat162_rn(v2 - __bfloat162float(h23.x),
                                                       v3 - __bfloat162float(h23.y));
            *(__nv_bfloat162*)(ohi + row * C_ + ecb + nj * 8) = h01;
            *(__nv_bfloat162*)(olo + row * C_ + ecb + nj * 8) = l01;
            *(__nv_bfloat162*)(ohi + (row + 8) * C_ + ecb + nj * 8) = h23;
            *(__nv_bfloat162*)(olo + (row + 8) * C_ + ecb + nj * 8) = l23;
        }
    }
}

// ---------------------------------------------------------------------------
// Launch sequence
// ---------------------------------------------------------------------------
extern "C" void kernel_launch(void* const* d_in, const int* in_sizes, int n_in,
                              void* d_out, int out_size)
{
    const float* x      = (const float*)d_in[0];
    const float* w_qkv  = (const float*)d_in[1];
    const float* b_qkv  = (const float*)d_in[2];
    const float* w_proj = (const float*)d_in[3];
    const float* b_proj = (const float*)d_in[4];
    float* out = (float*)d_out;

    __nv_bfloat16 *xhi, *xlo, *wthi, *wtlo, *qh, *ql, *kh, *kl;
    __half *vh;
    cudaGetSymbolAddress((void**)&xhi, g_xhi);
    cudaGetSymbolAddress((void**)&xlo, g_xlo);
    cudaGetSymbolAddress((void**)&wthi, g_wthi);
    cudaGetSymbolAddress((void**)&wtlo, g_wtlo);
    cudaGetSymbolAddress((void**)&qh, g_qh);
    cudaGetSymbolAddress((void**)&ql, g_ql);
    cudaGetSymbolAddress((void**)&kh, g_kh);
    cudaGetSymbolAddress((void**)&kl, g_kl);
    cudaGetSymbolAddress((void**)&vh, g_vh);

    cudaFuncSetAttribute(gemm_bf16x3<0>, cudaFuncAttributeMaxDynamicSharedMemorySize, SM_TOTAL);
    cudaFuncSetAttribute(gemm_bf16x3<1>, cudaFuncAttributeMaxDynamicSharedMemorySize, SM_TOTAL);
    cudaFuncSetAttribute(flash_attn, cudaFuncAttributeMaxDynamicSharedMemorySize, FA_TOTAL);

    // 1) split x -> bf16 hi/lo
    {
        int n4 = (M_ROWS * C_) / 4;
        cvt_split<<<(n4 + 255) / 256, 256>>>(x, xhi, xlo, n4);
    }
    // 2) transpose+split w_qkv
    {
        dim3 grid(N_QKV / 32, C_ / 32);
        wsplit_transpose<<<grid, 256>>>(w_qkv, wthi, wtlo, C_, N_QKV);
    }
    // 3) QKV GEMM -> per-head q/k split bf16, v fp16 (fused epilogue)
    {
        dim3 grid(N_QKV / 128, M_ROWS / 128);
        gemm_bf16x3<1><<<grid, 256, SM_TOTAL>>>(xhi, xlo, wthi, wtlo, b_qkv, nullptr,
                                                qh, ql, kh, kl, vh,
                                                M_ROWS, N_QKV, C_);
    }
    // 4) flash attention -> split-bf16 att (reuses xhi/xlo)
    {
        dim3 grid(T_ / 128, H_, B_);
        flash_attn<<<grid, 128, FA_TOTAL>>>(qh, ql, kh, kl, vh, xhi, xlo);
    }
    // 5) transpose+split w_proj
    {
        dim3 grid(C_ / 32, C_ / 32);
        wsplit_transpose<<<grid, 256>>>(w_proj, wthi, wtlo, C_, C_);
    }
    // 6) proj GEMM -> fp32 out
    {
        dim3 grid(C_ / 128, M_ROWS / 128);
        gemm_bf16x3<0><<<grid, 256, SM_TOTAL>>>(xhi, xlo, wthi, wtlo, b_proj, out,
                                                nullptr, nullptr, nullptr, nullptr,
                                                nullptr,
                                                M_ROWS, C_, C_);
    }
}

// round 7
// speedup vs baseline: 4.0452x; 1.0139x over previous
#include <cuda_runtime.h>
#include <cuda_bf16.h>
#include <cuda_fp16.h>
#include <cstdint>

// ---------------------------------------------------------------------------
// Problem constants
// ---------------------------------------------------------------------------
#define B_ 2
#define T_ 2048
#define C_ 1024
#define H_ 16
#define D_ 64
#define M_ROWS (B_ * T_)     // 4096
#define N_QKV  (3 * C_)      // 3072

// softmax scale * log2(e) folded into Q: (1/8) * 1.4426950408889634
#define QS 0.18033688011112042f

// Scratch (__device__ globals; allocation-free rule)
__device__ __nv_bfloat16 g_xhi[(size_t)M_ROWS * C_];
__device__ __nv_bfloat16 g_xlo[(size_t)M_ROWS * C_];
__device__ __nv_bfloat16 g_wthi[(size_t)N_QKV * C_];
__device__ __nv_bfloat16 g_wtlo[(size_t)N_QKV * C_];
// per-head 16-bit tensors [B,H,T,D]: q/k split bf16 hi+lo, v plain fp16
__device__ __nv_bfloat16 g_qh[(size_t)B_ * H_ * T_ * D_];
__device__ __nv_bfloat16 g_ql[(size_t)B_ * H_ * T_ * D_];
__device__ __nv_bfloat16 g_kh[(size_t)B_ * H_ * T_ * D_];
__device__ __nv_bfloat16 g_kl[(size_t)B_ * H_ * T_ * D_];
__device__ __half        g_vh[(size_t)B_ * H_ * T_ * D_];

// ---------------------------------------------------------------------------
// Warp MMA / async-copy helpers (sm_80+ baseline)
// ---------------------------------------------------------------------------
__device__ __forceinline__ uint32_t smem_to_u32(const void* p) {
    uint32_t a;
    asm("{ .reg .u64 t; cvta.to.shared.u64 t, %1; cvt.u32.u64 %0, t; }"
        : "=r"(a) : "l"(p));
    return a;
}
__device__ __forceinline__ void ldsm_x4(uint32_t (&r)[4], uint32_t addr) {
    asm volatile("ldmatrix.sync.aligned.m8n8.x4.shared.b16 {%0,%1,%2,%3}, [%4];"
                 : "=r"(r[0]), "=r"(r[1]), "=r"(r[2]), "=r"(r[3]) : "r"(addr));
}
__device__ __forceinline__ void ldsm_x4_t(uint32_t (&r)[4], uint32_t addr) {
    asm volatile("ldmatrix.sync.aligned.m8n8.x4.trans.shared.b16 {%0,%1,%2,%3}, [%4];"
                 : "=r"(r[0]), "=r"(r[1]), "=r"(r[2]), "=r"(r[3]) : "r"(addr));
}
__device__ __forceinline__ void mma16816(float (&d)[4],
                                         const uint32_t (&a)[4],
                                         const uint32_t b0, const uint32_t b1) {
    asm volatile(
        "mma.sync.aligned.m16n8k16.row.col.f32.bf16.bf16.f32 "
        "{%0,%1,%2,%3}, {%4,%5,%6,%7}, {%8,%9}, {%0,%1,%2,%3};"
        : "+f"(d[0]), "+f"(d[1]), "+f"(d[2]), "+f"(d[3])
        : "r"(a[0]), "r"(a[1]), "r"(a[2]), "r"(a[3]), "r"(b0), "r"(b1));
}
__device__ __forceinline__ void mma16816h(float (&d)[4],
                                          const uint32_t (&a)[4],
                                          const uint32_t b0, const uint32_t b1) {
    asm volatile(
        "mma.sync.aligned.m16n8k16.row.col.f32.f16.f16.f32 "
        "{%0,%1,%2,%3}, {%4,%5,%6,%7}, {%8,%9}, {%0,%1,%2,%3};"
        : "+f"(d[0]), "+f"(d[1]), "+f"(d[2]), "+f"(d[3])
        : "r"(a[0]), "r"(a[1]), "r"(a[2]), "r"(a[3]), "r"(b0), "r"(b1));
}
__device__ __forceinline__ uint32_t swz(uint32_t off) {
    return off ^ ((off >> 3) & 0x70);
}
__device__ __forceinline__ float ex2(float x) {
    float y; asm("ex2.approx.ftz.f32 %0, %1;" : "=f"(y) : "f"(x)); return y;
}
__device__ __forceinline__ void cp16(uint32_t dst, const void* src) {
    asm volatile("cp.async.ca.shared.global [%0], [%1], 16;" :: "r"(dst), "l"(src));
}
__device__ __forceinline__ void cp_commit() {
    asm volatile("cp.async.commit_group;" ::: "memory");
}
template<int N> __device__ __forceinline__ void cp_wait() {
    asm volatile("cp.async.wait_group %0;" :: "n"(N) : "memory");
}

// ---------------------------------------------------------------------------
// Prepass 1: split fp32 -> (bf16 hi, bf16 lo)
// ---------------------------------------------------------------------------
__global__ __launch_bounds__(256)
void cvt_split(const float* __restrict__ src,
               __nv_bfloat16* __restrict__ hi, __nv_bfloat16* __restrict__ lo, int n4)
{
    int i = blockIdx.x * 256 + threadIdx.x;
    if (i >= n4) return;
    float4 v = ((const float4*)src)[i];
    __nv_bfloat162 h01 = __floats2bfloat162_rn(v.x, v.y);
    __nv_bfloat162 h23 = __floats2bfloat162_rn(v.z, v.w);
    __nv_bfloat162 l01 = __floats2bfloat162_rn(v.x - __bfloat162float(h01.x),
                                               v.y - __bfloat162float(h01.y));
    __nv_bfloat162 l23 = __floats2bfloat162_rn(v.z - __bfloat162float(h23.x),
                                               v.w - __bfloat162float(h23.y));
    ((__nv_bfloat162*)hi)[i * 2 + 0] = h01;
    ((__nv_bfloat162*)hi)[i * 2 + 1] = h23;
    ((__nv_bfloat162*)lo)[i * 2 + 0] = l01;
    ((__nv_bfloat162*)lo)[i * 2 + 1] = l23;
}

// ---------------------------------------------------------------------------
// Prepass 2: W [K,N] fp32 -> W^T hi/lo [N,K] bf16
// ---------------------------------------------------------------------------
__global__ __launch_bounds__(256)
void wsplit_transpose(const float* __restrict__ W,
                      __nv_bfloat16* __restrict__ Thi, __nv_bfloat16* __restrict__ Tlo,
                      int K, int N)
{
    __shared__ float tile[32][33];
    const int tx = threadIdx.x & 31;
    const int ty = threadIdx.x >> 5;
    const int k0 = blockIdx.y * 32;
    const int n0 = blockIdx.x * 32;
#pragma unroll
    for (int r = ty; r < 32; r += 8)
        tile[r][tx] = W[(size_t)(k0 + r) * N + n0 + tx];
    __syncthreads();
#pragma unroll
    for (int r = ty; r < 32; r += 8) {
        float v = tile[tx][r];
        __nv_bfloat16 h = __float2bfloat16(v);
        __nv_bfloat16 l = __float2bfloat16(v - __bfloat162float(h));
        size_t o = (size_t)(n0 + r) * K + k0 + tx;
        Thi[o] = h;
        Tlo[o] = l;
    }
}

// ---------------------------------------------------------------------------
// HMMA GEMM, split-bf16 x3, cp.async 3-stage pipeline, 512 threads (16 warps,
// 4/SMSP), warp tile 32x32.
// MODE 0: write fp32 C + bias (final proj).
// MODE 1: write per-head q/k (split bf16, Q scaled by QS) and v (fp16).
// ---------------------------------------------------------------------------
#define SM_AHI 0
#define SM_ALO 16384
#define SM_BHI 32768
#define SM_BLO 49152
#define SM_STAGE 65536
#define SM_TOTAL (3 * SM_STAGE)     // 196608

template<int MODE>
__global__ __launch_bounds__(512)
void gemm_bf16x3(const __nv_bfloat16* __restrict__ Ahi, const __nv_bfloat16* __restrict__ Alo,
                 const __nv_bfloat16* __restrict__ Bhi, const __nv_bfloat16* __restrict__ Blo,
                 const float* __restrict__ bias, float* __restrict__ Cout,
                 __nv_bfloat16* __restrict__ qh, __nv_bfloat16* __restrict__ ql,
                 __nv_bfloat16* __restrict__ kh, __nv_bfloat16* __restrict__ kl,
                 __half* __restrict__ vh,
                 int M, int N, int K)
{
    extern __shared__ char smem[];
    const uint32_t sb = smem_to_u32(smem);

    const int tid  = threadIdx.x;
    const int wid  = tid >> 5;
    const int lane = tid & 31;
    const int rowBase = blockIdx.y * 128;
    const int colBase = blockIdx.x * 128;

    const int warp_m = wid & 3;        // 4 x 32-row quarters
    const int warp_n = wid >> 2;       // 4 x 32-col quarters

    float acc[2][4][4];
#pragma unroll
    for (int i = 0; i < 2; i++)
#pragma unroll
        for (int j = 0; j < 4; j++)
#pragma unroll
            for (int r = 0; r < 4; r++) acc[i][j][r] = 0.f;

    const int a_r  = warp_m * 32 + (lane & 15);
    const int a_cb = (lane >> 4) << 4;
    const int g    = lane >> 3;
    const int b_r  = warp_n * 32 + ((g >> 1) << 3) + (lane & 7);
    const int b_cb = (g & 1) << 4;

    // per-thread load slots: 1024 uint4 per tile / 512 threads = 2 each
    int ld_r[2], ld_cb[2];
    uint32_t ld_sw[2];
#pragma unroll
    for (int it = 0; it < 2; it++) {
        int idx = it * 512 + tid;
        ld_r[it]  = idx >> 3;
        ld_cb[it] = (idx & 7) << 4;
        ld_sw[it] = swz((uint32_t)(ld_r[it] * 128 + ld_cb[it]));
    }

    auto issue = [&](int ch, int st) {
        const int k0 = ch * 64;
        const uint32_t sbase = sb + st * SM_STAGE;
#pragma unroll
        for (int it = 0; it < 2; it++) {
            const int r = ld_r[it], cb = ld_cb[it];
            const uint32_t sw = ld_sw[it];
            cp16(sbase + SM_AHI + sw, (const char*)(Ahi + (size_t)(rowBase + r) * K + k0) + cb);
            cp16(sbase + SM_ALO + sw, (const char*)(Alo + (size_t)(rowBase + r) * K + k0) + cb);
            cp16(sbase + SM_BHI + sw, (const char*)(Bhi + (size_t)(colBase + r) * K + k0) + cb);
            cp16(sbase + SM_BLO + sw, (const char*)(Blo + (size_t)(colBase + r) * K + k0) + cb);
        }
        cp_commit();
    };

    const int nChunks = K / 64;
    issue(0, 0);
    issue(1, 1);

    for (int ch = 0; ch < nChunks; ch++) {
        if (ch + 1 < nChunks) cp_wait<1>(); else cp_wait<0>();
        __syncthreads();
        if (ch + 2 < nChunks) issue(ch + 2, (ch + 2) % 3);

        const uint32_t sbase = sb + (ch % 3) * SM_STAGE;
#pragma unroll
        for (int ks = 0; ks < 4; ks++) {
            const int kb = ks * 32;
            uint32_t ah[2][4], al[2][4];
#pragma unroll
            for (int mi = 0; mi < 2; mi++) {
                uint32_t off = swz((uint32_t)((a_r + mi * 16) * 128 + kb + a_cb));
                ldsm_x4(ah[mi], sbase + SM_AHI + off);
                ldsm_x4(al[mi], sbase + SM_ALO + off);
            }
            uint32_t bh[2][4], bl[2][4];
#pragma unroll
            for (int nt = 0; nt < 2; nt++) {
                uint32_t off = swz((uint32_t)((b_r + nt * 16) * 128 + kb + b_cb));
                ldsm_x4(bh[nt], sbase + SM_BHI + off);
                ldsm_x4(bl[nt], sbase + SM_BLO + off);
            }
#pragma unroll
            for (int mi = 0; mi < 2; mi++)
#pragma unroll
                for (int nj = 0; nj < 4; nj++) {
                    const uint32_t* bhj = &bh[nj >> 1][(nj & 1) * 2];
                    const uint32_t* blj = &bl[nj >> 1][(nj & 1) * 2];
                    mma16816(acc[mi][nj], ah[mi], bhj[0], bhj[1]);
                    mma16816(acc[mi][nj], ah[mi], blj[0], blj[1]);
                    mma16816(acc[mi][nj], al[mi], bhj[0], bhj[1]);
                }
        }
    }

    const int er = rowBase + warp_m * 32 + (lane >> 2);
    const int ec = colBase + warp_n * 32 + (lane & 3) * 2;

    if (MODE == 0) {
#pragma unroll
        for (int mi = 0; mi < 2; mi++) {
#pragma unroll
            for (int nj = 0; nj < 4; nj++) {
                const int c = ec + nj * 8;
                const float bx = __ldg(bias + c);
                const float by = __ldg(bias + c + 1);
                float2 v0 = { acc[mi][nj][0] + bx, acc[mi][nj][1] + by };
                float2 v1 = { acc[mi][nj][2] + bx, acc[mi][nj][3] + by };
                *(float2*)(Cout + (size_t)(er + mi * 16) * N + c) = v0;
                *(float2*)(Cout + (size_t)(er + mi * 16 + 8) * N + c) = v1;
            }
        }
    } else {
        // MODE 1: scatter per-head; q/k split bf16 (q scaled), v plain fp16.
#pragma unroll
        for (int nj = 0; nj < 4; nj++) {
            const int c   = ec + nj * 8;
            const int sec = c >> 10;             // 0=q,1=k,2=v
            const int hh  = (c & 1023) >> 6;
            const int dd  = c & 63;
            const float sc = (sec == 0) ? QS : 1.f;
            const float bx = __ldg(bias + c)     * sc;
            const float by = __ldg(bias + c + 1) * sc;
#pragma unroll
            for (int mi = 0; mi < 2; mi++) {
#pragma unroll
                for (int half = 0; half < 2; half++) {
                    const int r = er + mi * 16 + half * 8;
                    const int bb = r >> 11, tt = r & 2047;
                    const size_t dst = (((size_t)bb * H_ + hh) * T_ + tt) * D_ + dd;
                    float v0 = fmaf(acc[mi][nj][half * 2],     sc, bx);
                    float v1 = fmaf(acc[mi][nj][half * 2 + 1], sc, by);
                    if (sec == 2) {
                        *(__half2*)(vh + dst) = __floats2half2_rn(v0, v1);
                    } else {
                        __nv_bfloat16* hp = (sec == 0) ? qh : kh;
                        __nv_bfloat16* lp = (sec == 0) ? ql : kl;
                        __nv_bfloat162 h2 = __floats2bfloat162_rn(v0, v1);
                        __nv_bfloat162 l2 = __floats2bfloat162_rn(
                            v0 - __bfloat162float(h2.x), v1 - __bfloat162float(h2.y));
                        *(__nv_bfloat162*)(hp + dst) = h2;
                        *(__nv_bfloat162*)(lp + dst) = l2;
                    }
                }
            }
        }
    }
}

// ---------------------------------------------------------------------------
// Flash attention: S split-bf16 x3, O = P*V fp16, NO online max (m=0 —
// softmax(s)=2^s/sum(2^s) is invariant; logits bounded so 2^s safe in fp32,
// P safe in fp16). l accumulated per-thread, reduced once in epilogue.
// cp.async 3-stage K/V pipeline.
// ---------------------------------------------------------------------------
#define FA_QHI 0
#define FA_QLO 16384
#define FA_STAGE0 32768
#define FA_STSZ 24576
#define FA_ST(s) (FA_STAGE0 + (s) * FA_STSZ)
#define FA_KHI 0
#define FA_KLO 8192
#define FA_VH  16384
#define FA_TOTAL (FA_STAGE0 + 3 * FA_STSZ)   // 106496

__global__ __launch_bounds__(128)
void flash_attn(const __nv_bfloat16* __restrict__ qh, const __nv_bfloat16* __restrict__ ql,
                const __nv_bfloat16* __restrict__ kh, const __nv_bfloat16* __restrict__ kl,
                const __half* __restrict__ vh,
                __nv_bfloat16* __restrict__ ohi, __nv_bfloat16* __restrict__ olo)
{
    extern __shared__ char smem[];
    const uint32_t sb = smem_to_u32(smem);
    const int tid = threadIdx.x, wid = tid >> 5, lane = tid & 31;
    const int h = blockIdx.y, b = blockIdx.z;
    const int qt = gridDim.x - 1 - blockIdx.x;    // big tiles first

    const size_t hoff = ((size_t)b * H_ + h) * T_ * D_;
    const char* qh_p = (const char*)(qh + hoff + (size_t)qt * 128 * D_);
    const char* ql_p = (const char*)(ql + hoff + (size_t)qt * 128 * D_);
    const char* kh_p = (const char*)(kh + hoff);
    const char* kl_p = (const char*)(kl + hoff);
    const char* vh_p = (const char*)(vh + hoff);

    auto issue_kv = [&](int kt, int st) {
        const uint32_t sbase = sb + FA_ST(st);
#pragma unroll
        for (int it = 0; it < 4; it++) {
            int idx = it * 128 + tid;            // 0..511
            int r = idx >> 3, cb = (idx & 7) << 4;
            uint32_t sw = swz((uint32_t)(r * 128 + cb));
            size_t go = (size_t)(kt * 64 + r) * 128 + cb;    // bytes
            cp16(sbase + FA_KHI + sw, kh_p + go);
            cp16(sbase + FA_KLO + sw, kl_p + go);
            cp16(sbase + FA_VH  + sw, vh_p + go);
        }
        cp_commit();
    };

    const int nkt = 2 * qt + 2;
    issue_kv(0, 0);
    issue_kv(1, 1);

    // Load Q tiles (plain stores; covered by first in-loop barrier)
#pragma unroll
    for (int it = 0; it < 8; it++) {
        int idx = it * 128 + tid;
        int r = idx >> 3, cb = (idx & 7) << 4;
        uint32_t sw = swz((uint32_t)(r * 128 + cb));
        *(uint4*)(smem + FA_QHI + sw) = *(const uint4*)(qh_p + r * 128 + cb);
        *(uint4*)(smem + FA_QLO + sw) = *(const uint4*)(ql_p + r * 128 + cb);
    }

    float o[2][8][4];
#pragma unroll
    for (int mi = 0; mi < 2; mi++)
#pragma unroll
        for (int nj = 0; nj < 8; nj++)
#pragma unroll
            for (int r = 0; r < 4; r++) o[mi][nj][r] = 0.f;
    float ls[4] = { 0.f, 0.f, 0.f, 0.f };   // per-thread partial row sums

    const int a_r  = wid * 32 + (lane & 15);
    const int a_cb = (lane >> 4) << 4;
    const int g    = lane >> 3;
    const int b_r  = ((g >> 1) << 3) + (lane & 7);
    const int b_cb = (g & 1) << 4;
    const int vrow = ((lane >> 3) & 1) * 8 + (lane & 7);
    const int vcb  = ((lane >> 4) & 1) * 16;

    for (int kt = 0; kt < nkt; kt++) {
        if (kt + 1 < nkt) cp_wait<1>(); else cp_wait<0>();
        __syncthreads();
        if (kt + 2 < nkt) issue_kv(kt + 2, (kt + 2) % 3);

        const uint32_t kv = sb + FA_ST(kt % 3);

        // ---- S = Q K^T (split x3) ----
        float s[2][8][4];
#pragma unroll
        for (int mi = 0; mi < 2; mi++)
#pragma unroll
            for (int nj = 0; nj < 8; nj++)
#pragma unroll
                for (int r = 0; r < 4; r++) s[mi][nj][r] = 0.f;

#pragma unroll
        for (int ks = 0; ks < 4; ks++) {
            uint32_t qhf[2][4], qlf[2][4];
#pragma unroll
            for (int mi = 0; mi < 2; mi++) {
                uint32_t off = swz((uint32_t)((a_r + mi * 16) * 128 + ks * 32 + a_cb));
                ldsm_x4(qhf[mi], sb + FA_QHI + off);
                ldsm_x4(qlf[mi], sb + FA_QLO + off);
            }
            uint32_t kbh[4][4], kbl[4][4];
#pragma unroll
            for (int nt = 0; nt < 4; nt++) {
                uint32_t off = swz((uint32_t)((b_r + nt * 16) * 128 + ks * 32 + b_cb));
                ldsm_x4(kbh[nt], kv + FA_KHI + off);
                ldsm_x4(kbl[nt], kv + FA_KLO + off);
            }
#pragma unroll
            for (int mi = 0; mi < 2; mi++)
#pragma unroll
                for (int nj = 0; nj < 8; nj++) {
                    const uint32_t* bhj = &kbh[nj >> 1][(nj & 1) * 2];
                    const uint32_t* blj = &kbl[nj >> 1][(nj & 1) * 2];
                    mma16816(s[mi][nj], qhf[mi], bhj[0], bhj[1]);
                    mma16816(s[mi][nj], qhf[mi], blj[0], blj[1]);
                    mma16816(s[mi][nj], qlf[mi], bhj[0], bhj[1]);
                }
        }

        // ---- causal mask (last two key tiles only) ----
        if (kt >= 2 * qt) {
            const int row0 = qt * 128 + wid * 32 + (lane >> 2);
            const int colb = kt * 64 + (lane & 3) * 2;
#pragma unroll
            for (int mi = 0; mi < 2; mi++) {
                const int r0 = row0 + mi * 16, r1 = r0 + 8;
#pragma unroll
                for (int nj = 0; nj < 8; nj++) {
                    const int c0 = colb + nj * 8, c1 = c0 + 1;
                    if (c0 > r0) s[mi][nj][0] = -1e30f;
                    if (c1 > r0) s[mi][nj][1] = -1e30f;
                    if (c0 > r1) s[mi][nj][2] = -1e30f;
                    if (c1 > r1) s[mi][nj][3] = -1e30f;
                }
            }
        }

        // ---- p = 2^s (no max), accumulate l, pack P fp16 ----
        uint32_t ph[2][4][4];
#pragma unroll
        for (int mi = 0; mi < 2; mi++) {
#pragma unroll
            for (int nj = 0; nj < 8; nj++) {
                float p0 = ex2(s[mi][nj][0]);
                float p1 = ex2(s[mi][nj][1]);
                float p2 = ex2(s[mi][nj][2]);
                float p3 = ex2(s[mi][nj][3]);
                s[mi][nj][0] = p0; s[mi][nj][1] = p1;
                s[mi][nj][2] = p2; s[mi][nj][3] = p3;
                ls[mi * 2 + 0] += p0 + p1;
                ls[mi * 2 + 1] += p2 + p3;
            }
            // C-frag -> A-frag repack, fp16
#pragma unroll
            for (int ks = 0; ks < 4; ks++) {
#pragma unroll
                for (int rr = 0; rr < 4; rr++) {
                    const int nj = 2 * ks + (rr >> 1);
                    const int r0 = (rr & 1) * 2;
                    __half2 hh = __floats2half2_rn(s[mi][nj][r0], s[mi][nj][r0 + 1]);
                    ph[mi][ks][rr] = *(uint32_t*)&hh;
                }
            }
        }

        // ---- O += P V (fp16), V via ldmatrix.trans ----
#pragma unroll
        for (int ks = 0; ks < 4; ks++) {
#pragma unroll
            for (int nd = 0; nd < 4; nd++) {
                uint32_t vhf[4];
                uint32_t off = swz((uint32_t)((ks * 16 + vrow) * 128 + nd * 32 + vcb));
                ldsm_x4_t(vhf, kv + FA_VH + off);
#pragma unroll
                for (int mi = 0; mi < 2; mi++) {
                    mma16816h(o[mi][nd * 2],     ph[mi][ks], vhf[0], vhf[1]);
                    mma16816h(o[mi][nd * 2 + 1], ph[mi][ks], vhf[2], vhf[3]);
                }
            }
        }
    }

    // ---- epilogue: reduce l across quad lanes, O / l -> split-bf16 att ----
    float inv[4];
#pragma unroll
    for (int si = 0; si < 4; si++) {
        float l = ls[si];
        l += __shfl_xor_sync(0xffffffffu, l, 1);
        l += __shfl_xor_sync(0xffffffffu, l, 2);
        inv[si] = 1.f / l;
    }
    const int er0 = qt * 128 + wid * 32 + (lane >> 2);
    const int ecb = h * 64 + (lane & 3) * 2;
#pragma unroll
    for (int mi = 0; mi < 2; mi++) {
        const size_t row = (size_t)b * T_ + er0 + mi * 16;
#pragma unroll
        for (int nj = 0; nj < 8; nj++) {
            float v0 = o[mi][nj][0] * inv[mi * 2];
            float v1 = o[mi][nj][1] * inv[mi * 2];
            float v2 = o[mi][nj][2] * inv[mi * 2 + 1];
            float v3 = o[mi][nj][3] * inv[mi * 2 + 1];
            __nv_bfloat162 h01 = __floats2bfloat162_rn(v0, v1);
            __nv_bfloat162 h23 = __floats2bfloat162_rn(v2, v3);
            __nv_bfloat162 l01 = __floats2bfloat162_rn(v0 - __bfloat162float(h01.x),
                                                       v1 - __bfloat162float(h01.y));
            __nv_bfloat162 l23 = __floats2bfloat162_rn(v2 - __bfloat162float(h23.x),
                                                       v3 - __bfloat162float(h23.y));
            *(__nv_bfloat162*)(ohi + row * C_ + ecb + nj * 8) = h01;
            *(__nv_bfloat162*)(olo + row * C_ + ecb + nj * 8) = l01;
            *(__nv_bfloat162*)(ohi + (row + 8) * C_ + ecb + nj * 8) = h23;
            *(__nv_bfloat162*)(olo + (row + 8) * C_ + ecb + nj * 8) = l23;
        }
    }
}

// ---------------------------------------------------------------------------
// Launch sequence
// ---------------------------------------------------------------------------
extern "C" void kernel_launch(void* const* d_in, const int* in_sizes, int n_in,
                              void* d_out, int out_size)
{
    const float* x      = (const float*)d_in[0];
    const float* w_qkv  = (const float*)d_in[1];
    const float* b_qkv  = (const float*)d_in[2];
    const float* w_proj = (const float*)d_in[3];
    const float* b_proj = (const float*)d_in[4];
    float* out = (float*)d_out;

    __nv_bfloat16 *xhi, *xlo, *wthi, *wtlo, *qh, *ql, *kh, *kl;
    __half *vh;
    cudaGetSymbolAddress((void**)&xhi, g_xhi);
    cudaGetSymbolAddress((void**)&xlo, g_xlo);
    cudaGetSymbolAddress((void**)&wthi, g_wthi);
    cudaGetSymbolAddress((void**)&wtlo, g_wtlo);
    cudaGetSymbolAddress((void**)&qh, g_qh);
    cudaGetSymbolAddress((void**)&ql, g_ql);
    cudaGetSymbolAddress((void**)&kh, g_kh);
    cudaGetSymbolAddress((void**)&kl, g_kl);
    cudaGetSymbolAddress((void**)&vh, g_vh);

    cudaFuncSetAttribute(gemm_bf16x3<0>, cudaFuncAttributeMaxDynamicSharedMemorySize, SM_TOTAL);
    cudaFuncSetAttribute(gemm_bf16x3<1>, cudaFuncAttributeMaxDynamicSharedMemorySize, SM_TOTAL);
    cudaFuncSetAttribute(flash_attn, cudaFuncAttributeMaxDynamicSharedMemorySize, FA_TOTAL);

    // 1) split x -> bf16 hi/lo
    {
        int n4 = (M_ROWS * C_) / 4;
        cvt_split<<<(n4 + 255) / 256, 256>>>(x, xhi, xlo, n4);
    }
    // 2) transpose+split w_qkv
    {
        dim3 grid(N_QKV / 32, C_ / 32);
        wsplit_transpose<<<grid, 256>>>(w_qkv, wthi, wtlo, C_, N_QKV);
    }
    // 3) QKV GEMM -> per-head q/k split bf16, v fp16 (fused epilogue)
    {
        dim3 grid(N_QKV / 128, M_ROWS / 128);
        gemm_bf16x3<1><<<grid, 512, SM_TOTAL>>>(xhi, xlo, wthi, wtlo, b_qkv, nullptr,
                                                qh, ql, kh, kl, vh,
                                                M_ROWS, N_QKV, C_);
    }
    // 4) flash attention -> split-bf16 att (reuses xhi/xlo)
    {
        dim3 grid(T_ / 128, H_, B_);
        flash_attn<<<grid, 128, FA_TOTAL>>>(qh, ql, kh, kl, vh, xhi, xlo);
    }
    // 5) transpose+split w_proj
    {
        dim3 grid(C_ / 32, C_ / 32);
        wsplit_transpose<<<grid, 256>>>(w_proj, wthi, wtlo, C_, C_);
    }
    // 6) proj GEMM -> fp32 out
    {
        dim3 grid(C_ / 128, M_ROWS / 128);
        gemm_bf16x3<0><<<grid, 512, SM_TOTAL>>>(xhi, xlo, wthi, wtlo, b_proj, out,
                                                nullptr, nullptr, nullptr, nullptr,
                                                nullptr,
                                                M_ROWS, C_, C_);
    }
}

// round 8
// speedup vs baseline: 5.8539x; 1.4471x over previous
#include <cuda_runtime.h>
#include <cuda_bf16.h>
#include <cuda_fp16.h>
#include <cstdint>

// ---------------------------------------------------------------------------
// Problem constants
// ---------------------------------------------------------------------------
#define B_ 2
#define T_ 2048
#define C_ 1024
#define H_ 16
#define D_ 64
#define M_ROWS (B_ * T_)     // 4096
#define N_QKV  (3 * C_)      // 3072

// softmax scale * log2(e) folded into Q: (1/8) * 1.4426950408889634
#define QS 0.18033688011112042f

// Scratch (__device__ globals; allocation-free rule)
__device__ __half g_xh[(size_t)M_ROWS * C_];        // activations fp16 (x, then att)
__device__ __half g_wh[(size_t)N_QKV * C_];         // W^T hi fp16 [N,K]
__device__ __half g_wl[(size_t)N_QKV * C_];         // W^T lo fp16 [N,K]
// per-head fp16 [B,H,T,D]
__device__ __half g_qh[(size_t)B_ * H_ * T_ * D_];  // q (pre-scaled by QS)
__device__ __half g_kh[(size_t)B_ * H_ * T_ * D_];
__device__ __half g_vh[(size_t)B_ * H_ * T_ * D_];

// ---------------------------------------------------------------------------
// Warp MMA / async-copy helpers (sm_80+ baseline)
// ---------------------------------------------------------------------------
__device__ __forceinline__ uint32_t smem_to_u32(const void* p) {
    uint32_t a;
    asm("{ .reg .u64 t; cvta.to.shared.u64 t, %1; cvt.u32.u64 %0, t; }"
        : "=r"(a) : "l"(p));
    return a;
}
__device__ __forceinline__ void ldsm_x4(uint32_t (&r)[4], uint32_t addr) {
    asm volatile("ldmatrix.sync.aligned.m8n8.x4.shared.b16 {%0,%1,%2,%3}, [%4];"
                 : "=r"(r[0]), "=r"(r[1]), "=r"(r[2]), "=r"(r[3]) : "r"(addr));
}
__device__ __forceinline__ void ldsm_x4_t(uint32_t (&r)[4], uint32_t addr) {
    asm volatile("ldmatrix.sync.aligned.m8n8.x4.trans.shared.b16 {%0,%1,%2,%3}, [%4];"
                 : "=r"(r[0]), "=r"(r[1]), "=r"(r[2]), "=r"(r[3]) : "r"(addr));
}
__device__ __forceinline__ void mma16816h(float (&d)[4],
                                          const uint32_t (&a)[4],
                                          const uint32_t b0, const uint32_t b1) {
    asm volatile(
        "mma.sync.aligned.m16n8k16.row.col.f32.f16.f16.f32 "
        "{%0,%1,%2,%3}, {%4,%5,%6,%7}, {%8,%9}, {%0,%1,%2,%3};"
        : "+f"(d[0]), "+f"(d[1]), "+f"(d[2]), "+f"(d[3])
        : "r"(a[0]), "r"(a[1]), "r"(a[2]), "r"(a[3]), "r"(b0), "r"(b1));
}
__device__ __forceinline__ uint32_t swz(uint32_t off) {
    return off ^ ((off >> 3) & 0x70);
}
__device__ __forceinline__ float ex2(float x) {
    float y; asm("ex2.approx.ftz.f32 %0, %1;" : "=f"(y) : "f"(x)); return y;
}
__device__ __forceinline__ void cp16(uint32_t dst, const void* src) {
    asm volatile("cp.async.ca.shared.global [%0], [%1], 16;" :: "r"(dst), "l"(src));
}
__device__ __forceinline__ void cp_commit() {
    asm volatile("cp.async.commit_group;" ::: "memory");
}
template<int N> __device__ __forceinline__ void cp_wait() {
    asm volatile("cp.async.wait_group %0;" :: "n"(N) : "memory");
}

// ---------------------------------------------------------------------------
// Prepass 1: fp32 -> fp16
// ---------------------------------------------------------------------------
__global__ __launch_bounds__(256)
void cvt_f16(const float* __restrict__ src, __half* __restrict__ dst, int n4)
{
    int i = blockIdx.x * 256 + threadIdx.x;
    if (i >= n4) return;
    float4 v = ((const float4*)src)[i];
    ((__half2*)dst)[i * 2 + 0] = __floats2half2_rn(v.x, v.y);
    ((__half2*)dst)[i * 2 + 1] = __floats2half2_rn(v.z, v.w);
}

// ---------------------------------------------------------------------------
// Prepass 2: W [K,N] fp32 -> W^T hi/lo [N,K] fp16 (split)
// ---------------------------------------------------------------------------
__global__ __launch_bounds__(256)
void wsplit_transpose(const float* __restrict__ W,
                      __half* __restrict__ Thi, __half* __restrict__ Tlo,
                      int K, int N)
{
    __shared__ float tile[32][33];
    const int tx = threadIdx.x & 31;
    const int ty = threadIdx.x >> 5;
    const int k0 = blockIdx.y * 32;
    const int n0 = blockIdx.x * 32;
#pragma unroll
    for (int r = ty; r < 32; r += 8)
        tile[r][tx] = W[(size_t)(k0 + r) * N + n0 + tx];
    __syncthreads();
#pragma unroll
    for (int r = ty; r < 32; r += 8) {
        float v = tile[tx][r];
        __half h = __float2half_rn(v);
        __half l = __float2half_rn(v - __half2float(h));
        size_t o = (size_t)(n0 + r) * K + k0 + tx;
        Thi[o] = h;
        Tlo[o] = l;
    }
}

// ---------------------------------------------------------------------------
// HMMA GEMM fp16: A single, W split (2 MMA terms). cp.async 3-stage pipeline,
// 512 threads (16 warps), warp tile 32x32.
// MODE 0: fp32 C + bias.  MODE 1: per-head q (scaled)/k/v fp16.
// ---------------------------------------------------------------------------
#define SM_A  0
#define SM_BH 16384
#define SM_BL 32768
#define SM_STAGE 49152
#define SM_TOTAL (3 * SM_STAGE)     // 147456

template<int MODE>
__global__ __launch_bounds__(512)
void gemm_f16w2(const __half* __restrict__ A,
                const __half* __restrict__ Bhi, const __half* __restrict__ Blo,
                const float* __restrict__ bias, float* __restrict__ Cout,
                __half* __restrict__ qh, __half* __restrict__ kh,
                __half* __restrict__ vh,
                int M, int N, int K)
{
    extern __shared__ char smem[];
    const uint32_t sb = smem_to_u32(smem);

    const int tid  = threadIdx.x;
    const int wid  = tid >> 5;
    const int lane = tid & 31;
    const int rowBase = blockIdx.y * 128;
    const int colBase = blockIdx.x * 128;

    const int warp_m = wid & 3;
    const int warp_n = wid >> 2;

    float acc[2][4][4];
#pragma unroll
    for (int i = 0; i < 2; i++)
#pragma unroll
        for (int j = 0; j < 4; j++)
#pragma unroll
            for (int r = 0; r < 4; r++) acc[i][j][r] = 0.f;

    const int a_r  = warp_m * 32 + (lane & 15);
    const int a_cb = (lane >> 4) << 4;
    const int g    = lane >> 3;
    const int b_r  = warp_n * 32 + ((g >> 1) << 3) + (lane & 7);
    const int b_cb = (g & 1) << 4;

    int ld_r[2], ld_cb[2];
    uint32_t ld_sw[2];
#pragma unroll
    for (int it = 0; it < 2; it++) {
        int idx = it * 512 + tid;
        ld_r[it]  = idx >> 3;
        ld_cb[it] = (idx & 7) << 4;
        ld_sw[it] = swz((uint32_t)(ld_r[it] * 128 + ld_cb[it]));
    }

    auto issue = [&](int ch, int st) {
        const int k0 = ch * 64;
        const uint32_t sbase = sb + st * SM_STAGE;
#pragma unroll
        for (int it = 0; it < 2; it++) {
            const int r = ld_r[it], cb = ld_cb[it];
            const uint32_t sw = ld_sw[it];
            cp16(sbase + SM_A  + sw, (const char*)(A   + (size_t)(rowBase + r) * K + k0) + cb);
            cp16(sbase + SM_BH + sw, (const char*)(Bhi + (size_t)(colBase + r) * K + k0) + cb);
            cp16(sbase + SM_BL + sw, (const char*)(Blo + (size_t)(colBase + r) * K + k0) + cb);
        }
        cp_commit();
    };

    const int nChunks = K / 64;
    issue(0, 0);
    issue(1, 1);

    for (int ch = 0; ch < nChunks; ch++) {
        if (ch + 1 < nChunks) cp_wait<1>(); else cp_wait<0>();
        __syncthreads();
        if (ch + 2 < nChunks) issue(ch + 2, (ch + 2) % 3);

        const uint32_t sbase = sb + (ch % 3) * SM_STAGE;
#pragma unroll
        for (int ks = 0; ks < 4; ks++) {
            const int kb = ks * 32;
            uint32_t af[2][4];
#pragma unroll
            for (int mi = 0; mi < 2; mi++) {
                uint32_t off = swz((uint32_t)((a_r + mi * 16) * 128 + kb + a_cb));
                ldsm_x4(af[mi], sbase + SM_A + off);
            }
            uint32_t bh[2][4], bl[2][4];
#pragma unroll
            for (int nt = 0; nt < 2; nt++) {
                uint32_t off = swz((uint32_t)((b_r + nt * 16) * 128 + kb + b_cb));
                ldsm_x4(bh[nt], sbase + SM_BH + off);
                ldsm_x4(bl[nt], sbase + SM_BL + off);
            }
#pragma unroll
            for (int mi = 0; mi < 2; mi++)
#pragma unroll
                for (int nj = 0; nj < 4; nj++) {
                    const uint32_t* bhj = &bh[nj >> 1][(nj & 1) * 2];
                    const uint32_t* blj = &bl[nj >> 1][(nj & 1) * 2];
                    mma16816h(acc[mi][nj], af[mi], bhj[0], bhj[1]);
                    mma16816h(acc[mi][nj], af[mi], blj[0], blj[1]);
                }
        }
    }

    const int er = rowBase + warp_m * 32 + (lane >> 2);
    const int ec = colBase + warp_n * 32 + (lane & 3) * 2;

    if (MODE == 0) {
#pragma unroll
        for (int mi = 0; mi < 2; mi++) {
#pragma unroll
            for (int nj = 0; nj < 4; nj++) {
                const int c = ec + nj * 8;
                const float bx = __ldg(bias + c);
                const float by = __ldg(bias + c + 1);
                float2 v0 = { acc[mi][nj][0] + bx, acc[mi][nj][1] + by };
                float2 v1 = { acc[mi][nj][2] + bx, acc[mi][nj][3] + by };
                *(float2*)(Cout + (size_t)(er + mi * 16) * N + c) = v0;
                *(float2*)(Cout + (size_t)(er + mi * 16 + 8) * N + c) = v1;
            }
        }
    } else {
        // MODE 1: scatter per-head fp16; q scaled by QS.
#pragma unroll
        for (int nj = 0; nj < 4; nj++) {
            const int c   = ec + nj * 8;
            const int sec = c >> 10;             // 0=q,1=k,2=v
            const int hh  = (c & 1023) >> 6;
            const int dd  = c & 63;
            const float sc = (sec == 0) ? QS : 1.f;
            const float bx = __ldg(bias + c)     * sc;
            const float by = __ldg(bias + c + 1) * sc;
            __half* dp = (sec == 0) ? qh : (sec == 1) ? kh : vh;
#pragma unroll
            for (int mi = 0; mi < 2; mi++) {
#pragma unroll
                for (int half = 0; half < 2; half++) {
                    const int r = er + mi * 16 + half * 8;
                    const int bb = r >> 11, tt = r & 2047;
                    const size_t dst = (((size_t)bb * H_ + hh) * T_ + tt) * D_ + dd;
                    float v0 = fmaf(acc[mi][nj][half * 2],     sc, bx);
                    float v1 = fmaf(acc[mi][nj][half * 2 + 1], sc, by);
                    *(__half2*)(dp + dst) = __floats2half2_rn(v0, v1);
                }
            }
        }
    }
}

// ---------------------------------------------------------------------------
// Flash attention, all fp16 single-term (S = QK^T fp16, O = PV fp16),
// m=0 softmax (2^s / sum 2^s), 256 threads / 8 warps x 16 q-rows.
// cp.async 3-stage K/V pipeline. Output fp16 att [B*T, C].
// ---------------------------------------------------------------------------
#define FA_Q 0
#define FA_STAGE0 16384
#define FA_STSZ 16384
#define FA_ST(s) (FA_STAGE0 + (s) * FA_STSZ)
#define FA_K 0
#define FA_V 8192
#define FA_TOTAL (FA_STAGE0 + 3 * FA_STSZ)   // 65536

__global__ __launch_bounds__(256)
void flash_attn(const __half* __restrict__ qh, const __half* __restrict__ kh,
                const __half* __restrict__ vh, __half* __restrict__ att)
{
    extern __shared__ char smem[];
    const uint32_t sb = smem_to_u32(smem);
    const int tid = threadIdx.x, wid = tid >> 5, lane = tid & 31;
    const int h = blockIdx.y, b = blockIdx.z;
    const int qt = gridDim.x - 1 - blockIdx.x;    // big tiles first

    const size_t hoff = ((size_t)b * H_ + h) * T_ * D_;
    const char* qh_p = (const char*)(qh + hoff + (size_t)qt * 128 * D_);
    const char* kh_p = (const char*)(kh + hoff);
    const char* vh_p = (const char*)(vh + hoff);

    auto issue_kv = [&](int kt, int st) {
        const uint32_t sbase = sb + FA_ST(st);
#pragma unroll
        for (int it = 0; it < 2; it++) {
            int idx = it * 256 + tid;            // 0..511
            int r = idx >> 3, cb = (idx & 7) << 4;
            uint32_t sw = swz((uint32_t)(r * 128 + cb));
            size_t go = (size_t)(kt * 64 + r) * 128 + cb;    // bytes
            cp16(sbase + FA_K + sw, kh_p + go);
            cp16(sbase + FA_V + sw, vh_p + go);
        }
        cp_commit();
    };

    const int nkt = 2 * qt + 2;
    issue_kv(0, 0);
    issue_kv(1, 1);

    // Load Q tile (plain stores; covered by first in-loop barrier)
#pragma unroll
    for (int it = 0; it < 4; it++) {
        int idx = it * 256 + tid;
        int r = idx >> 3, cb = (idx & 7) << 4;
        uint32_t sw = swz((uint32_t)(r * 128 + cb));
        *(uint4*)(smem + FA_Q + sw) = *(const uint4*)(qh_p + r * 128 + cb);
    }

    float o[8][4];
#pragma unroll
    for (int nj = 0; nj < 8; nj++)
#pragma unroll
        for (int r = 0; r < 4; r++) o[nj][r] = 0.f;
    float ls[2] = { 0.f, 0.f };

    const int a_r  = wid * 16 + (lane & 15);
    const int a_cb = (lane >> 4) << 4;
    const int g    = lane >> 3;
    const int b_r  = ((g >> 1) << 3) + (lane & 7);
    const int b_cb = (g & 1) << 4;
    const int vrow = ((lane >> 3) & 1) * 8 + (lane & 7);
    const int vcb  = ((lane >> 4) & 1) * 16;

    for (int kt = 0; kt < nkt; kt++) {
        if (kt + 1 < nkt) cp_wait<1>(); else cp_wait<0>();
        __syncthreads();
        if (kt + 2 < nkt) issue_kv(kt + 2, (kt + 2) % 3);

        const uint32_t kv = sb + FA_ST(kt % 3);

        // ---- S = Q K^T (fp16 single) ----
        float s[8][4];
#pragma unroll
        for (int nj = 0; nj < 8; nj++)
#pragma unroll
            for (int r = 0; r < 4; r++) s[nj][r] = 0.f;

#pragma unroll
        for (int ks = 0; ks < 4; ks++) {
            uint32_t qf[4];
            {
                uint32_t off = swz((uint32_t)(a_r * 128 + ks * 32 + a_cb));
                ldsm_x4(qf, sb + FA_Q + off);
            }
            uint32_t kb[4][4];
#pragma unroll
            for (int nt = 0; nt < 4; nt++) {
                uint32_t off = swz((uint32_t)((b_r + nt * 16) * 128 + ks * 32 + b_cb));
                ldsm_x4(kb[nt], kv + FA_K + off);
            }
#pragma unroll
            for (int nj = 0; nj < 8; nj++) {
                const uint32_t* bj = &kb[nj >> 1][(nj & 1) * 2];
                mma16816h(s[nj], qf, bj[0], bj[1]);
            }
        }

        // ---- causal mask (last two key tiles only) ----
        if (kt >= 2 * qt) {
            const int r0 = qt * 128 + wid * 16 + (lane >> 2);
            const int r1 = r0 + 8;
            const int colb = kt * 64 + (lane & 3) * 2;
#pragma unroll
            for (int nj = 0; nj < 8; nj++) {
                const int c0 = colb + nj * 8, c1 = c0 + 1;
                if (c0 > r0) s[nj][0] = -1e30f;
                if (c1 > r0) s[nj][1] = -1e30f;
                if (c0 > r1) s[nj][2] = -1e30f;
                if (c1 > r1) s[nj][3] = -1e30f;
            }
        }

        // ---- p = 2^s (no max), accumulate l, pack P fp16 ----
        uint32_t ph[4][4];
#pragma unroll
        for (int nj = 0; nj < 8; nj++) {
            float p0 = ex2(s[nj][0]);
            float p1 = ex2(s[nj][1]);
            float p2 = ex2(s[nj][2]);
            float p3 = ex2(s[nj][3]);
            s[nj][0] = p0; s[nj][1] = p1;
            s[nj][2] = p2; s[nj][3] = p3;
            ls[0] += p0 + p1;
            ls[1] += p2 + p3;
        }
#pragma unroll
        for (int ks = 0; ks < 4; ks++) {
#pragma unroll
            for (int rr = 0; rr < 4; rr++) {
                const int nj = 2 * ks + (rr >> 1);
                const int r0 = (rr & 1) * 2;
                __half2 hh = __floats2half2_rn(s[nj][r0], s[nj][r0 + 1]);
                ph[ks][rr] = *(uint32_t*)&hh;
            }
        }

        // ---- O += P V (fp16), V via ldmatrix.trans ----
#pragma unroll
        for (int ks = 0; ks < 4; ks++) {
#pragma unroll
            for (int nd = 0; nd < 4; nd++) {
                uint32_t vf[4];
                uint32_t off = swz((uint32_t)((ks * 16 + vrow) * 128 + nd * 32 + vcb));
                ldsm_x4_t(vf, kv + FA_V + off);
                mma16816h(o[nd * 2],     ph[ks], vf[0], vf[1]);
                mma16816h(o[nd * 2 + 1], ph[ks], vf[2], vf[3]);
            }
        }
    }

    // ---- epilogue: reduce l across quad lanes, O / l -> fp16 att ----
    float inv[2];
#pragma unroll
    for (int si = 0; si < 2; si++) {
        float l = ls[si];
        l += __shfl_xor_sync(0xffffffffu, l, 1);
        l += __shfl_xor_sync(0xffffffffu, l, 2);
        inv[si] = 1.f / l;
    }
    const int er0 = qt * 128 + wid * 16 + (lane >> 2);
    const int ecb = h * 64 + (lane & 3) * 2;
    const size_t row = (size_t)b * T_ + er0;
#pragma unroll
    for (int nj = 0; nj < 8; nj++) {
        *(__half2*)(att + row * C_ + ecb + nj * 8) =
            __floats2half2_rn(o[nj][0] * inv[0], o[nj][1] * inv[0]);
        *(__half2*)(att + (row + 8) * C_ + ecb + nj * 8) =
            __floats2half2_rn(o[nj][2] * inv[1], o[nj][3] * inv[1]);
    }
}

// ---------------------------------------------------------------------------
// Launch sequence
// ---------------------------------------------------------------------------
extern "C" void kernel_launch(void* const* d_in, const int* in_sizes, int n_in,
                              void* d_out, int out_size)
{
    const float* x      = (const float*)d_in[0];
    const float* w_qkv  = (const float*)d_in[1];
    const float* b_qkv  = (const float*)d_in[2];
    const float* w_proj = (const float*)d_in[3];
    const float* b_proj = (const float*)d_in[4];
    float* out = (float*)d_out;

    __half *xh, *wh, *wl, *qh, *kh, *vh;
    cudaGetSymbolAddress((void**)&xh, g_xh);
    cudaGetSymbolAddress((void**)&wh, g_wh);
    cudaGetSymbolAddress((void**)&wl, g_wl);
    cudaGetSymbolAddress((void**)&qh, g_qh);
    cudaGetSymbolAddress((void**)&kh, g_kh);
    cudaGetSymbolAddress((void**)&vh, g_vh);

    cudaFuncSetAttribute(gemm_f16w2<0>, cudaFuncAttributeMaxDynamicSharedMemorySize, SM_TOTAL);
    cudaFuncSetAttribute(gemm_f16w2<1>, cudaFuncAttributeMaxDynamicSharedMemorySize, SM_TOTAL);
    cudaFuncSetAttribute(flash_attn, cudaFuncAttributeMaxDynamicSharedMemorySize, FA_TOTAL);

    // 1) x -> fp16
    {
        int n4 = (M_ROWS * C_) / 4;
        cvt_f16<<<(n4 + 255) / 256, 256>>>(x, xh, n4);
    }
    // 2) transpose+split w_qkv (fp16 hi/lo)
    {
        dim3 grid(N_QKV / 32, C_ / 32);
        wsplit_transpose<<<grid, 256>>>(w_qkv, wh, wl, C_, N_QKV);
    }
    // 3) QKV GEMM -> per-head q (scaled)/k/v fp16
    {
        dim3 grid(N_QKV / 128, M_ROWS / 128);
        gemm_f16w2<1><<<grid, 512, SM_TOTAL>>>(xh, wh, wl, b_qkv, nullptr,
                                               qh, kh, vh, M_ROWS, N_QKV, C_);
    }
    // 4) flash attention -> fp16 att (reuses xh)
    {
        dim3 grid(T_ / 128, H_, B_);
        flash_attn<<<grid, 256, FA_TOTAL>>>(qh, kh, vh, xh);
    }
    // 5) transpose+split w_proj
    {
        dim3 grid(C_ / 32, C_ / 32);
        wsplit_transpose<<<grid, 256>>>(w_proj, wh, wl, C_, C_);
    }
    // 6) proj GEMM -> fp32 out
    {
        dim3 grid(C_ / 128, M_ROWS / 128);
        gemm_f16w2<0><<<grid, 512, SM_TOTAL>>>(xh, wh, wl, b_proj, out,
                                               nullptr, nullptr, nullptr,
                                               M_ROWS, C_, C_);
    }
}

// round 9
// speedup vs baseline: 7.6314x; 1.3036x over previous
#include <cuda_runtime.h>
#include <cuda_bf16.h>
#include <cuda_fp16.h>
#include <cstdint>

// ---------------------------------------------------------------------------
// Problem constants
// ---------------------------------------------------------------------------
#define B_ 2
#define T_ 2048
#define C_ 1024
#define H_ 16
#define D_ 64
#define M_ROWS (B_ * T_)     // 4096
#define N_QKV  (3 * C_)      // 3072

// softmax scale * log2(e) folded into Q: (1/8) * 1.4426950408889634
#define QS 0.18033688011112042f

// Scratch (__device__ globals; allocation-free rule)
__device__ __half g_xh[(size_t)M_ROWS * C_];        // activations fp16 (x, then att)
__device__ __half g_wt[(size_t)N_QKV * C_];         // W^T fp16 [N,K]
// per-head fp16 [B,H,T,D]
__device__ __half g_qh[(size_t)B_ * H_ * T_ * D_];  // q (pre-scaled by QS)
__device__ __half g_kh[(size_t)B_ * H_ * T_ * D_];
__device__ __half g_vh[(size_t)B_ * H_ * T_ * D_];

// ---------------------------------------------------------------------------
// Warp MMA / async-copy helpers (sm_80+ baseline)
// ---------------------------------------------------------------------------
__device__ __forceinline__ uint32_t smem_to_u32(const void* p) {
    uint32_t a;
    asm("{ .reg .u64 t; cvta.to.shared.u64 t, %1; cvt.u32.u64 %0, t; }"
        : "=r"(a) : "l"(p));
    return a;
}
__device__ __forceinline__ void ldsm_x4(uint32_t (&r)[4], uint32_t addr) {
    asm volatile("ldmatrix.sync.aligned.m8n8.x4.shared.b16 {%0,%1,%2,%3}, [%4];"
                 : "=r"(r[0]), "=r"(r[1]), "=r"(r[2]), "=r"(r[3]) : "r"(addr));
}
__device__ __forceinline__ void ldsm_x4_t(uint32_t (&r)[4], uint32_t addr) {
    asm volatile("ldmatrix.sync.aligned.m8n8.x4.trans.shared.b16 {%0,%1,%2,%3}, [%4];"
                 : "=r"(r[0]), "=r"(r[1]), "=r"(r[2]), "=r"(r[3]) : "r"(addr));
}
__device__ __forceinline__ void mma16816h(float (&d)[4],
                                          const uint32_t (&a)[4],
                                          const uint32_t b0, const uint32_t b1) {
    asm volatile(
        "mma.sync.aligned.m16n8k16.row.col.f32.f16.f16.f32 "
        "{%0,%1,%2,%3}, {%4,%5,%6,%7}, {%8,%9}, {%0,%1,%2,%3};"
        : "+f"(d[0]), "+f"(d[1]), "+f"(d[2]), "+f"(d[3])
        : "r"(a[0]), "r"(a[1]), "r"(a[2]), "r"(a[3]), "r"(b0), "r"(b1));
}
__device__ __forceinline__ uint32_t swz(uint32_t off) {
    return off ^ ((off >> 3) & 0x70);
}
__device__ __forceinline__ float ex2(float x) {
    float y; asm("ex2.approx.ftz.f32 %0, %1;" : "=f"(y) : "f"(x)); return y;
}
__device__ __forceinline__ void cp16(uint32_t dst, const void* src) {
    asm volatile("cp.async.ca.shared.global [%0], [%1], 16;" :: "r"(dst), "l"(src));
}
__device__ __forceinline__ void cp_commit() {
    asm volatile("cp.async.commit_group;" ::: "memory");
}
template<int N> __device__ __forceinline__ void cp_wait() {
    asm volatile("cp.async.wait_group %0;" :: "n"(N) : "memory");
}

// ---------------------------------------------------------------------------
// Prepass 1: fp32 -> fp16
// ---------------------------------------------------------------------------
__global__ __launch_bounds__(256)
void cvt_f16(const float* __restrict__ src, __half* __restrict__ dst, int n4)
{
    int i = blockIdx.x * 256 + threadIdx.x;
    if (i >= n4) return;
    float4 v = ((const float4*)src)[i];
    ((__half2*)dst)[i * 2 + 0] = __floats2half2_rn(v.x, v.y);
    ((__half2*)dst)[i * 2 + 1] = __floats2half2_rn(v.z, v.w);
}

// ---------------------------------------------------------------------------
// Prepass 2: W [K,N] fp32 -> W^T [N,K] fp16
// ---------------------------------------------------------------------------
__global__ __launch_bounds__(256)
void wt_cvt(const float* __restrict__ W, __half* __restrict__ Wt, int K, int N)
{
    __shared__ float tile[32][33];
    const int tx = threadIdx.x & 31;
    const int ty = threadIdx.x >> 5;
    const int k0 = blockIdx.y * 32;
    const int n0 = blockIdx.x * 32;
#pragma unroll
    for (int r = ty; r < 32; r += 8)
        tile[r][tx] = W[(size_t)(k0 + r) * N + n0 + tx];
    __syncthreads();
#pragma unroll
    for (int r = ty; r < 32; r += 8)
        Wt[(size_t)(n0 + r) * K + k0 + tx] = __float2half_rn(tile[tx][r]);
}

// ---------------------------------------------------------------------------
// HMMA GEMM fp16 single-term. cp.async 3-stage pipeline, 512 threads,
// warp tile 32x32. MODE 0: fp32 C + bias.  MODE 1: per-head q(scaled)/k/v.
// ---------------------------------------------------------------------------
#define SM_A  0
#define SM_B  16384
#define SM_STAGE 32768
#define SM_TOTAL (3 * SM_STAGE)     // 98304

template<int MODE>
__global__ __launch_bounds__(512)
void gemm_f16(const __half* __restrict__ A, const __half* __restrict__ Bt,
              const float* __restrict__ bias, float* __restrict__ Cout,
              __half* __restrict__ qh, __half* __restrict__ kh,
              __half* __restrict__ vh,
              int M, int N, int K)
{
    extern __shared__ char smem[];
    const uint32_t sb = smem_to_u32(smem);

    const int tid  = threadIdx.x;
    const int wid  = tid >> 5;
    const int lane = tid & 31;
    const int rowBase = blockIdx.y * 128;
    const int colBase = blockIdx.x * 128;

    const int warp_m = wid & 3;
    const int warp_n = wid >> 2;

    float acc[2][4][4];
#pragma unroll
    for (int i = 0; i < 2; i++)
#pragma unroll
        for (int j = 0; j < 4; j++)
#pragma unroll
            for (int r = 0; r < 4; r++) acc[i][j][r] = 0.f;

    const int a_r  = warp_m * 32 + (lane & 15);
    const int a_cb = (lane >> 4) << 4;
    const int g    = lane >> 3;
    const int b_r  = warp_n * 32 + ((g >> 1) << 3) + (lane & 7);
    const int b_cb = (g & 1) << 4;

    int ld_r[2], ld_cb[2];
    uint32_t ld_sw[2];
#pragma unroll
    for (int it = 0; it < 2; it++) {
        int idx = it * 512 + tid;
        ld_r[it]  = idx >> 3;
        ld_cb[it] = (idx & 7) << 4;
        ld_sw[it] = swz((uint32_t)(ld_r[it] * 128 + ld_cb[it]));
    }

    auto issue = [&](int ch, int st) {
        const int k0 = ch * 64;
        const uint32_t sbase = sb + st * SM_STAGE;
#pragma unroll
        for (int it = 0; it < 2; it++) {
            const int r = ld_r[it], cb = ld_cb[it];
            const uint32_t sw = ld_sw[it];
            cp16(sbase + SM_A + sw, (const char*)(A  + (size_t)(rowBase + r) * K + k0) + cb);
            cp16(sbase + SM_B + sw, (const char*)(Bt + (size_t)(colBase + r) * K + k0) + cb);
        }
        cp_commit();
    };

    const int nChunks = K / 64;
    issue(0, 0);
    issue(1, 1);

    for (int ch = 0; ch < nChunks; ch++) {
        if (ch + 1 < nChunks) cp_wait<1>(); else cp_wait<0>();
        __syncthreads();
        if (ch + 2 < nChunks) issue(ch + 2, (ch + 2) % 3);

        const uint32_t sbase = sb + (ch % 3) * SM_STAGE;
#pragma unroll
        for (int ks = 0; ks < 4; ks++) {
            const int kb = ks * 32;
            uint32_t af[2][4];
#pragma unroll
            for (int mi = 0; mi < 2; mi++) {
                uint32_t off = swz((uint32_t)((a_r + mi * 16) * 128 + kb + a_cb));
                ldsm_x4(af[mi], sbase + SM_A + off);
            }
            uint32_t bf[2][4];
#pragma unroll
            for (int nt = 0; nt < 2; nt++) {
                uint32_t off = swz((uint32_t)((b_r + nt * 16) * 128 + kb + b_cb));
                ldsm_x4(bf[nt], sbase + SM_B + off);
            }
#pragma unroll
            for (int mi = 0; mi < 2; mi++)
#pragma unroll
                for (int nj = 0; nj < 4; nj++) {
                    const uint32_t* bj = &bf[nj >> 1][(nj & 1) * 2];
                    mma16816h(acc[mi][nj], af[mi], bj[0], bj[1]);
                }
        }
    }

    const int er = rowBase + warp_m * 32 + (lane >> 2);
    const int ec = colBase + warp_n * 32 + (lane & 3) * 2;

    if (MODE == 0) {
#pragma unroll
        for (int mi = 0; mi < 2; mi++) {
#pragma unroll
            for (int nj = 0; nj < 4; nj++) {
                const int c = ec + nj * 8;
                const float bx = __ldg(bias + c);
                const float by = __ldg(bias + c + 1);
                float2 v0 = { acc[mi][nj][0] + bx, acc[mi][nj][1] + by };
                float2 v1 = { acc[mi][nj][2] + bx, acc[mi][nj][3] + by };
                *(float2*)(Cout + (size_t)(er + mi * 16) * N + c) = v0;
                *(float2*)(Cout + (size_t)(er + mi * 16 + 8) * N + c) = v1;
            }
        }
    } else {
        // MODE 1: scatter per-head fp16; q scaled by QS.
#pragma unroll
        for (int nj = 0; nj < 4; nj++) {
            const int c   = ec + nj * 8;
            const int sec = c >> 10;             // 0=q,1=k,2=v
            const int hh  = (c & 1023) >> 6;
            const int dd  = c & 63;
            const float sc = (sec == 0) ? QS : 1.f;
            const float bx = __ldg(bias + c)     * sc;
            const float by = __ldg(bias + c + 1) * sc;
            __half* dp = (sec == 0) ? qh : (sec == 1) ? kh : vh;
#pragma unroll
            for (int mi = 0; mi < 2; mi++) {
#pragma unroll
                for (int half = 0; half < 2; half++) {
                    const int r = er + mi * 16 + half * 8;
                    const int bb = r >> 11, tt = r & 2047;
                    const size_t dst = (((size_t)bb * H_ + hh) * T_ + tt) * D_ + dd;
                    float v0 = fmaf(acc[mi][nj][half * 2],     sc, bx);
                    float v1 = fmaf(acc[mi][nj][half * 2 + 1], sc, by);
                    *(__half2*)(dp + dst) = __floats2half2_rn(v0, v1);
                }
            }
        }
    }
}

// ---------------------------------------------------------------------------
// Flash attention, all fp16 single-term (S = QK^T fp16, O = PV fp16),
// m=0 softmax (2^s / sum 2^s), 256 threads / 8 warps x 16 q-rows.
// cp.async 3-stage K/V pipeline. Output fp16 att [B*T, C].
// ---------------------------------------------------------------------------
#define FA_Q 0
#define FA_STAGE0 16384
#define FA_STSZ 16384
#define FA_ST(s) (FA_STAGE0 + (s) * FA_STSZ)
#define FA_K 0
#define FA_V 8192
#define FA_TOTAL (FA_STAGE0 + 3 * FA_STSZ)   // 65536

__global__ __launch_bounds__(256)
void flash_attn(const __half* __restrict__ qh, const __half* __restrict__ kh,
                const __half* __restrict__ vh, __half* __restrict__ att)
{
    extern __shared__ char smem[];
    const uint32_t sb = smem_to_u32(smem);
    const int tid = threadIdx.x, wid = tid >> 5, lane = tid & 31;
    const int h = blockIdx.y, b = blockIdx.z;
    const int qt = gridDim.x - 1 - blockIdx.x;    // big tiles first

    const size_t hoff = ((size_t)b * H_ + h) * T_ * D_;
    const char* qh_p = (const char*)(qh + hoff + (size_t)qt * 128 * D_);
    const char* kh_p = (const char*)(kh + hoff);
    const char* vh_p = (const char*)(vh + hoff);

    auto issue_kv = [&](int kt, int st) {
        const uint32_t sbase = sb + FA_ST(st);
#pragma unroll
        for (int it = 0; it < 2; it++) {
            int idx = it * 256 + tid;            // 0..511
            int r = idx >> 3, cb = (idx & 7) << 4;
            uint32_t sw = swz((uint32_t)(r * 128 + cb));
            size_t go = (size_t)(kt * 64 + r) * 128 + cb;    // bytes
            cp16(sbase + FA_K + sw, kh_p + go);
            cp16(sbase + FA_V + sw, vh_p + go);
        }
        cp_commit();
    };

    const int nkt = 2 * qt + 2;
    issue_kv(0, 0);
    issue_kv(1, 1);

    // Load Q tile (plain stores; covered by first in-loop barrier)
#pragma unroll
    for (int it = 0; it < 4; it++) {
        int idx = it * 256 + tid;
        int r = idx >> 3, cb = (idx & 7) << 4;
        uint32_t sw = swz((uint32_t)(r * 128 + cb));
        *(uint4*)(smem + FA_Q + sw) = *(const uint4*)(qh_p + r * 128 + cb);
    }

    float o[8][4];
#pragma unroll
    for (int nj = 0; nj < 8; nj++)
#pragma unroll
        for (int r = 0; r < 4; r++) o[nj][r] = 0.f;
    float ls[2] = { 0.f, 0.f };

    const int a_r  = wid * 16 + (lane & 15);
    const int a_cb = (lane >> 4) << 4;
    const int g    = lane >> 3;
    const int b_r  = ((g >> 1) << 3) + (lane & 7);
    const int b_cb = (g & 1) << 4;
    const int vrow = ((lane >> 3) & 1) * 8 + (lane & 7);
    const int vcb  = ((lane >> 4) & 1) * 16;

    for (int kt = 0; kt < nkt; kt++) {
        if (kt + 1 < nkt) cp_wait<1>(); else cp_wait<0>();
        __syncthreads();
        if (kt + 2 < nkt) issue_kv(kt + 2, (kt + 2) % 3);

        const uint32_t kv = sb + FA_ST(kt % 3);

        // ---- S = Q K^T (fp16 single) ----
        float s[8][4];
#pragma unroll
        for (int nj = 0; nj < 8; nj++)
#pragma unroll
            for (int r = 0; r < 4; r++) s[nj][r] = 0.f;

#pragma unroll
        for (int ks = 0; ks < 4; ks++) {
            uint32_t qf[4];
            {
                uint32_t off = swz((uint32_t)(a_r * 128 + ks * 32 + a_cb));
                ldsm_x4(qf, sb + FA_Q + off);
            }
            uint32_t kb[4][4];
#pragma unroll
            for (int nt = 0; nt < 4; nt++) {
                uint32_t off = swz((uint32_t)((b_r + nt * 16) * 128 + ks * 32 + b_cb));
                ldsm_x4(kb[nt], kv + FA_K + off);
            }
#pragma unroll
            for (int nj = 0; nj < 8; nj++) {
                const uint32_t* bj = &kb[nj >> 1][(nj & 1) * 2];
                mma16816h(s[nj], qf, bj[0], bj[1]);
            }
        }

        // ---- causal mask (last two key tiles only) ----
        if (kt >= 2 * qt) {
            const int r0 = qt * 128 + wid * 16 + (lane >> 2);
            const int r1 = r0 + 8;
            const int colb = kt * 64 + (lane & 3) * 2;
#pragma unroll
            for (int nj = 0; nj < 8; nj++) {
                const int c0 = colb + nj * 8, c1 = c0 + 1;
                if (c0 > r0) s[nj][0] = -1e30f;
                if (c1 > r0) s[nj][1] = -1e30f;
                if (c0 > r1) s[nj][2] = -1e30f;
                if (c1 > r1) s[nj][3] = -1e30f;
            }
        }

        // ---- p = 2^s (no max), accumulate l, pack P fp16 ----
        uint32_t ph[4][4];
#pragma unroll
        for (int nj = 0; nj < 8; nj++) {
            float p0 = ex2(s[nj][0]);
            float p1 = ex2(s[nj][1]);
            float p2 = ex2(s[nj][2]);
            float p3 = ex2(s[nj][3]);
            s[nj][0] = p0; s[nj][1] = p1;
            s[nj][2] = p2; s[nj][3] = p3;
            ls[0] += p0 + p1;
            ls[1] += p2 + p3;
        }
#pragma unroll
        for (int ks = 0; ks < 4; ks++) {
#pragma unroll
            for (int rr = 0; rr < 4; rr++) {
                const int nj = 2 * ks + (rr >> 1);
                const int r0 = (rr & 1) * 2;
                __half2 hh = __floats2half2_rn(s[nj][r0], s[nj][r0 + 1]);
                ph[ks][rr] = *(uint32_t*)&hh;
            }
        }

        // ---- O += P V (fp16), V via ldmatrix.trans ----
#pragma unroll
        for (int ks = 0; ks < 4; ks++) {
#pragma unroll
            for (int nd = 0; nd < 4; nd++) {
                uint32_t vf[4];
                uint32_t off = swz((uint32_t)((ks * 16 + vrow) * 128 + nd * 32 + vcb));
                ldsm_x4_t(vf, kv + FA_V + off);
                mma16816h(o[nd * 2],     ph[ks], vf[0], vf[1]);
                mma16816h(o[nd * 2 + 1], ph[ks], vf[2], vf[3]);
            }
        }
    }

    // ---- epilogue: reduce l across quad lanes, O / l -> fp16 att ----
    float inv[2];
#pragma unroll
    for (int si = 0; si < 2; si++) {
        float l = ls[si];
        l += __shfl_xor_sync(0xffffffffu, l, 1);
        l += __shfl_xor_sync(0xffffffffu, l, 2);
        inv[si] = 1.f / l;
    }
    const int er0 = qt * 128 + wid * 16 + (lane >> 2);
    const int ecb = h * 64 + (lane & 3) * 2;
    const size_t row = (size_t)b * T_ + er0;
#pragma unroll
    for (int nj = 0; nj < 8; nj++) {
        *(__half2*)(att + row * C_ + ecb + nj * 8) =
            __floats2half2_rn(o[nj][0] * inv[0], o[nj][1] * inv[0]);
        *(__half2*)(att + (row + 8) * C_ + ecb + nj * 8) =
            __floats2half2_rn(o[nj][2] * inv[1], o[nj][3] * inv[1]);
    }
}

// ---------------------------------------------------------------------------
// Launch sequence
// ---------------------------------------------------------------------------
extern "C" void kernel_launch(void* const* d_in, const int* in_sizes, int n_in,
                              void* d_out, int out_size)
{
    const float* x      = (const float*)d_in[0];
    const float* w_qkv  = (const float*)d_in[1];
    const float* b_qkv  = (const float*)d_in[2];
    const float* w_proj = (const float*)d_in[3];
    const float* b_proj = (const float*)d_in[4];
    float* out = (float*)d_out;

    __half *xh, *wt, *qh, *kh, *vh;
    cudaGetSymbolAddress((void**)&xh, g_xh);
    cudaGetSymbolAddress((void**)&wt, g_wt);
    cudaGetSymbolAddress((void**)&qh, g_qh);
    cudaGetSymbolAddress((void**)&kh, g_kh);
    cudaGetSymbolAddress((void**)&vh, g_vh);

    cudaFuncSetAttribute(gemm_f16<0>, cudaFuncAttributeMaxDynamicSharedMemorySize, SM_TOTAL);
    cudaFuncSetAttribute(gemm_f16<1>, cudaFuncAttributeMaxDynamicSharedMemorySize, SM_TOTAL);
    cudaFuncSetAttribute(flash_attn, cudaFuncAttributeMaxDynamicSharedMemorySize, FA_TOTAL);

    // 1) x -> fp16
    {
        int n4 = (M_ROWS * C_) / 4;
        cvt_f16<<<(n4 + 255) / 256, 256>>>(x, xh, n4);
    }
    // 2) transpose+cvt w_qkv -> [N,K] fp16
    {
        dim3 grid(N_QKV / 32, C_ / 32);
        wt_cvt<<<grid, 256>>>(w_qkv, wt, C_, N_QKV);
    }
    // 3) QKV GEMM -> per-head q (scaled)/k/v fp16
    {
        dim3 grid(N_QKV / 128, M_ROWS / 128);
        gemm_f16<1><<<grid, 512, SM_TOTAL>>>(xh, wt, b_qkv, nullptr,
                                             qh, kh, vh, M_ROWS, N_QKV, C_);
    }
    // 4) flash attention -> fp16 att (reuses xh)
    {
        dim3 grid(T_ / 128, H_, B_);
        flash_attn<<<grid, 256, FA_TOTAL>>>(qh, kh, vh, xh);
    }
    // 5) transpose+cvt w_proj
    {
        dim3 grid(C_ / 32, C_ / 32);
        wt_cvt<<<grid, 256>>>(w_proj, wt, C_, C_);
    }
    // 6) proj GEMM -> fp32 out
    {
        dim3 grid(C_ / 128, M_ROWS / 128);
        gemm_f16<0><<<grid, 512, SM_TOTAL>>>(xh, wt, b_proj, out,
                                             nullptr, nullptr, nullptr,
                                             M_ROWS, C_, C_);
    }
}

// round 10
// speedup vs baseline: 7.9827x; 1.0460x over previous
#include <cuda_runtime.h>
#include <cuda_bf16.h>
#include <cuda_fp16.h>
#include <cstdint>

// ---------------------------------------------------------------------------
// Problem constants
// ---------------------------------------------------------------------------
#define B_ 2
#define T_ 2048
#define C_ 1024
#define H_ 16
#define D_ 64
#define M_ROWS (B_ * T_)     // 4096
#define N_QKV  (3 * C_)      // 3072

// softmax scale * log2(e) folded into Q: (1/8) * 1.4426950408889634
#define QS 0.18033688011112042f

// Scratch (__device__ globals; allocation-free rule)
__device__ __half g_xh[(size_t)M_ROWS * C_];        // activations fp16 (x, then att)
__device__ __half g_wt[(size_t)N_QKV * C_];         // W^T fp16 [N,K]
// per-head fp16 [B,H,T,D]
__device__ __half g_qh[(size_t)B_ * H_ * T_ * D_];  // q (pre-scaled by QS)
__device__ __half g_kh[(size_t)B_ * H_ * T_ * D_];
__device__ __half g_vh[(size_t)B_ * H_ * T_ * D_];

// ---------------------------------------------------------------------------
// Warp MMA / async-copy helpers (sm_80+ baseline)
// ---------------------------------------------------------------------------
__device__ __forceinline__ uint32_t smem_to_u32(const void* p) {
    uint32_t a;
    asm("{ .reg .u64 t; cvta.to.shared.u64 t, %1; cvt.u32.u64 %0, t; }"
        : "=r"(a) : "l"(p));
    return a;
}
__device__ __forceinline__ void ldsm_x4(uint32_t (&r)[4], uint32_t addr) {
    asm volatile("ldmatrix.sync.aligned.m8n8.x4.shared.b16 {%0,%1,%2,%3}, [%4];"
                 : "=r"(r[0]), "=r"(r[1]), "=r"(r[2]), "=r"(r[3]) : "r"(addr));
}
__device__ __forceinline__ void ldsm_x4_t(uint32_t (&r)[4], uint32_t addr) {
    asm volatile("ldmatrix.sync.aligned.m8n8.x4.trans.shared.b16 {%0,%1,%2,%3}, [%4];"
                 : "=r"(r[0]), "=r"(r[1]), "=r"(r[2]), "=r"(r[3]) : "r"(addr));
}
__device__ __forceinline__ void mma16816h(float (&d)[4],
                                          const uint32_t (&a)[4],
                                          const uint32_t b0, const uint32_t b1) {
    asm volatile(
        "mma.sync.aligned.m16n8k16.row.col.f32.f16.f16.f32 "
        "{%0,%1,%2,%3}, {%4,%5,%6,%7}, {%8,%9}, {%0,%1,%2,%3};"
        : "+f"(d[0]), "+f"(d[1]), "+f"(d[2]), "+f"(d[3])
        : "r"(a[0]), "r"(a[1]), "r"(a[2]), "r"(a[3]), "r"(b0), "r"(b1));
}
__device__ __forceinline__ uint32_t swz(uint32_t off) {
    return off ^ ((off >> 3) & 0x70);
}
__device__ __forceinline__ float ex2(float x) {
    float y; asm("ex2.approx.ftz.f32 %0, %1;" : "=f"(y) : "f"(x)); return y;
}
__device__ __forceinline__ void cp16(uint32_t dst, const void* src) {
    asm volatile("cp.async.ca.shared.global [%0], [%1], 16;" :: "r"(dst), "l"(src));
}
__device__ __forceinline__ void cp_commit() {
    asm volatile("cp.async.commit_group;" ::: "memory");
}
template<int N> __device__ __forceinline__ void cp_wait() {
    asm volatile("cp.async.wait_group %0;" :: "n"(N) : "memory");
}

// ---------------------------------------------------------------------------
// Prepass 1: fp32 -> fp16
// ---------------------------------------------------------------------------
__global__ __launch_bounds__(256)
void cvt_f16(const float* __restrict__ src, __half* __restrict__ dst, int n4)
{
    int i = blockIdx.x * 256 + threadIdx.x;
    if (i >= n4) return;
    float4 v = ((const float4*)src)[i];
    ((__half2*)dst)[i * 2 + 0] = __floats2half2_rn(v.x, v.y);
    ((__half2*)dst)[i * 2 + 1] = __floats2half2_rn(v.z, v.w);
}

// ---------------------------------------------------------------------------
// Prepass 2: W [K,N] fp32 -> W^T [N,K] fp16
// ---------------------------------------------------------------------------
__global__ __launch_bounds__(256)
void wt_cvt(const float* __restrict__ W, __half* __restrict__ Wt, int K, int N)
{
    __shared__ float tile[32][33];
    const int tx = threadIdx.x & 31;
    const int ty = threadIdx.x >> 5;
    const int k0 = blockIdx.y * 32;
    const int n0 = blockIdx.x * 32;
#pragma unroll
    for (int r = ty; r < 32; r += 8)
        tile[r][tx] = W[(size_t)(k0 + r) * N + n0 + tx];
    __syncthreads();
#pragma unroll
    for (int r = ty; r < 32; r += 8)
        Wt[(size_t)(n0 + r) * K + k0 + tx] = __float2half_rn(tile[tx][r]);
}

// ---------------------------------------------------------------------------
// HMMA GEMM fp16 single-term (unchanged from R9). cp.async 3-stage pipeline,
// 512 threads, warp tile 32x32. MODE 0: fp32 C + bias. MODE 1: q/k/v scatter.
// ---------------------------------------------------------------------------
#define SM_A  0
#define SM_B  16384
#define SM_STAGE 32768
#define SM_TOTAL (3 * SM_STAGE)     // 98304

template<int MODE>
__global__ __launch_bounds__(512)
void gemm_f16(const __half* __restrict__ A, const __half* __restrict__ Bt,
              const float* __restrict__ bias, float* __restrict__ Cout,
              __half* __restrict__ qh, __half* __restrict__ kh,
              __half* __restrict__ vh,
              int M, int N, int K)
{
    extern __shared__ char smem[];
    const uint32_t sb = smem_to_u32(smem);

    const int tid  = threadIdx.x;
    const int wid  = tid >> 5;
    const int lane = tid & 31;
    const int rowBase = blockIdx.y * 128;
    const int colBase = blockIdx.x * 128;

    const int warp_m = wid & 3;
    const int warp_n = wid >> 2;

    float acc[2][4][4];
#pragma unroll
    for (int i = 0; i < 2; i++)
#pragma unroll
        for (int j = 0; j < 4; j++)
#pragma unroll
            for (int r = 0; r < 4; r++) acc[i][j][r] = 0.f;

    const int a_r  = warp_m * 32 + (lane & 15);
    const int a_cb = (lane >> 4) << 4;
    const int g    = lane >> 3;
    const int b_r  = warp_n * 32 + ((g >> 1) << 3) + (lane & 7);
    const int b_cb = (g & 1) << 4;

    int ld_r[2], ld_cb[2];
    uint32_t ld_sw[2];
#pragma unroll
    for (int it = 0; it < 2; it++) {
        int idx = it * 512 + tid;
        ld_r[it]  = idx >> 3;
        ld_cb[it] = (idx & 7) << 4;
        ld_sw[it] = swz((uint32_t)(ld_r[it] * 128 + ld_cb[it]));
    }

    auto issue = [&](int ch, int st) {
        const int k0 = ch * 64;
        const uint32_t sbase = sb + st * SM_STAGE;
#pragma unroll
        for (int it = 0; it < 2; it++) {
            const int r = ld_r[it], cb = ld_cb[it];
            const uint32_t sw = ld_sw[it];
            cp16(sbase + SM_A + sw, (const char*)(A  + (size_t)(rowBase + r) * K + k0) + cb);
            cp16(sbase + SM_B + sw, (const char*)(Bt + (size_t)(colBase + r) * K + k0) + cb);
        }
        cp_commit();
    };

    const int nChunks = K / 64;
    issue(0, 0);
    issue(1, 1);

    for (int ch = 0; ch < nChunks; ch++) {
        if (ch + 1 < nChunks) cp_wait<1>(); else cp_wait<0>();
        __syncthreads();
        if (ch + 2 < nChunks) issue(ch + 2, (ch + 2) % 3);

        const uint32_t sbase = sb + (ch % 3) * SM_STAGE;
#pragma unroll
        for (int ks = 0; ks < 4; ks++) {
            const int kb = ks * 32;
            uint32_t af[2][4];
#pragma unroll
            for (int mi = 0; mi < 2; mi++) {
                uint32_t off = swz((uint32_t)((a_r + mi * 16) * 128 + kb + a_cb));
                ldsm_x4(af[mi], sbase + SM_A + off);
            }
            uint32_t bf[2][4];
#pragma unroll
            for (int nt = 0; nt < 2; nt++) {
                uint32_t off = swz((uint32_t)((b_r + nt * 16) * 128 + kb + b_cb));
                ldsm_x4(bf[nt], sbase + SM_B + off);
            }
#pragma unroll
            for (int mi = 0; mi < 2; mi++)
#pragma unroll
                for (int nj = 0; nj < 4; nj++) {
                    const uint32_t* bj = &bf[nj >> 1][(nj & 1) * 2];
                    mma16816h(acc[mi][nj], af[mi], bj[0], bj[1]);
                }
        }
    }

    const int er = rowBase + warp_m * 32 + (lane >> 2);
    const int ec = colBase + warp_n * 32 + (lane & 3) * 2;

    if (MODE == 0) {
#pragma unroll
        for (int mi = 0; mi < 2; mi++) {
#pragma unroll
            for (int nj = 0; nj < 4; nj++) {
                const int c = ec + nj * 8;
                const float bx = __ldg(bias + c);
                const float by = __ldg(bias + c + 1);
                float2 v0 = { acc[mi][nj][0] + bx, acc[mi][nj][1] + by };
                float2 v1 = { acc[mi][nj][2] + bx, acc[mi][nj][3] + by };
                *(float2*)(Cout + (size_t)(er + mi * 16) * N + c) = v0;
                *(float2*)(Cout + (size_t)(er + mi * 16 + 8) * N + c) = v1;
            }
        }
    } else {
#pragma unroll
        for (int nj = 0; nj < 4; nj++) {
            const int c   = ec + nj * 8;
            const int sec = c >> 10;             // 0=q,1=k,2=v
            const int hh  = (c & 1023) >> 6;
            const int dd  = c & 63;
            const float sc = (sec == 0) ? QS : 1.f;
            const float bx = __ldg(bias + c)     * sc;
            const float by = __ldg(bias + c + 1) * sc;
            __half* dp = (sec == 0) ? qh : (sec == 1) ? kh : vh;
#pragma unroll
            for (int mi = 0; mi < 2; mi++) {
#pragma unroll
                for (int half = 0; half < 2; half++) {
                    const int r = er + mi * 16 + half * 8;
                    const int bb = r >> 11, tt = r & 2047;
                    const size_t dst = (((size_t)bb * H_ + hh) * T_ + tt) * D_ + dd;
                    float v0 = fmaf(acc[mi][nj][half * 2],     sc, bx);
                    float v1 = fmaf(acc[mi][nj][half * 2 + 1], sc, by);
                    *(__half2*)(dp + dst) = __floats2half2_rn(v0, v1);
                }
            }
        }
    }
}

// ---------------------------------------------------------------------------
// Flash attention v2: fp16 single-term, m=0 softmax, 128 threads / 4 warps,
// 32 q-rows per warp (2 Q-frags), Q frags hoisted into registers.
// Per-warp masked-tile skip on the diagonal tiles.
// cp.async 3-stage K/V pipeline. Output fp16 att [B*T, C].
// ---------------------------------------------------------------------------
#define FA_Q 0
#define FA_STAGE0 16384
#define FA_STSZ 16384
#define FA_ST(s) (FA_STAGE0 + (s) * FA_STSZ)
#define FA_K 0
#define FA_V 8192
#define FA_TOTAL (FA_STAGE0 + 3 * FA_STSZ)   // 65536

__global__ __launch_bounds__(128)
void flash_attn(const __half* __restrict__ qh, const __half* __restrict__ kh,
                const __half* __restrict__ vh, __half* __restrict__ att)
{
    extern __shared__ char smem[];
    const uint32_t sb = smem_to_u32(smem);
    const int tid = threadIdx.x, wid = tid >> 5, lane = tid & 31;
    const int h = blockIdx.y, b = blockIdx.z;
    const int qt = gridDim.x - 1 - blockIdx.x;    // big tiles first

    const size_t hoff = ((size_t)b * H_ + h) * T_ * D_;
    const char* qh_p = (const char*)(qh + hoff + (size_t)qt * 128 * D_);
    const char* kh_p = (const char*)(kh + hoff);
    const char* vh_p = (const char*)(vh + hoff);

    auto issue_kv = [&](int kt, int st) {
        const uint32_t sbase = sb + FA_ST(st);
#pragma unroll
        for (int it = 0; it < 4; it++) {
            int idx = it * 128 + tid;            // 0..511
            int r = idx >> 3, cb = (idx & 7) << 4;
            uint32_t sw = swz((uint32_t)(r * 128 + cb));
            size_t go = (size_t)(kt * 64 + r) * 128 + cb;    // bytes
            cp16(sbase + FA_K + sw, kh_p + go);
            cp16(sbase + FA_V + sw, vh_p + go);
        }
        cp_commit();
    };

    const int nkt = 2 * qt + 2;
    issue_kv(0, 0);
    issue_kv(1, 1);

    // Load Q tile into smem (plain stores), then hoist Q frags to registers.
#pragma unroll
    for (int it = 0; it < 8; it++) {
        int idx = it * 128 + tid;
        int r = idx >> 3, cb = (idx & 7) << 4;
        uint32_t sw = swz((uint32_t)(r * 128 + cb));
        *(uint4*)(smem + FA_Q + sw) = *(const uint4*)(qh_p + r * 128 + cb);
    }
    __syncthreads();

    const int a_r  = wid * 32 + (lane & 15);
    const int a_cb = (lane >> 4) << 4;
    uint32_t qf[4][2][4];                 // [ks][mi][reg], loop-invariant
#pragma unroll
    for (int ks = 0; ks < 4; ks++)
#pragma unroll
        for (int mi = 0; mi < 2; mi++) {
            uint32_t off = swz((uint32_t)((a_r + mi * 16) * 128 + ks * 32 + a_cb));
            ldsm_x4(qf[ks][mi], sb + FA_Q + off);
        }

    float o[2][8][4];
#pragma unroll
    for (int mi = 0; mi < 2; mi++)
#pragma unroll
        for (int nj = 0; nj < 8; nj++)
#pragma unroll
            for (int r = 0; r < 4; r++) o[mi][nj][r] = 0.f;
    float ls[4] = { 0.f, 0.f, 0.f, 0.f };

    const int g    = lane >> 3;
    const int b_r  = ((g >> 1) << 3) + (lane & 7);
    const int b_cb = (g & 1) << 4;
    const int vrow = ((lane >> 3) & 1) * 8 + (lane & 7);
    const int vcb  = ((lane >> 4) & 1) * 16;
    const int warpRowMax = qt * 128 + wid * 32 + 31;   // last row this warp owns

    for (int kt = 0; kt < nkt; kt++) {
        if (kt + 1 < nkt) cp_wait<1>(); else cp_wait<0>();
        __syncthreads();
        if (kt + 2 < nkt) issue_kv(kt + 2, (kt + 2) % 3);

        // Fully-masked tile for this warp? (all keys above the diagonal)
        if (kt * 64 > warpRowMax) continue;

        const uint32_t kv = sb + FA_ST(kt % 3);

        // ---- S = Q K^T (fp16 single), K frags shared across both Q frags ----
        float s[2][8][4];
#pragma unroll
        for (int mi = 0; mi < 2; mi++)
#pragma unroll
            for (int nj = 0; nj < 8; nj++)
#pragma unroll
                for (int r = 0; r < 4; r++) s[mi][nj][r] = 0.f;

#pragma unroll
        for (int ks = 0; ks < 4; ks++) {
            uint32_t kb[4][4];
#pragma unroll
            for (int nt = 0; nt < 4; nt++) {
                uint32_t off = swz((uint32_t)((b_r + nt * 16) * 128 + ks * 32 + b_cb));
                ldsm_x4(kb[nt], kv + FA_K + off);
            }
#pragma unroll
            for (int mi = 0; mi < 2; mi++)
#pragma unroll
                for (int nj = 0; nj < 8; nj++) {
                    const uint32_t* bj = &kb[nj >> 1][(nj & 1) * 2];
                    mma16816h(s[mi][nj], qf[ks][mi], bj[0], bj[1]);
                }
        }

        // ---- causal mask (diagonal tiles only) ----
        if (kt * 64 + 63 > qt * 128 + wid * 32) {
            const int colb = kt * 64 + (lane & 3) * 2;
#pragma unroll
            for (int mi = 0; mi < 2; mi++) {
                const int r0 = qt * 128 + wid * 32 + mi * 16 + (lane >> 2);
                const int r1 = r0 + 8;
#pragma unroll
                for (int nj = 0; nj < 8; nj++) {
                    const int c0 = colb + nj * 8, c1 = c0 + 1;
                    if (c0 > r0) s[mi][nj][0] = -1e30f;
                    if (c1 > r0) s[mi][nj][1] = -1e30f;
                    if (c0 > r1) s[mi][nj][2] = -1e30f;
                    if (c1 > r1) s[mi][nj][3] = -1e30f;
                }
            }
        }

        // ---- p = 2^s (no max), accumulate l, pack P fp16 ----
        uint32_t ph[2][4][4];
#pragma unroll
        for (int mi = 0; mi < 2; mi++) {
#pragma unroll
            for (int nj = 0; nj < 8; nj++) {
                float p0 = ex2(s[mi][nj][0]);
                float p1 = ex2(s[mi][nj][1]);
                float p2 = ex2(s[mi][nj][2]);
                float p3 = ex2(s[mi][nj][3]);
                s[mi][nj][0] = p0; s[mi][nj][1] = p1;
                s[mi][nj][2] = p2; s[mi][nj][3] = p3;
                ls[mi * 2 + 0] += p0 + p1;
                ls[mi * 2 + 1] += p2 + p3;
            }
#pragma unroll
            for (int ks = 0; ks < 4; ks++) {
#pragma unroll
                for (int rr = 0; rr < 4; rr++) {
                    const int nj = 2 * ks + (rr >> 1);
                    const int r0 = (rr & 1) * 2;
                    __half2 hh = __floats2half2_rn(s[mi][nj][r0], s[mi][nj][r0 + 1]);
                    ph[mi][ks][rr] = *(uint32_t*)&hh;
                }
            }
        }

        // ---- O += P V (fp16), V frags shared across both row-halves ----
#pragma unroll
        for (int ks = 0; ks < 4; ks++) {
#pragma unroll
            for (int nd = 0; nd < 4; nd++) {
                uint32_t vf[4];
                uint32_t off = swz((uint32_t)((ks * 16 + vrow) * 128 + nd * 32 + vcb));
                ldsm_x4_t(vf, kv + FA_V + off);
#pragma unroll
                for (int mi = 0; mi < 2; mi++) {
                    mma16816h(o[mi][nd * 2],     ph[mi][ks], vf[0], vf[1]);
                    mma16816h(o[mi][nd * 2 + 1], ph[mi][ks], vf[2], vf[3]);
                }
            }
        }
    }

    // ---- epilogue: reduce l across quad lanes, O / l -> fp16 att ----
    float inv[4];
#pragma unroll
    for (int si = 0; si < 4; si++) {
        float l = ls[si];
        l += __shfl_xor_sync(0xffffffffu, l, 1);
        l += __shfl_xor_sync(0xffffffffu, l, 2);
        inv[si] = 1.f / l;
    }
    const int ecb = h * 64 + (lane & 3) * 2;
#pragma unroll
    for (int mi = 0; mi < 2; mi++) {
        const int er0 = qt * 128 + wid * 32 + mi * 16 + (lane >> 2);
        const size_t row = (size_t)b * T_ + er0;
#pragma unroll
        for (int nj = 0; nj < 8; nj++) {
            *(__half2*)(att + row * C_ + ecb + nj * 8) =
                __floats2half2_rn(o[mi][nj][0] * inv[mi * 2],
                                  o[mi][nj][1] * inv[mi * 2]);
            *(__half2*)(att + (row + 8) * C_ + ecb + nj * 8) =
                __floats2half2_rn(o[mi][nj][2] * inv[mi * 2 + 1],
                                  o[mi][nj][3] * inv[mi * 2 + 1]);
        }
    }
}

// ---------------------------------------------------------------------------
// Launch sequence
// ---------------------------------------------------------------------------
extern "C" void kernel_launch(void* const* d_in, const int* in_sizes, int n_in,
                              void* d_out, int out_size)
{
    const float* x      = (const float*)d_in[0];
    const float* w_qkv  = (const float*)d_in[1];
    const float* b_qkv  = (const float*)d_in[2];
    const float* w_proj = (const float*)d_in[3];
    const float* b_proj = (const float*)d_in[4];
    float* out = (float*)d_out;

    __half *xh, *wt, *qh, *kh, *vh;
    cudaGetSymbolAddress((void**)&xh, g_xh);
    cudaGetSymbolAddress((void**)&wt, g_wt);
    cudaGetSymbolAddress((void**)&qh, g_qh);
    cudaGetSymbolAddress((void**)&kh, g_kh);
    cudaGetSymbolAddress((void**)&vh, g_vh);

    cudaFuncSetAttribute(gemm_f16<0>, cudaFuncAttributeMaxDynamicSharedMemorySize, SM_TOTAL);
    cudaFuncSetAttribute(gemm_f16<1>, cudaFuncAttributeMaxDynamicSharedMemorySize, SM_TOTAL);
    cudaFuncSetAttribute(flash_attn, cudaFuncAttributeMaxDynamicSharedMemorySize, FA_TOTAL);

    // 1) x -> fp16
    {
        int n4 = (M_ROWS * C_) / 4;
        cvt_f16<<<(n4 + 255) / 256, 256>>>(x, xh, n4);
    }
    // 2) transpose+cvt w_qkv -> [N,K] fp16
    {
        dim3 grid(N_QKV / 32, C_ / 32);
        wt_cvt<<<grid, 256>>>(w_qkv, wt, C_, N_QKV);
    }
    // 3) QKV GEMM -> per-head q (scaled)/k/v fp16
    {
        dim3 grid(N_QKV / 128, M_ROWS / 128);
        gemm_f16<1><<<grid, 512, SM_TOTAL>>>(xh, wt, b_qkv, nullptr,
                                             qh, kh, vh, M_ROWS, N_QKV, C_);
    }
    // 4) flash attention -> fp16 att (reuses xh)
    {
        dim3 grid(T_ / 128, H_, B_);
        flash_attn<<<grid, 128, FA_TOTAL>>>(qh, kh, vh, xh);
    }
    // 5) transpose+cvt w_proj
    {
        dim3 grid(C_ / 32, C_ / 32);
        wt_cvt<<<grid, 256>>>(w_proj, wt, C_, C_);
    }
    // 6) proj GEMM -> fp32 out
    {
        dim3 grid(C_ / 128, M_ROWS / 128);
        gemm_f16<0><<<grid, 512, SM_TOTAL>>>(xh, wt, b_proj, out,
                                             nullptr, nullptr, nullptr,
                                             M_ROWS, C_, C_);
    }
}

// round 11
// speedup vs baseline: 8.0309x; 1.0060x over previous
#include <cuda_runtime.h>
#include <cuda_bf16.h>
#include <cuda_fp16.h>
#include <cstdint>

// ---------------------------------------------------------------------------
// Problem constants
// ---------------------------------------------------------------------------
#define B_ 2
#define T_ 2048
#define C_ 1024
#define H_ 16
#define D_ 64
#define M_ROWS (B_ * T_)     // 4096
#define N_QKV  (3 * C_)      // 3072

// softmax scale * log2(e) folded into Q: (1/8) * 1.4426950408889634
#define QS 0.18033688011112042f

// Scratch (__device__ globals; allocation-free rule)
__device__ __half g_xh[(size_t)M_ROWS * C_];        // activations fp16 (x, then att)
__device__ __half g_wt[(size_t)N_QKV * C_];         // W^T fp16 [N,K]
// per-head fp16 [B,H,T,D]
__device__ __half g_qh[(size_t)B_ * H_ * T_ * D_];  // q (pre-scaled by QS)
__device__ __half g_kh[(size_t)B_ * H_ * T_ * D_];
__device__ __half g_vh[(size_t)B_ * H_ * T_ * D_];

// ---------------------------------------------------------------------------
// Warp MMA / async-copy helpers (sm_80+ baseline)
// ---------------------------------------------------------------------------
__device__ __forceinline__ uint32_t smem_to_u32(const void* p) {
    uint32_t a;
    asm("{ .reg .u64 t; cvta.to.shared.u64 t, %1; cvt.u32.u64 %0, t; }"
        : "=r"(a) : "l"(p));
    return a;
}
__device__ __forceinline__ void ldsm_x4(uint32_t (&r)[4], uint32_t addr) {
    asm volatile("ldmatrix.sync.aligned.m8n8.x4.shared.b16 {%0,%1,%2,%3}, [%4];"
                 : "=r"(r[0]), "=r"(r[1]), "=r"(r[2]), "=r"(r[3]) : "r"(addr));
}
__device__ __forceinline__ void ldsm_x4_t(uint32_t (&r)[4], uint32_t addr) {
    asm volatile("ldmatrix.sync.aligned.m8n8.x4.trans.shared.b16 {%0,%1,%2,%3}, [%4];"
                 : "=r"(r[0]), "=r"(r[1]), "=r"(r[2]), "=r"(r[3]) : "r"(addr));
}
__device__ __forceinline__ void mma16816h(float (&d)[4],
                                          const uint32_t (&a)[4],
                                          const uint32_t b0, const uint32_t b1) {
    asm volatile(
        "mma.sync.aligned.m16n8k16.row.col.f32.f16.f16.f32 "
        "{%0,%1,%2,%3}, {%4,%5,%6,%7}, {%8,%9}, {%0,%1,%2,%3};"
        : "+f"(d[0]), "+f"(d[1]), "+f"(d[2]), "+f"(d[3])
        : "r"(a[0]), "r"(a[1]), "r"(a[2]), "r"(a[3]), "r"(b0), "r"(b1));
}
__device__ __forceinline__ uint32_t swz(uint32_t off) {
    return off ^ ((off >> 3) & 0x70);
}
__device__ __forceinline__ float ex2(float x) {
    float y; asm("ex2.approx.ftz.f32 %0, %1;" : "=f"(y) : "f"(x)); return y;
}
__device__ __forceinline__ void cp16(uint32_t dst, const void* src) {
    asm volatile("cp.async.ca.shared.global [%0], [%1], 16;" :: "r"(dst), "l"(src));
}
__device__ __forceinline__ void cp_commit() {
    asm volatile("cp.async.commit_group;" ::: "memory");
}
template<int N> __device__ __forceinline__ void cp_wait() {
    asm volatile("cp.async.wait_group %0;" :: "n"(N) : "memory");
}

// ---------------------------------------------------------------------------
// Prepass 1: fp32 -> fp16
// ---------------------------------------------------------------------------
__global__ __launch_bounds__(256)
void cvt_f16(const float* __restrict__ src, __half* __restrict__ dst, int n4)
{
    int i = blockIdx.x * 256 + threadIdx.x;
    if (i >= n4) return;
    float4 v = ((const float4*)src)[i];
    ((__half2*)dst)[i * 2 + 0] = __floats2half2_rn(v.x, v.y);
    ((__half2*)dst)[i * 2 + 1] = __floats2half2_rn(v.z, v.w);
}

// ---------------------------------------------------------------------------
// Prepass 2: W [K,N] fp32 -> W^T [N,K] fp16
// ---------------------------------------------------------------------------
__global__ __launch_bounds__(256)
void wt_cvt(const float* __restrict__ W, __half* __restrict__ Wt, int K, int N)
{
    __shared__ float tile[32][33];
    const int tx = threadIdx.x & 31;
    const int ty = threadIdx.x >> 5;
    const int k0 = blockIdx.y * 32;
    const int n0 = blockIdx.x * 32;
#pragma unroll
    for (int r = ty; r < 32; r += 8)
        tile[r][tx] = W[(size_t)(k0 + r) * N + n0 + tx];
    __syncthreads();
#pragma unroll
    for (int r = ty; r < 32; r += 8)
        Wt[(size_t)(n0 + r) * K + k0 + tx] = __float2half_rn(tile[tx][r]);
}

// ---------------------------------------------------------------------------
// HMMA GEMM fp16 single-term, 256 threads / 8 warps, warp tile 64x32
// (6 LDSM : 16 MMA per ks). cp.async 3-stage, 2 CTAs/SM.
// MODE 0: fp32 C + bias.  MODE 1: per-head q(scaled)/k/v scatter.
// ---------------------------------------------------------------------------
#define SM_A  0
#define SM_B  16384
#define SM_STAGE 32768
#define SM_TOTAL (3 * SM_STAGE)     // 98304

template<int MODE>
__global__ __launch_bounds__(256)
void gemm_f16(const __half* __restrict__ A, const __half* __restrict__ Bt,
              const float* __restrict__ bias, float* __restrict__ Cout,
              __half* __restrict__ qh, __half* __restrict__ kh,
              __half* __restrict__ vh,
              int M, int N, int K)
{
    extern __shared__ char smem[];
    const uint32_t sb = smem_to_u32(smem);

    const int tid  = threadIdx.x;
    const int wid  = tid >> 5;
    const int lane = tid & 31;
    const int rowBase = blockIdx.y * 128;
    const int colBase = blockIdx.x * 128;

    const int warp_m = wid & 1;        // 2 x 64-row halves
    const int warp_n = wid >> 1;       // 4 x 32-col quarters

    float acc[4][4][4];
#pragma unroll
    for (int i = 0; i < 4; i++)
#pragma unroll
        for (int j = 0; j < 4; j++)
#pragma unroll
            for (int r = 0; r < 4; r++) acc[i][j][r] = 0.f;

    const int a_r  = warp_m * 64 + (lane & 15);
    const int a_cb = (lane >> 4) << 4;
    const int g    = lane >> 3;
    const int b_r  = warp_n * 32 + ((g >> 1) << 3) + (lane & 7);
    const int b_cb = (g & 1) << 4;

    // load slots: 1024 uint4 per tile / 256 threads = 4 each
    int ld_r[4], ld_cb[4];
    uint32_t ld_sw[4];
#pragma unroll
    for (int it = 0; it < 4; it++) {
        int idx = it * 256 + tid;
        ld_r[it]  = idx >> 3;
        ld_cb[it] = (idx & 7) << 4;
        ld_sw[it] = swz((uint32_t)(ld_r[it] * 128 + ld_cb[it]));
    }

    auto issue = [&](int ch, int st) {
        const int k0 = ch * 64;
        const uint32_t sbase = sb + st * SM_STAGE;
#pragma unroll
        for (int it = 0; it < 4; it++) {
            const int r = ld_r[it], cb = ld_cb[it];
            const uint32_t sw = ld_sw[it];
            cp16(sbase + SM_A + sw, (const char*)(A  + (size_t)(rowBase + r) * K + k0) + cb);
            cp16(sbase + SM_B + sw, (const char*)(Bt + (size_t)(colBase + r) * K + k0) + cb);
        }
        cp_commit();
    };

    const int nChunks = K / 64;
    issue(0, 0);
    issue(1, 1);

    for (int ch = 0; ch < nChunks; ch++) {
        if (ch + 1 < nChunks) cp_wait<1>(); else cp_wait<0>();
        __syncthreads();
        if (ch + 2 < nChunks) issue(ch + 2, (ch + 2) % 3);

        const uint32_t sbase = sb + (ch % 3) * SM_STAGE;
#pragma unroll
        for (int ks = 0; ks < 4; ks++) {
            const int kb = ks * 32;
            uint32_t af[4][4];
#pragma unroll
            for (int mi = 0; mi < 4; mi++) {
                uint32_t off = swz((uint32_t)((a_r + mi * 16) * 128 + kb + a_cb));
                ldsm_x4(af[mi], sbase + SM_A + off);
            }
            uint32_t bf[2][4];
#pragma unroll
            for (int nt = 0; nt < 2; nt++) {
                uint32_t off = swz((uint32_t)((b_r + nt * 16) * 128 + kb + b_cb));
                ldsm_x4(bf[nt], sbase + SM_B + off);
            }
#pragma unroll
            for (int mi = 0; mi < 4; mi++)
#pragma unroll
                for (int nj = 0; nj < 4; nj++) {
                    const uint32_t* bj = &bf[nj >> 1][(nj & 1) * 2];
                    mma16816h(acc[mi][nj], af[mi], bj[0], bj[1]);
                }
        }
    }

    const int er = rowBase + warp_m * 64 + (lane >> 2);
    const int ec = colBase + warp_n * 32 + (lane & 3) * 2;

    if (MODE == 0) {
#pragma unroll
        for (int mi = 0; mi < 4; mi++) {
#pragma unroll
            for (int nj = 0; nj < 4; nj++) {
                const int c = ec + nj * 8;
                const float bx = __ldg(bias + c);
                const float by = __ldg(bias + c + 1);
                float2 v0 = { acc[mi][nj][0] + bx, acc[mi][nj][1] + by };
                float2 v1 = { acc[mi][nj][2] + bx, acc[mi][nj][3] + by };
                *(float2*)(Cout + (size_t)(er + mi * 16) * N + c) = v0;
                *(float2*)(Cout + (size_t)(er + mi * 16 + 8) * N + c) = v1;
            }
        }
    } else {
#pragma unroll
        for (int nj = 0; nj < 4; nj++) {
            const int c   = ec + nj * 8;
            const int sec = c >> 10;             // 0=q,1=k,2=v
            const int hh  = (c & 1023) >> 6;
            const int dd  = c & 63;
            const float sc = (sec == 0) ? QS : 1.f;
            const float bx = __ldg(bias + c)     * sc;
            const float by = __ldg(bias + c + 1) * sc;
            __half* dp = (sec == 0) ? qh : (sec == 1) ? kh : vh;
#pragma unroll
            for (int mi = 0; mi < 4; mi++) {
#pragma unroll
                for (int half = 0; half < 2; half++) {
                    const int r = er + mi * 16 + half * 8;
                    const int bb = r >> 11, tt = r & 2047;
                    const size_t dst = (((size_t)bb * H_ + hh) * T_ + tt) * D_ + dd;
                    float v0 = fmaf(acc[mi][nj][half * 2],     sc, bx);
                    float v1 = fmaf(acc[mi][nj][half * 2 + 1], sc, by);
                    *(__half2*)(dp + dst) = __floats2half2_rn(v0, v1);
                }
            }
        }
    }
}

// ---------------------------------------------------------------------------
// Flash attention v3: fp16 single-term, m=0 softmax, 128 threads / 4 warps,
// 32 q-rows per warp, Q frags hoisted. 128-key DOUBLE TILE per iteration
// (two 64-key halves processed back-to-back) -> half the syncs/waits.
// cp.async 3-stage (32KB/stage). Output fp16 att [B*T, C].
// ---------------------------------------------------------------------------
#define FA_Q 0
#define FA_STAGE0 16384
#define FA_STSZ 32768
#define FA_ST(s) (FA_STAGE0 + (s) * FA_STSZ)
#define FA_K 0
#define FA_V 16384
#define FA_TOTAL (FA_STAGE0 + 3 * FA_STSZ)   // 114688

__global__ __launch_bounds__(128)
void flash_attn(const __half* __restrict__ qh, const __half* __restrict__ kh,
                const __half* __restrict__ vh, __half* __restrict__ att)
{
    extern __shared__ char smem[];
    const uint32_t sb = smem_to_u32(smem);
    const int tid = threadIdx.x, wid = tid >> 5, lane = tid & 31;
    const int h = blockIdx.y, b = blockIdx.z;
    const int qt = gridDim.x - 1 - blockIdx.x;    // big tiles first

    const size_t hoff = ((size_t)b * H_ + h) * T_ * D_;
    const char* qh_p = (const char*)(qh + hoff + (size_t)qt * 128 * D_);
    const char* kh_p = (const char*)(kh + hoff);
    const char* vh_p = (const char*)(vh + hoff);

    // one iteration = 128 keys (two 64-key halves); K 16KB + V 16KB per stage
    auto issue_kv = [&](int it128, int st) {
        const uint32_t sbase = sb + FA_ST(st);
#pragma unroll
        for (int it = 0; it < 8; it++) {
            int idx = it * 128 + tid;            // 0..1023
            int r = idx >> 3, cb = (idx & 7) << 4;
            uint32_t sw = swz((uint32_t)(r * 128 + cb));
            size_t go = (size_t)(it128 * 128 + r) * 128 + cb;    // bytes
            cp16(sbase + FA_K + sw, kh_p + go);
            cp16(sbase + FA_V + sw, vh_p + go);
        }
        cp_commit();
    };

    const int nit = qt + 1;               // 128-key iterations
    issue_kv(0, 0);
    if (nit > 1) issue_kv(1, 1);

    // Load Q tile into smem (plain stores), then hoist Q frags to registers.
#pragma unroll
    for (int it = 0; it < 8; it++) {
        int idx = it * 128 + tid;
        int r = idx >> 3, cb = (idx & 7) << 4;
        uint32_t sw = swz((uint32_t)(r * 128 + cb));
        *(uint4*)(smem + FA_Q + sw) = *(const uint4*)(qh_p + r * 128 + cb);
    }
    __syncthreads();

    const int a_r  = wid * 32 + (lane & 15);
    const int a_cb = (lane >> 4) << 4;
    uint32_t qf[4][2][4];                 // [ks][mi][reg], loop-invariant
#pragma unroll
    for (int ks = 0; ks < 4; ks++)
#pragma unroll
        for (int mi = 0; mi < 2; mi++) {
            uint32_t off = swz((uint32_t)((a_r + mi * 16) * 128 + ks * 32 + a_cb));
            ldsm_x4(qf[ks][mi], sb + FA_Q + off);
        }

    float o[2][8][4];
#pragma unroll
    for (int mi = 0; mi < 2; mi++)
#pragma unroll
        for (int nj = 0; nj < 8; nj++)
#pragma unroll
            for (int r = 0; r < 4; r++) o[mi][nj][r] = 0.f;
    float ls[4] = { 0.f, 0.f, 0.f, 0.f };

    const int g    = lane >> 3;
    const int b_r  = ((g >> 1) << 3) + (lane & 7);
    const int b_cb = (g & 1) << 4;
    const int vrow = ((lane >> 3) & 1) * 8 + (lane & 7);
    const int vcb  = ((lane >> 4) & 1) * 16;
    const int warpRow0   = qt * 128 + wid * 32;        // first row this warp owns
    const int warpRowMax = warpRow0 + 31;              // last row this warp owns

    for (int it128 = 0; it128 < nit; it128++) {
        if (it128 + 1 < nit) cp_wait<1>(); else cp_wait<0>();
        __syncthreads();
        if (it128 + 2 < nit) issue_kv(it128 + 2, (it128 + 2) % 3);

        const uint32_t kvb = sb + FA_ST(it128 % 3);

#pragma unroll
        for (int half = 0; half < 2; half++) {
            const int key0 = it128 * 128 + half * 64;
            // fully-masked 64-key sub-tile for this warp?
            if (key0 > warpRowMax) continue;

            const uint32_t krow0 = (uint32_t)(half * 64) * 128;   // byte offset

            // ---- S = Q K^T ----
            float s[2][8][4];
#pragma unroll
            for (int mi = 0; mi < 2; mi++)
#pragma unroll
                for (int nj = 0; nj < 8; nj++)
#pragma unroll
                    for (int r = 0; r < 4; r++) s[mi][nj][r] = 0.f;

#pragma unroll
            for (int ks = 0; ks < 4; ks++) {
                uint32_t kb[4][4];
#pragma unroll
                for (int nt = 0; nt < 4; nt++) {
                    uint32_t off = swz(krow0 + (uint32_t)((b_r + nt * 16) * 128 + ks * 32 + b_cb));
                    ldsm_x4(kb[nt], kvb + FA_K + off);
                }
#pragma unroll
                for (int mi = 0; mi < 2; mi++)
#pragma unroll
                    for (int nj = 0; nj < 8; nj++) {
                        const uint32_t* bj = &kb[nj >> 1][(nj & 1) * 2];
                        mma16816h(s[mi][nj], qf[ks][mi], bj[0], bj[1]);
                    }
            }

            // ---- causal mask (diagonal sub-tiles only) ----
            if (key0 + 63 > warpRow0) {
                const int colb = key0 + (lane & 3) * 2;
#pragma unroll
                for (int mi = 0; mi < 2; mi++) {
                    const int r0 = warpRow0 + mi * 16 + (lane >> 2);
                    const int r1 = r0 + 8;
#pragma unroll
                    for (int nj = 0; nj < 8; nj++) {
                        const int c0 = colb + nj * 8, c1 = c0 + 1;
                        if (c0 > r0) s[mi][nj][0] = -1e30f;
                        if (c1 > r0) s[mi][nj][1] = -1e30f;
                        if (c0 > r1) s[mi][nj][2] = -1e30f;
                        if (c1 > r1) s[mi][nj][3] = -1e30f;
                    }
                }
            }

            // ---- p = 2^s (no max), accumulate l, pack P fp16 ----
            uint32_t ph[2][4][4];
#pragma unroll
            for (int mi = 0; mi < 2; mi++) {
#pragma unroll
                for (int nj = 0; nj < 8; nj++) {
                    float p0 = ex2(s[mi][nj][0]);
                    float p1 = ex2(s[mi][nj][1]);
                    float p2 = ex2(s[mi][nj][2]);
                    float p3 = ex2(s[mi][nj][3]);
                    s[mi][nj][0] = p0; s[mi][nj][1] = p1;
                    s[mi][nj][2] = p2; s[mi][nj][3] = p3;
                    ls[mi * 2 + 0] += p0 + p1;
                    ls[mi * 2 + 1] += p2 + p3;
                }
#pragma unroll
                for (int ks = 0; ks < 4; ks++) {
#pragma unroll
                    for (int rr = 0; rr < 4; rr++) {
                        const int nj = 2 * ks + (rr >> 1);
                        const int r0 = (rr & 1) * 2;
                        __half2 hh = __floats2half2_rn(s[mi][nj][r0], s[mi][nj][r0 + 1]);
                        ph[mi][ks][rr] = *(uint32_t*)&hh;
                    }
                }
            }

            // ---- O += P V ----
#pragma unroll
            for (int ks = 0; ks < 4; ks++) {
#pragma unroll
                for (int nd = 0; nd < 4; nd++) {
                    uint32_t vf[4];
                    uint32_t off = swz(krow0 + (uint32_t)((ks * 16 + vrow) * 128 + nd * 32 + vcb));
                    ldsm_x4_t(vf, kvb + FA_V + off);
#pragma unroll
                    for (int mi = 0; mi < 2; mi++) {
                        mma16816h(o[mi][nd * 2],     ph[mi][ks], vf[0], vf[1]);
                        mma16816h(o[mi][nd * 2 + 1], ph[mi][ks], vf[2], vf[3]);
                    }
                }
            }
        }
    }

    // ---- epilogue: reduce l across quad lanes, O / l -> fp16 att ----
    float inv[4];
#pragma unroll
    for (int si = 0; si < 4; si++) {
        float l = ls[si];
        l += __shfl_xor_sync(0xffffffffu, l, 1);
        l += __shfl_xor_sync(0xffffffffu, l, 2);
        inv[si] = 1.f / l;
    }
    const int ecb = h * 64 + (lane & 3) * 2;
#pragma unroll
    for (int mi = 0; mi < 2; mi++) {
        const int er0 = qt * 128 + wid * 32 + mi * 16 + (lane >> 2);
        const size_t row = (size_t)b * T_ + er0;
#pragma unroll
        for (int nj = 0; nj < 8; nj++) {
            *(__half2*)(att + row * C_ + ecb + nj * 8) =
                __floats2half2_rn(o[mi][nj][0] * inv[mi * 2],
                                  o[mi][nj][1] * inv[mi * 2]);
            *(__half2*)(att + (row + 8) * C_ + ecb + nj * 8) =
                __floats2half2_rn(o[mi][nj][2] * inv[mi * 2 + 1],
                                  o[mi][nj][3] * inv[mi * 2 + 1]);
        }
    }
}

// ---------------------------------------------------------------------------
// Launch sequence
// ---------------------------------------------------------------------------
extern "C" void kernel_launch(void* const* d_in, const int* in_sizes, int n_in,
                              void* d_out, int out_size)
{
    const float* x      = (const float*)d_in[0];
    const float* w_qkv  = (const float*)d_in[1];
    const float* b_qkv  = (const float*)d_in[2];
    const float* w_proj = (const float*)d_in[3];
    const float* b_proj = (const float*)d_in[4];
    float* out = (float*)d_out;

    __half *xh, *wt, *qh, *kh, *vh;
    cudaGetSymbolAddress((void**)&xh, g_xh);
    cudaGetSymbolAddress((void**)&wt, g_wt);
    cudaGetSymbolAddress((void**)&qh, g_qh);
    cudaGetSymbolAddress((void**)&kh, g_kh);
    cudaGetSymbolAddress((void**)&vh, g_vh);

    cudaFuncSetAttribute(gemm_f16<0>, cudaFuncAttributeMaxDynamicSharedMemorySize, SM_TOTAL);
    cudaFuncSetAttribute(gemm_f16<1>, cudaFuncAttributeMaxDynamicSharedMemorySize, SM_TOTAL);
    cudaFuncSetAttribute(flash_attn, cudaFuncAttributeMaxDynamicSharedMemorySize, FA_TOTAL);

    // 1) x -> fp16
    {
        int n4 = (M_ROWS * C_) / 4;
        cvt_f16<<<(n4 + 255) / 256, 256>>>(x, xh, n4);
    }
    // 2) transpose+cvt w_qkv -> [N,K] fp16
    {
        dim3 grid(N_QKV / 32, C_ / 32);
        wt_cvt<<<grid, 256>>>(w_qkv, wt, C_, N_QKV);
    }
    // 3) QKV GEMM -> per-head q (scaled)/k/v fp16
    {
        dim3 grid(N_QKV / 128, M_ROWS / 128);
        gemm_f16<1><<<grid, 256, SM_TOTAL>>>(xh, wt, b_qkv, nullptr,
                                             qh, kh, vh, M_ROWS, N_QKV, C_);
    }
    // 4) flash attention -> fp16 att (reuses xh)
    {
        dim3 grid(T_ / 128, H_, B_);
        flash_attn<<<grid, 128, FA_TOTAL>>>(qh, kh, vh, xh);
    }
    // 5) transpose+cvt w_proj
    {
        dim3 grid(C_ / 32, C_ / 32);
        wt_cvt<<<grid, 256>>>(w_proj, wt, C_, C_);
    }
    // 6) proj GEMM -> fp32 out
    {
        dim3 grid(C_ / 128, M_ROWS / 128);
        gemm_f16<0><<<grid, 256, SM_TOTAL>>>(xh, wt, b_proj, out,
                                             nullptr, nullptr, nullptr,
                                             M_ROWS, C_, C_);
    }
}

// round 12
// speedup vs baseline: 8.3374x; 1.0382x over previous
#include <cuda_runtime.h>
#include <cuda_bf16.h>
#include <cuda_fp16.h>
#include <cstdint>

// ---------------------------------------------------------------------------
// Problem constants
// ---------------------------------------------------------------------------
#define B_ 2
#define T_ 2048
#define C_ 1024
#define H_ 16
#define D_ 64
#define M_ROWS (B_ * T_)     // 4096
#define N_QKV  (3 * C_)      // 3072

// softmax scale * log2(e) folded into Q: (1/8) * 1.4426950408889634
#define QS 0.18033688011112042f

// Scratch (__device__ globals; allocation-free rule)
__device__ __half g_xh[(size_t)M_ROWS * C_];        // activations fp16 (x, then att)
__device__ __half g_wt[(size_t)N_QKV * C_];         // W^T fp16 [N,K]
// per-head fp16 [B,H,T,D]
__device__ __half g_qh[(size_t)B_ * H_ * T_ * D_];  // q (pre-scaled by QS)
__device__ __half g_kh[(size_t)B_ * H_ * T_ * D_];
__device__ __half g_vh[(size_t)B_ * H_ * T_ * D_];

// ---------------------------------------------------------------------------
// Warp MMA / async-copy helpers (sm_80+ baseline)
// ---------------------------------------------------------------------------
__device__ __forceinline__ uint32_t smem_to_u32(const void* p) {
    uint32_t a;
    asm("{ .reg .u64 t; cvta.to.shared.u64 t, %1; cvt.u32.u64 %0, t; }"
        : "=r"(a) : "l"(p));
    return a;
}
__device__ __forceinline__ void ldsm_x4(uint32_t (&r)[4], uint32_t addr) {
    asm volatile("ldmatrix.sync.aligned.m8n8.x4.shared.b16 {%0,%1,%2,%3}, [%4];"
                 : "=r"(r[0]), "=r"(r[1]), "=r"(r[2]), "=r"(r[3]) : "r"(addr));
}
__device__ __forceinline__ void ldsm_x4_t(uint32_t (&r)[4], uint32_t addr) {
    asm volatile("ldmatrix.sync.aligned.m8n8.x4.trans.shared.b16 {%0,%1,%2,%3}, [%4];"
                 : "=r"(r[0]), "=r"(r[1]), "=r"(r[2]), "=r"(r[3]) : "r"(addr));
}
__device__ __forceinline__ void mma16816h(float (&d)[4],
                                          const uint32_t (&a)[4],
                                          const uint32_t b0, const uint32_t b1) {
    asm volatile(
        "mma.sync.aligned.m16n8k16.row.col.f32.f16.f16.f32 "
        "{%0,%1,%2,%3}, {%4,%5,%6,%7}, {%8,%9}, {%0,%1,%2,%3};"
        : "+f"(d[0]), "+f"(d[1]), "+f"(d[2]), "+f"(d[3])
        : "r"(a[0]), "r"(a[1]), "r"(a[2]), "r"(a[3]), "r"(b0), "r"(b1));
}
__device__ __forceinline__ uint32_t swz(uint32_t off) {
    return off ^ ((off >> 3) & 0x70);
}
__device__ __forceinline__ float ex2(float x) {
    float y; asm("ex2.approx.ftz.f32 %0, %1;" : "=f"(y) : "f"(x)); return y;
}
__device__ __forceinline__ void cp16(uint32_t dst, const void* src) {
    asm volatile("cp.async.ca.shared.global [%0], [%1], 16;" :: "r"(dst), "l"(src));
}
__device__ __forceinline__ void cp_commit() {
    asm volatile("cp.async.commit_group;" ::: "memory");
}
template<int N> __device__ __forceinline__ void cp_wait() {
    asm volatile("cp.async.wait_group %0;" :: "n"(N) : "memory");
}

// ---------------------------------------------------------------------------
// Prepass 1: fp32 -> fp16
// ---------------------------------------------------------------------------
__global__ __launch_bounds__(256)
void cvt_f16(const float* __restrict__ src, __half* __restrict__ dst, int n4)
{
    int i = blockIdx.x * 256 + threadIdx.x;
    if (i >= n4) return;
    float4 v = ((const float4*)src)[i];
    ((__half2*)dst)[i * 2 + 0] = __floats2half2_rn(v.x, v.y);
    ((__half2*)dst)[i * 2 + 1] = __floats2half2_rn(v.z, v.w);
}

// ---------------------------------------------------------------------------
// Prepass 2: W [K,N] fp32 -> W^T [N,K] fp16
// ---------------------------------------------------------------------------
__global__ __launch_bounds__(256)
void wt_cvt(const float* __restrict__ W, __half* __restrict__ Wt, int K, int N)
{
    __shared__ float tile[32][33];
    const int tx = threadIdx.x & 31;
    const int ty = threadIdx.x >> 5;
    const int k0 = blockIdx.y * 32;
    const int n0 = blockIdx.x * 32;
#pragma unroll
    for (int r = ty; r < 32; r += 8)
        tile[r][tx] = W[(size_t)(k0 + r) * N + n0 + tx];
    __syncthreads();
#pragma unroll
    for (int r = ty; r < 32; r += 8)
        Wt[(size_t)(n0 + r) * K + k0 + tx] = __float2half_rn(tile[tx][r]);
}

// ---------------------------------------------------------------------------
// HMMA GEMM fp16 single-term, 256 threads / 8 warps, warp tile 64x32
// (6 LDSM : 16 MMA per ks). cp.async 3-stage, 2 CTAs/SM.  [R11 — keep]
// MODE 0: fp32 C + bias.  MODE 1: per-head q(scaled)/k/v scatter.
// ---------------------------------------------------------------------------
#define SM_A  0
#define SM_B  16384
#define SM_STAGE 32768
#define SM_TOTAL (3 * SM_STAGE)     // 98304

template<int MODE>
__global__ __launch_bounds__(256)
void gemm_f16(const __half* __restrict__ A, const __half* __restrict__ Bt,
              const float* __restrict__ bias, float* __restrict__ Cout,
              __half* __restrict__ qh, __half* __restrict__ kh,
              __half* __restrict__ vh,
              int M, int N, int K)
{
    extern __shared__ char smem[];
    const uint32_t sb = smem_to_u32(smem);

    const int tid  = threadIdx.x;
    const int wid  = tid >> 5;
    const int lane = tid & 31;
    const int rowBase = blockIdx.y * 128;
    const int colBase = blockIdx.x * 128;

    const int warp_m = wid & 1;        // 2 x 64-row halves
    const int warp_n = wid >> 1;       // 4 x 32-col quarters

    float acc[4][4][4];
#pragma unroll
    for (int i = 0; i < 4; i++)
#pragma unroll
        for (int j = 0; j < 4; j++)
#pragma unroll
            for (int r = 0; r < 4; r++) acc[i][j][r] = 0.f;

    const int a_r  = warp_m * 64 + (lane & 15);
    const int a_cb = (lane >> 4) << 4;
    const int g    = lane >> 3;
    const int b_r  = warp_n * 32 + ((g >> 1) << 3) + (lane & 7);
    const int b_cb = (g & 1) << 4;

    int ld_r[4], ld_cb[4];
    uint32_t ld_sw[4];
#pragma unroll
    for (int it = 0; it < 4; it++) {
        int idx = it * 256 + tid;
        ld_r[it]  = idx >> 3;
        ld_cb[it] = (idx & 7) << 4;
        ld_sw[it] = swz((uint32_t)(ld_r[it] * 128 + ld_cb[it]));
    }

    auto issue = [&](int ch, int st) {
        const int k0 = ch * 64;
        const uint32_t sbase = sb + st * SM_STAGE;
#pragma unroll
        for (int it = 0; it < 4; it++) {
            const int r = ld_r[it], cb = ld_cb[it];
            const uint32_t sw = ld_sw[it];
            cp16(sbase + SM_A + sw, (const char*)(A  + (size_t)(rowBase + r) * K + k0) + cb);
            cp16(sbase + SM_B + sw, (const char*)(Bt + (size_t)(colBase + r) * K + k0) + cb);
        }
        cp_commit();
    };

    const int nChunks = K / 64;
    issue(0, 0);
    issue(1, 1);

    for (int ch = 0; ch < nChunks; ch++) {
        if (ch + 1 < nChunks) cp_wait<1>(); else cp_wait<0>();
        __syncthreads();
        if (ch + 2 < nChunks) issue(ch + 2, (ch + 2) % 3);

        const uint32_t sbase = sb + (ch % 3) * SM_STAGE;
#pragma unroll
        for (int ks = 0; ks < 4; ks++) {
            const int kb = ks * 32;
            uint32_t af[4][4];
#pragma unroll
            for (int mi = 0; mi < 4; mi++) {
                uint32_t off = swz((uint32_t)((a_r + mi * 16) * 128 + kb + a_cb));
                ldsm_x4(af[mi], sbase + SM_A + off);
            }
            uint32_t bf[2][4];
#pragma unroll
            for (int nt = 0; nt < 2; nt++) {
                uint32_t off = swz((uint32_t)((b_r + nt * 16) * 128 + kb + b_cb));
                ldsm_x4(bf[nt], sbase + SM_B + off);
            }
#pragma unroll
            for (int mi = 0; mi < 4; mi++)
#pragma unroll
                for (int nj = 0; nj < 4; nj++) {
                    const uint32_t* bj = &bf[nj >> 1][(nj & 1) * 2];
                    mma16816h(acc[mi][nj], af[mi], bj[0], bj[1]);
                }
        }
    }

    const int er = rowBase + warp_m * 64 + (lane >> 2);
    const int ec = colBase + warp_n * 32 + (lane & 3) * 2;

    if (MODE == 0) {
#pragma unroll
        for (int mi = 0; mi < 4; mi++) {
#pragma unroll
            for (int nj = 0; nj < 4; nj++) {
                const int c = ec + nj * 8;
                const float bx = __ldg(bias + c);
                const float by = __ldg(bias + c + 1);
                float2 v0 = { acc[mi][nj][0] + bx, acc[mi][nj][1] + by };
                float2 v1 = { acc[mi][nj][2] + bx, acc[mi][nj][3] + by };
                *(float2*)(Cout + (size_t)(er + mi * 16) * N + c) = v0;
                *(float2*)(Cout + (size_t)(er + mi * 16 + 8) * N + c) = v1;
            }
        }
    } else {
#pragma unroll
        for (int nj = 0; nj < 4; nj++) {
            const int c   = ec + nj * 8;
            const int sec = c >> 10;             // 0=q,1=k,2=v
            const int hh  = (c & 1023) >> 6;
            const int dd  = c & 63;
            const float sc = (sec == 0) ? QS : 1.f;
            const float bx = __ldg(bias + c)     * sc;
            const float by = __ldg(bias + c + 1) * sc;
            __half* dp = (sec == 0) ? qh : (sec == 1) ? kh : vh;
#pragma unroll
            for (int mi = 0; mi < 4; mi++) {
#pragma unroll
                for (int half = 0; half < 2; half++) {
                    const int r = er + mi * 16 + half * 8;
                    const int bb = r >> 11, tt = r & 2047;
                    const size_t dst = (((size_t)bb * H_ + hh) * T_ + tt) * D_ + dd;
                    float v0 = fmaf(acc[mi][nj][half * 2],     sc, bx);
                    float v1 = fmaf(acc[mi][nj][half * 2 + 1], sc, by);
                    *(__half2*)(dp + dst) = __floats2half2_rn(v0, v1);
                }
            }
        }
    }
}

// ---------------------------------------------------------------------------
// Flash attention (R10 — revert to known-good): fp16 single-term, m=0
// softmax, 128 threads / 4 warps, 32 q-rows per warp, Q frags hoisted,
// per-warp masked-tile skip, 64-key tiles, cp.async 3-stage (16KB/stage).
// ---------------------------------------------------------------------------
#define FA_Q 0
#define FA_STAGE0 16384
#define FA_STSZ 16384
#define FA_ST(s) (FA_STAGE0 + (s) * FA_STSZ)
#define FA_K 0
#define FA_V 8192
#define FA_TOTAL (FA_STAGE0 + 3 * FA_STSZ)   // 65536

__global__ __launch_bounds__(128)
void flash_attn(const __half* __restrict__ qh, const __half* __restrict__ kh,
                const __half* __restrict__ vh, __half* __restrict__ att)
{
    extern __shared__ char smem[];
    const uint32_t sb = smem_to_u32(smem);
    const int tid = threadIdx.x, wid = tid >> 5, lane = tid & 31;
    const int h = blockIdx.y, b = blockIdx.z;
    const int qt = gridDim.x - 1 - blockIdx.x;    // big tiles first

    const size_t hoff = ((size_t)b * H_ + h) * T_ * D_;
    const char* qh_p = (const char*)(qh + hoff + (size_t)qt * 128 * D_);
    const char* kh_p = (const char*)(kh + hoff);
    const char* vh_p = (const char*)(vh + hoff);

    auto issue_kv = [&](int kt, int st) {
        const uint32_t sbase = sb + FA_ST(st);
#pragma unroll
        for (int it = 0; it < 4; it++) {
            int idx = it * 128 + tid;            // 0..511
            int r = idx >> 3, cb = (idx & 7) << 4;
            uint32_t sw = swz((uint32_t)(r * 128 + cb));
            size_t go = (size_t)(kt * 64 + r) * 128 + cb;    // bytes
            cp16(sbase + FA_K + sw, kh_p + go);
            cp16(sbase + FA_V + sw, vh_p + go);
        }
        cp_commit();
    };

    const int nkt = 2 * qt + 2;
    issue_kv(0, 0);
    issue_kv(1, 1);

    // Load Q tile into smem (plain stores), then hoist Q frags to registers.
#pragma unroll
    for (int it = 0; it < 8; it++) {
        int idx = it * 128 + tid;
        int r = idx >> 3, cb = (idx & 7) << 4;
        uint32_t sw = swz((uint32_t)(r * 128 + cb));
        *(uint4*)(smem + FA_Q + sw) = *(const uint4*)(qh_p + r * 128 + cb);
    }
    __syncthreads();

    const int a_r  = wid * 32 + (lane & 15);
    const int a_cb = (lane >> 4) << 4;
    uint32_t qf[4][2][4];                 // [ks][mi][reg], loop-invariant
#pragma unroll
    for (int ks = 0; ks < 4; ks++)
#pragma unroll
        for (int mi = 0; mi < 2; mi++) {
            uint32_t off = swz((uint32_t)((a_r + mi * 16) * 128 + ks * 32 + a_cb));
            ldsm_x4(qf[ks][mi], sb + FA_Q + off);
        }

    float o[2][8][4];
#pragma unroll
    for (int mi = 0; mi < 2; mi++)
#pragma unroll
        for (int nj = 0; nj < 8; nj++)
#pragma unroll
            for (int r = 0; r < 4; r++) o[mi][nj][r] = 0.f;
    float ls[4] = { 0.f, 0.f, 0.f, 0.f };

    const int g    = lane >> 3;
    const int b_r  = ((g >> 1) << 3) + (lane & 7);
    const int b_cb = (g & 1) << 4;
    const int vrow = ((lane >> 3) & 1) * 8 + (lane & 7);
    const int vcb  = ((lane >> 4) & 1) * 16;
    const int warpRowMax = qt * 128 + wid * 32 + 31;   // last row this warp owns

    for (int kt = 0; kt < nkt; kt++) {
        if (kt + 1 < nkt) cp_wait<1>(); else cp_wait<0>();
        __syncthreads();
        if (kt + 2 < nkt) issue_kv(kt + 2, (kt + 2) % 3);

        // Fully-masked tile for this warp? (all keys above the diagonal)
        if (kt * 64 > warpRowMax) continue;

        const uint32_t kv = sb + FA_ST(kt % 3);

        // ---- S = Q K^T (fp16 single), K frags shared across both Q frags ----
        float s[2][8][4];
#pragma unroll
        for (int mi = 0; mi < 2; mi++)
#pragma unroll
            for (int nj = 0; nj < 8; nj++)
#pragma unroll
                for (int r = 0; r < 4; r++) s[mi][nj][r] = 0.f;

#pragma unroll
        for (int ks = 0; ks < 4; ks++) {
            uint32_t kb[4][4];
#pragma unroll
            for (int nt = 0; nt < 4; nt++) {
                uint32_t off = swz((uint32_t)((b_r + nt * 16) * 128 + ks * 32 + b_cb));
                ldsm_x4(kb[nt], kv + FA_K + off);
            }
#pragma unroll
            for (int mi = 0; mi < 2; mi++)
#pragma unroll
                for (int nj = 0; nj < 8; nj++) {
                    const uint32_t* bj = &kb[nj >> 1][(nj & 1) * 2];
                    mma16816h(s[mi][nj], qf[ks][mi], bj[0], bj[1]);
                }
        }

        // ---- causal mask (diagonal tiles only) ----
        if (kt * 64 + 63 > qt * 128 + wid * 32) {
            const int colb = kt * 64 + (lane & 3) * 2;
#pragma unroll
            for (int mi = 0; mi < 2; mi++) {
                const int r0 = qt * 128 + wid * 32 + mi * 16 + (lane >> 2);
                const int r1 = r0 + 8;
#pragma unroll
                for (int nj = 0; nj < 8; nj++) {
                    const int c0 = colb + nj * 8, c1 = c0 + 1;
                    if (c0 > r0) s[mi][nj][0] = -1e30f;
                    if (c1 > r0) s[mi][nj][1] = -1e30f;
                    if (c0 > r1) s[mi][nj][2] = -1e30f;
                    if (c1 > r1) s[mi][nj][3] = -1e30f;
                }
            }
        }

        // ---- p = 2^s (no max), accumulate l, pack P fp16 ----
        uint32_t ph[2][4][4];
#pragma unroll
        for (int mi = 0; mi < 2; mi++) {
#pragma unroll
            for (int nj = 0; nj < 8; nj++) {
                float p0 = ex2(s[mi][nj][0]);
                float p1 = ex2(s[mi][nj][1]);
                float p2 = ex2(s[mi][nj][2]);
                float p3 = ex2(s[mi][nj][3]);
                s[mi][nj][0] = p0; s[mi][nj][1] = p1;
                s[mi][nj][2] = p2; s[mi][nj][3] = p3;
                ls[mi * 2 + 0] += p0 + p1;
                ls[mi * 2 + 1] += p2 + p3;
            }
#pragma unroll
            for (int ks = 0; ks < 4; ks++) {
#pragma unroll
                for (int rr = 0; rr < 4; rr++) {
                    const int nj = 2 * ks + (rr >> 1);
                    const int r0 = (rr & 1) * 2;
                    __half2 hh = __floats2half2_rn(s[mi][nj][r0], s[mi][nj][r0 + 1]);
                    ph[mi][ks][rr] = *(uint32_t*)&hh;
                }
            }
        }

        // ---- O += P V (fp16), V frags shared across both row-halves ----
#pragma unroll
        for (int ks = 0; ks < 4; ks++) {
#pragma unroll
            for (int nd = 0; nd < 4; nd++) {
                uint32_t vf[4];
                uint32_t off = swz((uint32_t)((ks * 16 + vrow) * 128 + nd * 32 + vcb));
                ldsm_x4_t(vf, kv + FA_V + off);
#pragma unroll
                for (int mi = 0; mi < 2; mi++) {
                    mma16816h(o[mi][nd * 2],     ph[mi][ks], vf[0], vf[1]);
                    mma16816h(o[mi][nd * 2 + 1], ph[mi][ks], vf[2], vf[3]);
                }
            }
        }
    }

    // ---- epilogue: reduce l across quad lanes, O / l -> fp16 att ----
    float inv[4];
#pragma unroll
    for (int si = 0; si < 4; si++) {
        float l = ls[si];
        l += __shfl_xor_sync(0xffffffffu, l, 1);
        l += __shfl_xor_sync(0xffffffffu, l, 2);
        inv[si] = 1.f / l;
    }
    const int ecb = h * 64 + (lane & 3) * 2;
#pragma unroll
    for (int mi = 0; mi < 2; mi++) {
        const int er0 = qt * 128 + wid * 32 + mi * 16 + (lane >> 2);
        const size_t row = (size_t)b * T_ + er0;
#pragma unroll
        for (int nj = 0; nj < 8; nj++) {
            *(__half2*)(att + row * C_ + ecb + nj * 8) =
                __floats2half2_rn(o[mi][nj][0] * inv[mi * 2],
                                  o[mi][nj][1] * inv[mi * 2]);
            *(__half2*)(att + (row + 8) * C_ + ecb + nj * 8) =
                __floats2half2_rn(o[mi][nj][2] * inv[mi * 2 + 1],
                                  o[mi][nj][3] * inv[mi * 2 + 1]);
        }
    }
}

// ---------------------------------------------------------------------------
// Launch sequence
// ---------------------------------------------------------------------------
extern "C" void kernel_launch(void* const* d_in, const int* in_sizes, int n_in,
                              void* d_out, int out_size)
{
    const float* x      = (const float*)d_in[0];
    const float* w_qkv  = (const float*)d_in[1];
    const float* b_qkv  = (const float*)d_in[2];
    const float* w_proj = (const float*)d_in[3];
    const float* b_proj = (const float*)d_in[4];
    float* out = (float*)d_out;

    __half *xh, *wt, *qh, *kh, *vh;
    cudaGetSymbolAddress((void**)&xh, g_xh);
    cudaGetSymbolAddress((void**)&wt, g_wt);
    cudaGetSymbolAddress((void**)&qh, g_qh);
    cudaGetSymbolAddress((void**)&kh, g_kh);
    cudaGetSymbolAddress((void**)&vh, g_vh);

    cudaFuncSetAttribute(gemm_f16<0>, cudaFuncAttributeMaxDynamicSharedMemorySize, SM_TOTAL);
    cudaFuncSetAttribute(gemm_f16<1>, cudaFuncAttributeMaxDynamicSharedMemorySize, SM_TOTAL);
    cudaFuncSetAttribute(flash_attn, cudaFuncAttributeMaxDynamicSharedMemorySize, FA_TOTAL);

    // 1) x -> fp16
    {
        int n4 = (M_ROWS * C_) / 4;
        cvt_f16<<<(n4 + 255) / 256, 256>>>(x, xh, n4);
    }
    // 2) transpose+cvt w_qkv -> [N,K] fp16
    {
        dim3 grid(N_QKV / 32, C_ / 32);
        wt_cvt<<<grid, 256>>>(w_qkv, wt, C_, N_QKV);
    }
    // 3) QKV GEMM -> per-head q (scaled)/k/v fp16
    {
        dim3 grid(N_QKV / 128, M_ROWS / 128);
        gemm_f16<1><<<grid, 256, SM_TOTAL>>>(xh, wt, b_qkv, nullptr,
                                             qh, kh, vh, M_ROWS, N_QKV, C_);
    }
    // 4) flash attention -> fp16 att (reuses xh)
    {
        dim3 grid(T_ / 128, H_, B_);
        flash_attn<<<grid, 128, FA_TOTAL>>>(qh, kh, vh, xh);
    }
    // 5) transpose+cvt w_proj
    {
        dim3 grid(C_ / 32, C_ / 32);
        wt_cvt<<<grid, 256>>>(w_proj, wt, C_, C_);
    }
    // 6) proj GEMM -> fp32 out
    {
        dim3 grid(C_ / 128, M_ROWS / 128);
        gemm_f16<0><<<grid, 256, SM_TOTAL>>>(xh, wt, b_proj, out,
                                             nullptr, nullptr, nullptr,
                                             M_ROWS, C_, C_);
    }
}

// round 13
// speedup vs baseline: 8.4345x; 1.0116x over previous
#include <cuda_runtime.h>
#include <cuda_bf16.h>
#include <cuda_fp16.h>
#include <cstdint>

// ---------------------------------------------------------------------------
// Problem constants
// ---------------------------------------------------------------------------
#define B_ 2
#define T_ 2048
#define C_ 1024
#define H_ 16
#define D_ 64
#define M_ROWS (B_ * T_)     // 4096
#define N_QKV  (3 * C_)      // 3072

// softmax scale * log2(e) folded into Q: (1/8) * 1.4426950408889634
#define QS 0.18033688011112042f

// Scratch (__device__ globals; allocation-free rule)
__device__ __half g_xh[(size_t)M_ROWS * C_];        // activations fp16 (x, then att)
__device__ __half g_wt[(size_t)N_QKV * C_];         // W_qkv^T fp16 [N,K]
__device__ __half g_wt2[(size_t)C_ * C_];           // W_proj^T fp16 [N,K]
// per-head fp16 [B,H,T,D]
__device__ __half g_qh[(size_t)B_ * H_ * T_ * D_];  // q (pre-scaled by QS)
__device__ __half g_kh[(size_t)B_ * H_ * T_ * D_];
__device__ __half g_vh[(size_t)B_ * H_ * T_ * D_];

// ---------------------------------------------------------------------------
// Warp MMA / async-copy helpers (sm_80+ baseline)
// ---------------------------------------------------------------------------
__device__ __forceinline__ uint32_t smem_to_u32(const void* p) {
    uint32_t a;
    asm("{ .reg .u64 t; cvta.to.shared.u64 t, %1; cvt.u32.u64 %0, t; }"
        : "=r"(a) : "l"(p));
    return a;
}
__device__ __forceinline__ void ldsm_x4(uint32_t (&r)[4], uint32_t addr) {
    asm volatile("ldmatrix.sync.aligned.m8n8.x4.shared.b16 {%0,%1,%2,%3}, [%4];"
                 : "=r"(r[0]), "=r"(r[1]), "=r"(r[2]), "=r"(r[3]) : "r"(addr));
}
__device__ __forceinline__ void ldsm_x4_t(uint32_t (&r)[4], uint32_t addr) {
    asm volatile("ldmatrix.sync.aligned.m8n8.x4.trans.shared.b16 {%0,%1,%2,%3}, [%4];"
                 : "=r"(r[0]), "=r"(r[1]), "=r"(r[2]), "=r"(r[3]) : "r"(addr));
}
__device__ __forceinline__ void mma16816h(float (&d)[4],
                                          const uint32_t (&a)[4],
                                          const uint32_t b0, const uint32_t b1) {
    asm volatile(
        "mma.sync.aligned.m16n8k16.row.col.f32.f16.f16.f32 "
        "{%0,%1,%2,%3}, {%4,%5,%6,%7}, {%8,%9}, {%0,%1,%2,%3};"
        : "+f"(d[0]), "+f"(d[1]), "+f"(d[2]), "+f"(d[3])
        : "r"(a[0]), "r"(a[1]), "r"(a[2]), "r"(a[3]), "r"(b0), "r"(b1));
}
__device__ __forceinline__ uint32_t swz(uint32_t off) {
    return off ^ ((off >> 3) & 0x70);
}
__device__ __forceinline__ float ex2(float x) {
    float y; asm("ex2.approx.ftz.f32 %0, %1;" : "=f"(y) : "f"(x)); return y;
}
__device__ __forceinline__ void cp16(uint32_t dst, const void* src) {
    asm volatile("cp.async.ca.shared.global [%0], [%1], 16;" :: "r"(dst), "l"(src));
}
__device__ __forceinline__ void cp_commit() {
    asm volatile("cp.async.commit_group;" ::: "memory");
}
template<int N> __device__ __forceinline__ void cp_wait() {
    asm volatile("cp.async.wait_group %0;" :: "n"(N) : "memory");
}

// ---------------------------------------------------------------------------
// Fused prepass: ONE kernel does
//   blocks [0, 4096)        : x fp32 -> fp16 (4 elems/thread)
//   blocks [4096, 7168)     : w_qkv [1024,3072] -> W^T fp16 [3072,1024] (32x32)
//   blocks [7168, 8192)     : w_proj [1024,1024] -> W^T fp16 [1024,1024] (32x32)
// ---------------------------------------------------------------------------
#define PRE_XBLOCKS   4096
#define PRE_QKVBLOCKS 3072   // (3072/32) * (1024/32)
#define PRE_PROJBLOCKS 1024  // (1024/32) * (1024/32)
#define PRE_TOTAL (PRE_XBLOCKS + PRE_QKVBLOCKS + PRE_PROJBLOCKS)

__global__ __launch_bounds__(256)
void prepass(const float* __restrict__ x,
             const float* __restrict__ w_qkv, const float* __restrict__ w_proj,
             __half* __restrict__ xh,
             __half* __restrict__ wt_qkv, __half* __restrict__ wt_proj)
{
    const int bid = blockIdx.x;

    if (bid < PRE_XBLOCKS) {
        int i = bid * 256 + threadIdx.x;         // n4 = 4096*1024/4 = 1048576
        float4 v = ((const float4*)x)[i];
        ((__half2*)xh)[i * 2 + 0] = __floats2half2_rn(v.x, v.y);
        ((__half2*)xh)[i * 2 + 1] = __floats2half2_rn(v.z, v.w);
        return;
    }

    // Weight transpose job
    const float* W;
    __half* Wt;
    int N, tileIdx;
    if (bid < PRE_XBLOCKS + PRE_QKVBLOCKS) {
        W = w_qkv; Wt = wt_qkv; N = N_QKV;
        tileIdx = bid - PRE_XBLOCKS;
    } else {
        W = w_proj; Wt = wt_proj; N = C_;
        tileIdx = bid - PRE_XBLOCKS - PRE_QKVBLOCKS;
    }
    const int ntilesN = N / 32;
    const int n0 = (tileIdx % ntilesN) * 32;
    const int k0 = (tileIdx / ntilesN) * 32;     // K = 1024 always

    __shared__ float tile[32][33];
    const int tx = threadIdx.x & 31;
    const int ty = threadIdx.x >> 5;
#pragma unroll
    for (int r = ty; r < 32; r += 8)
        tile[r][tx] = W[(size_t)(k0 + r) * N + n0 + tx];
    __syncthreads();
#pragma unroll
    for (int r = ty; r < 32; r += 8)
        Wt[(size_t)(n0 + r) * C_ + k0 + tx] = __float2half_rn(tile[tx][r]);
}

// ---------------------------------------------------------------------------
// HMMA GEMM fp16 single-term, 256 threads / 8 warps, warp tile 64x32
// (6 LDSM : 16 MMA per ks). cp.async 3-stage, 2 CTAs/SM.
// MODE 0: fp32 C + bias.  MODE 1: per-head q(scaled)/k/v scatter.
// ---------------------------------------------------------------------------
#define SM_A  0
#define SM_B  16384
#define SM_STAGE 32768
#define SM_TOTAL (3 * SM_STAGE)     // 98304

template<int MODE>
__global__ __launch_bounds__(256)
void gemm_f16(const __half* __restrict__ A, const __half* __restrict__ Bt,
              const float* __restrict__ bias, float* __restrict__ Cout,
              __half* __restrict__ qh, __half* __restrict__ kh,
              __half* __restrict__ vh,
              int M, int N, int K)
{
    extern __shared__ char smem[];
    const uint32_t sb = smem_to_u32(smem);

    const int tid  = threadIdx.x;
    const int wid  = tid >> 5;
    const int lane = tid & 31;
    const int rowBase = blockIdx.y * 128;
    const int colBase = blockIdx.x * 128;

    const int warp_m = wid & 1;        // 2 x 64-row halves
    const int warp_n = wid >> 1;       // 4 x 32-col quarters

    float acc[4][4][4];
#pragma unroll
    for (int i = 0; i < 4; i++)
#pragma unroll
        for (int j = 0; j < 4; j++)
#pragma unroll
            for (int r = 0; r < 4; r++) acc[i][j][r] = 0.f;

    const int a_r  = warp_m * 64 + (lane & 15);
    const int a_cb = (lane >> 4) << 4;
    const int g    = lane >> 3;
    const int b_r  = warp_n * 32 + ((g >> 1) << 3) + (lane & 7);
    const int b_cb = (g & 1) << 4;

    int ld_r[4], ld_cb[4];
    uint32_t ld_sw[4];
#pragma unroll
    for (int it = 0; it < 4; it++) {
        int idx = it * 256 + tid;
        ld_r[it]  = idx >> 3;
        ld_cb[it] = (idx & 7) << 4;
        ld_sw[it] = swz((uint32_t)(ld_r[it] * 128 + ld_cb[it]));
    }

    auto issue = [&](int ch, int st) {
        const int k0 = ch * 64;
        const uint32_t sbase = sb + st * SM_STAGE;
#pragma unroll
        for (int it = 0; it < 4; it++) {
            const int r = ld_r[it], cb = ld_cb[it];
            const uint32_t sw = ld_sw[it];
            cp16(sbase + SM_A + sw, (const char*)(A  + (size_t)(rowBase + r) * K + k0) + cb);
            cp16(sbase + SM_B + sw, (const char*)(Bt + (size_t)(colBase + r) * K + k0) + cb);
        }
        cp_commit();
    };

    const int nChunks = K / 64;
    issue(0, 0);
    issue(1, 1);

    for (int ch = 0; ch < nChunks; ch++) {
        if (ch + 1 < nChunks) cp_wait<1>(); else cp_wait<0>();
        __syncthreads();
        if (ch + 2 < nChunks) issue(ch + 2, (ch + 2) % 3);

        const uint32_t sbase = sb + (ch % 3) * SM_STAGE;
#pragma unroll
        for (int ks = 0; ks < 4; ks++) {
            const int kb = ks * 32;
            uint32_t af[4][4];
#pragma unroll
            for (int mi = 0; mi < 4; mi++) {
                uint32_t off = swz((uint32_t)((a_r + mi * 16) * 128 + kb + a_cb));
                ldsm_x4(af[mi], sbase + SM_A + off);
            }
            uint32_t bf[2][4];
#pragma unroll
            for (int nt = 0; nt < 2; nt++) {
                uint32_t off = swz((uint32_t)((b_r + nt * 16) * 128 + kb + b_cb));
                ldsm_x4(bf[nt], sbase + SM_B + off);
            }
#pragma unroll
            for (int mi = 0; mi < 4; mi++)
#pragma unroll
                for (int nj = 0; nj < 4; nj++) {
                    const uint32_t* bj = &bf[nj >> 1][(nj & 1) * 2];
                    mma16816h(acc[mi][nj], af[mi], bj[0], bj[1]);
                }
        }
    }

    const int er = rowBase + warp_m * 64 + (lane >> 2);
    const int ec = colBase + warp_n * 32 + (lane & 3) * 2;

    if (MODE == 0) {
#pragma unroll
        for (int mi = 0; mi < 4; mi++) {
#pragma unroll
            for (int nj = 0; nj < 4; nj++) {
                const int c = ec + nj * 8;
                const float bx = __ldg(bias + c);
                const float by = __ldg(bias + c + 1);
                float2 v0 = { acc[mi][nj][0] + bx, acc[mi][nj][1] + by };
                float2 v1 = { acc[mi][nj][2] + bx, acc[mi][nj][3] + by };
                *(float2*)(Cout + (size_t)(er + mi * 16) * N + c) = v0;
                *(float2*)(Cout + (size_t)(er + mi * 16 + 8) * N + c) = v1;
            }
        }
    } else {
#pragma unroll
        for (int nj = 0; nj < 4; nj++) {
            const int c   = ec + nj * 8;
            const int sec = c >> 10;             // 0=q,1=k,2=v
            const int hh  = (c & 1023) >> 6;
            const int dd  = c & 63;
            const float sc = (sec == 0) ? QS : 1.f;
            const float bx = __ldg(bias + c)     * sc;
            const float by = __ldg(bias + c + 1) * sc;
            __half* dp = (sec == 0) ? qh : (sec == 1) ? kh : vh;
#pragma unroll
            for (int mi = 0; mi < 4; mi++) {
#pragma unroll
                for (int half = 0; half < 2; half++) {
                    const int r = er + mi * 16 + half * 8;
                    const int bb = r >> 11, tt = r & 2047;
                    const size_t dst = (((size_t)bb * H_ + hh) * T_ + tt) * D_ + dd;
                    float v0 = fmaf(acc[mi][nj][half * 2],     sc, bx);
                    float v1 = fmaf(acc[mi][nj][half * 2 + 1], sc, by);
                    *(__half2*)(dp + dst) = __floats2half2_rn(v0, v1);
                }
            }
        }
    }
}

// ---------------------------------------------------------------------------
// Flash attention (known-good R10/R12): fp16 single-term, m=0 softmax,
// 128 threads / 4 warps, 32 q-rows per warp, Q frags hoisted, per-warp
// masked-tile skip, 64-key tiles, cp.async 3-stage (16KB/stage).
// ---------------------------------------------------------------------------
#define FA_Q 0
#define FA_STAGE0 16384
#define FA_STSZ 16384
#define FA_ST(s) (FA_STAGE0 + (s) * FA_STSZ)
#define FA_K 0
#define FA_V 8192
#define FA_TOTAL (FA_STAGE0 + 3 * FA_STSZ)   // 65536

__global__ __launch_bounds__(128)
void flash_attn(const __half* __restrict__ qh, const __half* __restrict__ kh,
                const __half* __restrict__ vh, __half* __restrict__ att)
{
    extern __shared__ char smem[];
    const uint32_t sb = smem_to_u32(smem);
    const int tid = threadIdx.x, wid = tid >> 5, lane = tid & 31;
    const int h = blockIdx.y, b = blockIdx.z;
    const int qt = gridDim.x - 1 - blockIdx.x;    // big tiles first

    const size_t hoff = ((size_t)b * H_ + h) * T_ * D_;
    const char* qh_p = (const char*)(qh + hoff + (size_t)qt * 128 * D_);
    const char* kh_p = (const char*)(kh + hoff);
    const char* vh_p = (const char*)(vh + hoff);

    auto issue_kv = [&](int kt, int st) {
        const uint32_t sbase = sb + FA_ST(st);
#pragma unroll
        for (int it = 0; it < 4; it++) {
            int idx = it * 128 + tid;            // 0..511
            int r = idx >> 3, cb = (idx & 7) << 4;
            uint32_t sw = swz((uint32_t)(r * 128 + cb));
            size_t go = (size_t)(kt * 64 + r) * 128 + cb;    // bytes
            cp16(sbase + FA_K + sw, kh_p + go);
            cp16(sbase + FA_V + sw, vh_p + go);
        }
        cp_commit();
    };

    const int nkt = 2 * qt + 2;
    issue_kv(0, 0);
    issue_kv(1, 1);

    // Load Q tile into smem (plain stores), then hoist Q frags to registers.
#pragma unroll
    for (int it = 0; it < 8; it++) {
        int idx = it * 128 + tid;
        int r = idx >> 3, cb = (idx & 7) << 4;
        uint32_t sw = swz((uint32_t)(r * 128 + cb));
        *(uint4*)(smem + FA_Q + sw) = *(const uint4*)(qh_p + r * 128 + cb);
    }
    __syncthreads();

    const int a_r  = wid * 32 + (lane & 15);
    const int a_cb = (lane >> 4) << 4;
    uint32_t qf[4][2][4];                 // [ks][mi][reg], loop-invariant
#pragma unroll
    for (int ks = 0; ks < 4; ks++)
#pragma unroll
        for (int mi = 0; mi < 2; mi++) {
            uint32_t off = swz((uint32_t)((a_r + mi * 16) * 128 + ks * 32 + a_cb));
            ldsm_x4(qf[ks][mi], sb + FA_Q + off);
        }

    float o[2][8][4];
#pragma unroll
    for (int mi = 0; mi < 2; mi++)
#pragma unroll
        for (int nj = 0; nj < 8; nj++)
#pragma unroll
            for (int r = 0; r < 4; r++) o[mi][nj][r] = 0.f;
    float ls[4] = { 0.f, 0.f, 0.f, 0.f };

    const int g    = lane >> 3;
    const int b_r  = ((g >> 1) << 3) + (lane & 7);
    const int b_cb = (g & 1) << 4;
    const int vrow = ((lane >> 3) & 1) * 8 + (lane & 7);
    const int vcb  = ((lane >> 4) & 1) * 16;
    const int warpRowMax = qt * 128 + wid * 32 + 31;   // last row this warp owns

    for (int kt = 0; kt < nkt; kt++) {
        if (kt + 1 < nkt) cp_wait<1>(); else cp_wait<0>();
        __syncthreads();
        if (kt + 2 < nkt) issue_kv(kt + 2, (kt + 2) % 3);

        // Fully-masked tile for this warp? (all keys above the diagonal)
        if (kt * 64 > warpRowMax) continue;

        const uint32_t kv = sb + FA_ST(kt % 3);

        // ---- S = Q K^T (fp16 single), K frags shared across both Q frags ----
        float s[2][8][4];
#pragma unroll
        for (int mi = 0; mi < 2; mi++)
#pragma unroll
            for (int nj = 0; nj < 8; nj++)
#pragma unroll
                for (int r = 0; r < 4; r++) s[mi][nj][r] = 0.f;

#pragma unroll
        for (int ks = 0; ks < 4; ks++) {
            uint32_t kb[4][4];
#pragma unroll
            for (int nt = 0; nt < 4; nt++) {
                uint32_t off = swz((uint32_t)((b_r + nt * 16) * 128 + ks * 32 + b_cb));
                ldsm_x4(kb[nt], kv + FA_K + off);
            }
#pragma unroll
            for (int mi = 0; mi < 2; mi++)
#pragma unroll
                for (int nj = 0; nj < 8; nj++) {
                    const uint32_t* bj = &kb[nj >> 1][(nj & 1) * 2];
                    mma16816h(s[mi][nj], qf[ks][mi], bj[0], bj[1]);
                }
        }

        // ---- causal mask (diagonal tiles only) ----
        if (kt * 64 + 63 > qt * 128 + wid * 32) {
            const int colb = kt * 64 + (lane & 3) * 2;
#pragma unroll
            for (int mi = 0; mi < 2; mi++) {
                const int r0 = qt * 128 + wid * 32 + mi * 16 + (lane >> 2);
                const int r1 = r0 + 8;
#pragma unroll
                for (int nj = 0; nj < 8; nj++) {
                    const int c0 = colb + nj * 8, c1 = c0 + 1;
                    if (c0 > r0) s[mi][nj][0] = -1e30f;
                    if (c1 > r0) s[mi][nj][1] = -1e30f;
                    if (c0 > r1) s[mi][nj][2] = -1e30f;
                    if (c1 > r1) s[mi][nj][3] = -1e30f;
                }
            }
        }

        // ---- p = 2^s (no max), accumulate l, pack P fp16 ----
        uint32_t ph[2][4][4];
#pragma unroll
        for (int mi = 0; mi < 2; mi++) {
#pragma unroll
            for (int nj = 0; nj < 8; nj++) {
                float p0 = ex2(s[mi][nj][0]);
                float p1 = ex2(s[mi][nj][1]);
                float p2 = ex2(s[mi][nj][2]);
                float p3 = ex2(s[mi][nj][3]);
                s[mi][nj][0] = p0; s[mi][nj][1] = p1;
                s[mi][nj][2] = p2; s[mi][nj][3] = p3;
                ls[mi * 2 + 0] += p0 + p1;
                ls[mi * 2 + 1] += p2 + p3;
            }
#pragma unroll
            for (int ks = 0; ks < 4; ks++) {
#pragma unroll
                for (int rr = 0; rr < 4; rr++) {
                    const int nj = 2 * ks + (rr >> 1);
                    const int r0 = (rr & 1) * 2;
                    __half2 hh = __floats2half2_rn(s[mi][nj][r0], s[mi][nj][r0 + 1]);
                    ph[mi][ks][rr] = *(uint32_t*)&hh;
                }
            }
        }

        // ---- O += P V (fp16), V frags shared across both row-halves ----
#pragma unroll
        for (int ks = 0; ks < 4; ks++) {
#pragma unroll
            for (int nd = 0; nd < 4; nd++) {
                uint32_t vf[4];
                uint32_t off = swz((uint32_t)((ks * 16 + vrow) * 128 + nd * 32 + vcb));
                ldsm_x4_t(vf, kv + FA_V + off);
#pragma unroll
                for (int mi = 0; mi < 2; mi++) {
                    mma16816h(o[mi][nd * 2],     ph[mi][ks], vf[0], vf[1]);
                    mma16816h(o[mi][nd * 2 + 1], ph[mi][ks], vf[2], vf[3]);
                }
            }
        }
    }

    // ---- epilogue: reduce l across quad lanes, O / l -> fp16 att ----
    float inv[4];
#pragma unroll
    for (int si = 0; si < 4; si++) {
        float l = ls[si];
        l += __shfl_xor_sync(0xffffffffu, l, 1);
        l += __shfl_xor_sync(0xffffffffu, l, 2);
        inv[si] = 1.f / l;
    }
    const int ecb = h * 64 + (lane & 3) * 2;
#pragma unroll
    for (int mi = 0; mi < 2; mi++) {
        const int er0 = qt * 128 + wid * 32 + mi * 16 + (lane >> 2);
        const size_t row = (size_t)b * T_ + er0;
#pragma unroll
        for (int nj = 0; nj < 8; nj++) {
            *(__half2*)(att + row * C_ + ecb + nj * 8) =
                __floats2half2_rn(o[mi][nj][0] * inv[mi * 2],
                                  o[mi][nj][1] * inv[mi * 2]);
            *(__half2*)(att + (row + 8) * C_ + ecb + nj * 8) =
                __floats2half2_rn(o[mi][nj][2] * inv[mi * 2 + 1],
                                  o[mi][nj][3] * inv[mi * 2 + 1]);
        }
    }
}

// ---------------------------------------------------------------------------
// Launch sequence: prepass -> QKV GEMM -> flash -> proj GEMM
// ---------------------------------------------------------------------------
extern "C" void kernel_launch(void* const* d_in, const int* in_sizes, int n_in,
                              void* d_out, int out_size)
{
    const float* x      = (const float*)d_in[0];
    const float* w_qkv  = (const float*)d_in[1];
    const float* b_qkv  = (const float*)d_in[2];
    const float* w_proj = (const float*)d_in[3];
    const float* b_proj = (const float*)d_in[4];
    float* out = (float*)d_out;

    __half *xh, *wt, *wt2, *qh, *kh, *vh;
    cudaGetSymbolAddress((void**)&xh, g_xh);
    cudaGetSymbolAddress((void**)&wt, g_wt);
    cudaGetSymbolAddress((void**)&wt2, g_wt2);
    cudaGetSymbolAddress((void**)&qh, g_qh);
    cudaGetSymbolAddress((void**)&kh, g_kh);
    cudaGetSymbolAddress((void**)&vh, g_vh);

    cudaFuncSetAttribute(gemm_f16<0>, cudaFuncAttributeMaxDynamicSharedMemorySize, SM_TOTAL);
    cudaFuncSetAttribute(gemm_f16<1>, cudaFuncAttributeMaxDynamicSharedMemorySize, SM_TOTAL);
    cudaFuncSetAttribute(flash_attn, cudaFuncAttributeMaxDynamicSharedMemorySize, FA_TOTAL);

    // 1) fused prepass: x->fp16, w_qkv->W^T fp16, w_proj->W^T fp16
    prepass<<<PRE_TOTAL, 256>>>(x, w_qkv, w_proj, xh, wt, wt2);

    // 2) QKV GEMM -> per-head q (scaled)/k/v fp16
    {
        dim3 grid(N_QKV / 128, M_ROWS / 128);
        gemm_f16<1><<<grid, 256, SM_TOTAL>>>(xh, wt, b_qkv, nullptr,
                                             qh, kh, vh, M_ROWS, N_QKV, C_);
    }
    // 3) flash attention -> fp16 att (reuses xh)
    {
        dim3 grid(T_ / 128, H_, B_);
        flash_attn<<<grid, 128, FA_TOTAL>>>(qh, kh, vh, xh);
    }
    // 4) proj GEMM -> fp32 out
    {
        dim3 grid(C_ / 128, M_ROWS / 128);
        gemm_f16<0><<<grid, 256, SM_TOTAL>>>(xh, wt2, b_proj, out,
                                             nullptr, nullptr, nullptr,
                                             M_ROWS, C_, C_);
    }
}

// round 14
// speedup vs baseline: 9.1302x; 1.0825x over previous
#include <cuda_runtime.h>
#include <cuda_bf16.h>
#include <cuda_fp16.h>
#include <cstdint>

// ---------------------------------------------------------------------------
// Problem constants
// ---------------------------------------------------------------------------
#define B_ 2
#define T_ 2048
#define C_ 1024
#define H_ 16
#define D_ 64
#define M_ROWS (B_ * T_)     // 4096
#define N_QKV  (3 * C_)      // 3072

// softmax scale * log2(e) folded into Q: (1/8) * 1.4426950408889634
#define QS 0.18033688011112042f

// Scratch (__device__ globals; allocation-free rule)
__device__ __half g_xh[(size_t)M_ROWS * C_];        // activations fp16 (x, then att)
__device__ __half g_wt[(size_t)N_QKV * C_];         // W_qkv^T fp16 [N,K]
__device__ __half g_wt2[(size_t)C_ * C_];           // W_proj^T fp16 [N,K]
// per-head fp16 [B,H,T,D]
__device__ __half g_qh[(size_t)B_ * H_ * T_ * D_];  // q (pre-scaled by QS)
__device__ __half g_kh[(size_t)B_ * H_ * T_ * D_];
__device__ __half g_vh[(size_t)B_ * H_ * T_ * D_];

// ---------------------------------------------------------------------------
// Warp MMA / async-copy helpers (sm_80+ baseline)
// ---------------------------------------------------------------------------
__device__ __forceinline__ uint32_t smem_to_u32(const void* p) {
    uint32_t a;
    asm("{ .reg .u64 t; cvta.to.shared.u64 t, %1; cvt.u32.u64 %0, t; }"
        : "=r"(a) : "l"(p));
    return a;
}
__device__ __forceinline__ void ldsm_x4(uint32_t (&r)[4], uint32_t addr) {
    asm volatile("ldmatrix.sync.aligned.m8n8.x4.shared.b16 {%0,%1,%2,%3}, [%4];"
                 : "=r"(r[0]), "=r"(r[1]), "=r"(r[2]), "=r"(r[3]) : "r"(addr));
}
__device__ __forceinline__ void ldsm_x4_t(uint32_t (&r)[4], uint32_t addr) {
    asm volatile("ldmatrix.sync.aligned.m8n8.x4.trans.shared.b16 {%0,%1,%2,%3}, [%4];"
                 : "=r"(r[0]), "=r"(r[1]), "=r"(r[2]), "=r"(r[3]) : "r"(addr));
}
__device__ __forceinline__ void mma16816h(float (&d)[4],
                                          const uint32_t (&a)[4],
                                          const uint32_t b0, const uint32_t b1) {
    asm volatile(
        "mma.sync.aligned.m16n8k16.row.col.f32.f16.f16.f32 "
        "{%0,%1,%2,%3}, {%4,%5,%6,%7}, {%8,%9}, {%0,%1,%2,%3};"
        : "+f"(d[0]), "+f"(d[1]), "+f"(d[2]), "+f"(d[3])
        : "r"(a[0]), "r"(a[1]), "r"(a[2]), "r"(a[3]), "r"(b0), "r"(b1));
}
__device__ __forceinline__ uint32_t swz(uint32_t off) {
    return off ^ ((off >> 3) & 0x70);
}
__device__ __forceinline__ float ex2(float x) {
    float y; asm("ex2.approx.ftz.f32 %0, %1;" : "=f"(y) : "f"(x)); return y;
}
__device__ __forceinline__ void cp16(uint32_t dst, const void* src) {
    asm volatile("cp.async.ca.shared.global [%0], [%1], 16;" :: "r"(dst), "l"(src));
}
__device__ __forceinline__ void cp_commit() {
    asm volatile("cp.async.commit_group;" ::: "memory");
}
template<int N> __device__ __forceinline__ void cp_wait() {
    asm volatile("cp.async.wait_group %0;" :: "n"(N) : "memory");
}

// ---------------------------------------------------------------------------
// Fused prepass (R13): x->fp16, w_qkv->W^T, w_proj->W^T in one kernel.
// ---------------------------------------------------------------------------
#define PRE_XBLOCKS   4096
#define PRE_QKVBLOCKS 3072
#define PRE_PROJBLOCKS 1024
#define PRE_TOTAL (PRE_XBLOCKS + PRE_QKVBLOCKS + PRE_PROJBLOCKS)

__global__ __launch_bounds__(256)
void prepass(const float* __restrict__ x,
             const float* __restrict__ w_qkv, const float* __restrict__ w_proj,
             __half* __restrict__ xh,
             __half* __restrict__ wt_qkv, __half* __restrict__ wt_proj)
{
    const int bid = blockIdx.x;

    if (bid < PRE_XBLOCKS) {
        int i = bid * 256 + threadIdx.x;
        float4 v = ((const float4*)x)[i];
        ((__half2*)xh)[i * 2 + 0] = __floats2half2_rn(v.x, v.y);
        ((__half2*)xh)[i * 2 + 1] = __floats2half2_rn(v.z, v.w);
        return;
    }

    const float* W;
    __half* Wt;
    int N, tileIdx;
    if (bid < PRE_XBLOCKS + PRE_QKVBLOCKS) {
        W = w_qkv; Wt = wt_qkv; N = N_QKV;
        tileIdx = bid - PRE_XBLOCKS;
    } else {
        W = w_proj; Wt = wt_proj; N = C_;
        tileIdx = bid - PRE_XBLOCKS - PRE_QKVBLOCKS;
    }
    const int ntilesN = N / 32;
    const int n0 = (tileIdx % ntilesN) * 32;
    const int k0 = (tileIdx / ntilesN) * 32;

    __shared__ float tile[32][33];
    const int tx = threadIdx.x & 31;
    const int ty = threadIdx.x >> 5;
#pragma unroll
    for (int r = ty; r < 32; r += 8)
        tile[r][tx] = W[(size_t)(k0 + r) * N + n0 + tx];
    __syncthreads();
#pragma unroll
    for (int r = ty; r < 32; r += 8)
        Wt[(size_t)(n0 + r) * C_ + k0 + tx] = __float2half_rn(tile[tx][r]);
}

// ---------------------------------------------------------------------------
// HMMA GEMM fp16 single-term, 256 threads / 8 warps, warp tile 64x32.
// __launch_bounds__(256, 2): cap regs at 128 -> 2 CTAs/SM (RF was the limiter
// at 156 regs; smem 96KB x2 = 192KB fits the 227KB carveout).
// MODE 0: fp32 C + bias.  MODE 1: per-head q(scaled)/k/v scatter.
// ---------------------------------------------------------------------------
#define SM_A  0
#define SM_B  16384
#define SM_STAGE 32768
#define SM_TOTAL (3 * SM_STAGE)     // 98304

template<int MODE>
__global__ __launch_bounds__(256, 2)
void gemm_f16(const __half* __restrict__ A, const __half* __restrict__ Bt,
              const float* __restrict__ bias, float* __restrict__ Cout,
              __half* __restrict__ qh, __half* __restrict__ kh,
              __half* __restrict__ vh,
              int M, int N, int K)
{
    extern __shared__ char smem[];
    const uint32_t sb = smem_to_u32(smem);

    const int tid  = threadIdx.x;
    const int wid  = tid >> 5;
    const int lane = tid & 31;
    const int rowBase = blockIdx.y * 128;
    const int colBase = blockIdx.x * 128;

    const int warp_m = wid & 1;        // 2 x 64-row halves
    const int warp_n = wid >> 1;       // 4 x 32-col quarters

    float acc[4][4][4];
#pragma unroll
    for (int i = 0; i < 4; i++)
#pragma unroll
        for (int j = 0; j < 4; j++)
#pragma unroll
            for (int r = 0; r < 4; r++) acc[i][j][r] = 0.f;

    const int a_r  = warp_m * 64 + (lane & 15);
    const int a_cb = (lane >> 4) << 4;
    const int g    = lane >> 3;
    const int b_r  = warp_n * 32 + ((g >> 1) << 3) + (lane & 7);
    const int b_cb = (g & 1) << 4;

    int ld_r[4], ld_cb[4];
    uint32_t ld_sw[4];
#pragma unroll
    for (int it = 0; it < 4; it++) {
        int idx = it * 256 + tid;
        ld_r[it]  = idx >> 3;
        ld_cb[it] = (idx & 7) << 4;
        ld_sw[it] = swz((uint32_t)(ld_r[it] * 128 + ld_cb[it]));
    }

    auto issue = [&](int ch, int st) {
        const int k0 = ch * 64;
        const uint32_t sbase = sb + st * SM_STAGE;
#pragma unroll
        for (int it = 0; it < 4; it++) {
            const int r = ld_r[it], cb = ld_cb[it];
            const uint32_t sw = ld_sw[it];
            cp16(sbase + SM_A + sw, (const char*)(A  + (size_t)(rowBase + r) * K + k0) + cb);
            cp16(sbase + SM_B + sw, (const char*)(Bt + (size_t)(colBase + r) * K + k0) + cb);
        }
        cp_commit();
    };

    const int nChunks = K / 64;
    issue(0, 0);
    issue(1, 1);

    for (int ch = 0; ch < nChunks; ch++) {
        if (ch + 1 < nChunks) cp_wait<1>(); else cp_wait<0>();
        __syncthreads();
        if (ch + 2 < nChunks) issue(ch + 2, (ch + 2) % 3);

        const uint32_t sbase = sb + (ch % 3) * SM_STAGE;
#pragma unroll
        for (int ks = 0; ks < 4; ks++) {
            const int kb = ks * 32;
            uint32_t af[4][4];
#pragma unroll
            for (int mi = 0; mi < 4; mi++) {
                uint32_t off = swz((uint32_t)((a_r + mi * 16) * 128 + kb + a_cb));
                ldsm_x4(af[mi], sbase + SM_A + off);
            }
            uint32_t bf[2][4];
#pragma unroll
            for (int nt = 0; nt < 2; nt++) {
                uint32_t off = swz((uint32_t)((b_r + nt * 16) * 128 + kb + b_cb));
                ldsm_x4(bf[nt], sbase + SM_B + off);
            }
#pragma unroll
            for (int mi = 0; mi < 4; mi++)
#pragma unroll
                for (int nj = 0; nj < 4; nj++) {
                    const uint32_t* bj = &bf[nj >> 1][(nj & 1) * 2];
                    mma16816h(acc[mi][nj], af[mi], bj[0], bj[1]);
                }
        }
    }

    const int er = rowBase + warp_m * 64 + (lane >> 2);
    const int ec = colBase + warp_n * 32 + (lane & 3) * 2;

    if (MODE == 0) {
#pragma unroll
        for (int mi = 0; mi < 4; mi++) {
#pragma unroll
            for (int nj = 0; nj < 4; nj++) {
                const int c = ec + nj * 8;
                const float bx = __ldg(bias + c);
                const float by = __ldg(bias + c + 1);
                float2 v0 = { acc[mi][nj][0] + bx, acc[mi][nj][1] + by };
                float2 v1 = { acc[mi][nj][2] + bx, acc[mi][nj][3] + by };
                *(float2*)(Cout + (size_t)(er + mi * 16) * N + c) = v0;
                *(float2*)(Cout + (size_t)(er + mi * 16 + 8) * N + c) = v1;
            }
        }
    } else {
#pragma unroll
        for (int nj = 0; nj < 4; nj++) {
            const int c   = ec + nj * 8;
            const int sec = c >> 10;             // 0=q,1=k,2=v
            const int hh  = (c & 1023) >> 6;
            const int dd  = c & 63;
            const float sc = (sec == 0) ? QS : 1.f;
            const float bx = __ldg(bias + c)     * sc;
            const float by = __ldg(bias + c + 1) * sc;
            __half* dp = (sec == 0) ? qh : (sec == 1) ? kh : vh;
#pragma unroll
            for (int mi = 0; mi < 4; mi++) {
#pragma unroll
                for (int half = 0; half < 2; half++) {
                    const int r = er + mi * 16 + half * 8;
                    const int bb = r >> 11, tt = r & 2047;
                    const size_t dst = (((size_t)bb * H_ + hh) * T_ + tt) * D_ + dd;
                    float v0 = fmaf(acc[mi][nj][half * 2],     sc, bx);
                    float v1 = fmaf(acc[mi][nj][half * 2 + 1], sc, by);
                    *(__half2*)(dp + dst) = __floats2half2_rn(v0, v1);
                }
            }
        }
    }
}

// ---------------------------------------------------------------------------
// Flash attention (known-good R10/R12): fp16 single-term, m=0 softmax,
// 128 threads / 4 warps, 32 q-rows per warp, Q frags hoisted, per-warp
// masked-tile skip, 64-key tiles, cp.async 3-stage (16KB/stage).
// ---------------------------------------------------------------------------
#define FA_Q 0
#define FA_STAGE0 16384
#define FA_STSZ 16384
#define FA_ST(s) (FA_STAGE0 + (s) * FA_STSZ)
#define FA_K 0
#define FA_V 8192
#define FA_TOTAL (FA_STAGE0 + 3 * FA_STSZ)   // 65536

__global__ __launch_bounds__(128)
void flash_attn(const __half* __restrict__ qh, const __half* __restrict__ kh,
                const __half* __restrict__ vh, __half* __restrict__ att)
{
    extern __shared__ char smem[];
    const uint32_t sb = smem_to_u32(smem);
    const int tid = threadIdx.x, wid = tid >> 5, lane = tid & 31;
    const int h = blockIdx.y, b = blockIdx.z;
    const int qt = gridDim.x - 1 - blockIdx.x;    // big tiles first

    const size_t hoff = ((size_t)b * H_ + h) * T_ * D_;
    const char* qh_p = (const char*)(qh + hoff + (size_t)qt * 128 * D_);
    const char* kh_p = (const char*)(kh + hoff);
    const char* vh_p = (const char*)(vh + hoff);

    auto issue_kv = [&](int kt, int st) {
        const uint32_t sbase = sb + FA_ST(st);
#pragma unroll
        for (int it = 0; it < 4; it++) {
            int idx = it * 128 + tid;            // 0..511
            int r = idx >> 3, cb = (idx & 7) << 4;
            uint32_t sw = swz((uint32_t)(r * 128 + cb));
            size_t go = (size_t)(kt * 64 + r) * 128 + cb;    // bytes
            cp16(sbase + FA_K + sw, kh_p + go);
            cp16(sbase + FA_V + sw, vh_p + go);
        }
        cp_commit();
    };

    const int nkt = 2 * qt + 2;
    issue_kv(0, 0);
    issue_kv(1, 1);

    // Load Q tile into smem (plain stores), then hoist Q frags to registers.
#pragma unroll
    for (int it = 0; it < 8; it++) {
        int idx = it * 128 + tid;
        int r = idx >> 3, cb = (idx & 7) << 4;
        uint32_t sw = swz((uint32_t)(r * 128 + cb));
        *(uint4*)(smem + FA_Q + sw) = *(const uint4*)(qh_p + r * 128 + cb);
    }
    __syncthreads();

    const int a_r  = wid * 32 + (lane & 15);
    const int a_cb = (lane >> 4) << 4;
    uint32_t qf[4][2][4];                 // [ks][mi][reg], loop-invariant
#pragma unroll
    for (int ks = 0; ks < 4; ks++)
#pragma unroll
        for (int mi = 0; mi < 2; mi++) {
            uint32_t off = swz((uint32_t)((a_r + mi * 16) * 128 + ks * 32 + a_cb));
            ldsm_x4(qf[ks][mi], sb + FA_Q + off);
        }

    float o[2][8][4];
#pragma unroll
    for (int mi = 0; mi < 2; mi++)
#pragma unroll
        for (int nj = 0; nj < 8; nj++)
#pragma unroll
            for (int r = 0; r < 4; r++) o[mi][nj][r] = 0.f;
    float ls[4] = { 0.f, 0.f, 0.f, 0.f };

    const int g    = lane >> 3;
    const int b_r  = ((g >> 1) << 3) + (lane & 7);
    const int b_cb = (g & 1) << 4;
    const int vrow = ((lane >> 3) & 1) * 8 + (lane & 7);
    const int vcb  = ((lane >> 4) & 1) * 16;
    const int warpRowMax = qt * 128 + wid * 32 + 31;   // last row this warp owns

    for (int kt = 0; kt < nkt; kt++) {
        if (kt + 1 < nkt) cp_wait<1>(); else cp_wait<0>();
        __syncthreads();
        if (kt + 2 < nkt) issue_kv(kt + 2, (kt + 2) % 3);

        // Fully-masked tile for this warp? (all keys above the diagonal)
        if (kt * 64 > warpRowMax) continue;

        const uint32_t kv = sb + FA_ST(kt % 3);

        // ---- S = Q K^T (fp16 single), K frags shared across both Q frags ----
        float s[2][8][4];
#pragma unroll
        for (int mi = 0; mi < 2; mi++)
#pragma unroll
            for (int nj = 0; nj < 8; nj++)
#pragma unroll
                for (int r = 0; r < 4; r++) s[mi][nj][r] = 0.f;

#pragma unroll
        for (int ks = 0; ks < 4; ks++) {
            uint32_t kb[4][4];
#pragma unroll
            for (int nt = 0; nt < 4; nt++) {
                uint32_t off = swz((uint32_t)((b_r + nt * 16) * 128 + ks * 32 + b_cb));
                ldsm_x4(kb[nt], kv + FA_K + off);
            }
#pragma unroll
            for (int mi = 0; mi < 2; mi++)
#pragma unroll
                for (int nj = 0; nj < 8; nj++) {
                    const uint32_t* bj = &kb[nj >> 1][(nj & 1) * 2];
                    mma16816h(s[mi][nj], qf[ks][mi], bj[0], bj[1]);
                }
        }

        // ---- causal mask (diagonal tiles only) ----
        if (kt * 64 + 63 > qt * 128 + wid * 32) {
            const int colb = kt * 64 + (lane & 3) * 2;
#pragma unroll
            for (int mi = 0; mi < 2; mi++) {
                const int r0 = qt * 128 + wid * 32 + mi * 16 + (lane >> 2);
                const int r1 = r0 + 8;
#pragma unroll
                for (int nj = 0; nj < 8; nj++) {
                    const int c0 = colb + nj * 8, c1 = c0 + 1;
                    if (c0 > r0) s[mi][nj][0] = -1e30f;
                    if (c1 > r0) s[mi][nj][1] = -1e30f;
                    if (c0 > r1) s[mi][nj][2] = -1e30f;
                    if (c1 > r1) s[mi][nj][3] = -1e30f;
                }
            }
        }

        // ---- p = 2^s (no max), accumulate l, pack P fp16 ----
        uint32_t ph[2][4][4];
#pragma unroll
        for (int mi = 0; mi < 2; mi++) {
#pragma unroll
            for (int nj = 0; nj < 8; nj++) {
                float p0 = ex2(s[mi][nj][0]);
                float p1 = ex2(s[mi][nj][1]);
                float p2 = ex2(s[mi][nj][2]);
                float p3 = ex2(s[mi][nj][3]);
                s[mi][nj][0] = p0; s[mi][nj][1] = p1;
                s[mi][nj][2] = p2; s[mi][nj][3] = p3;
                ls[mi * 2 + 0] += p0 + p1;
                ls[mi * 2 + 1] += p2 + p3;
            }
#pragma unroll
            for (int ks = 0; ks < 4; ks++) {
#pragma unroll
                for (int rr = 0; rr < 4; rr++) {
                    const int nj = 2 * ks + (rr >> 1);
                    const int r0 = (rr & 1) * 2;
                    __half2 hh = __floats2half2_rn(s[mi][nj][r0], s[mi][nj][r0 + 1]);
                    ph[mi][ks][rr] = *(uint32_t*)&hh;
                }
            }
        }

        // ---- O += P V (fp16), V frags shared across both row-halves ----
#pragma unroll
        for (int ks = 0; ks < 4; ks++) {
#pragma unroll
            for (int nd = 0; nd < 4; nd++) {
                uint32_t vf[4];
                uint32_t off = swz((uint32_t)((ks * 16 + vrow) * 128 + nd * 32 + vcb));
                ldsm_x4_t(vf, kv + FA_V + off);
#pragma unroll
                for (int mi = 0; mi < 2; mi++) {
                    mma16816h(o[mi][nd * 2],     ph[mi][ks], vf[0], vf[1]);
                    mma16816h(o[mi][nd * 2 + 1], ph[mi][ks], vf[2], vf[3]);
                }
            }
        }
    }

    // ---- epilogue: reduce l across quad lanes, O / l -> fp16 att ----
    float inv[4];
#pragma unroll
    for (int si = 0; si < 4; si++) {
        float l = ls[si];
        l += __shfl_xor_sync(0xffffffffu, l, 1);
        l += __shfl_xor_sync(0xffffffffu, l, 2);
        inv[si] = 1.f / l;
    }
    const int ecb = h * 64 + (lane & 3) * 2;
#pragma unroll
    for (int mi = 0; mi < 2; mi++) {
        const int er0 = qt * 128 + wid * 32 + mi * 16 + (lane >> 2);
        const size_t row = (size_t)b * T_ + er0;
#pragma unroll
        for (int nj = 0; nj < 8; nj++) {
            *(__half2*)(att + row * C_ + ecb + nj * 8) =
                __floats2half2_rn(o[mi][nj][0] * inv[mi * 2],
                                  o[mi][nj][1] * inv[mi * 2]);
            *(__half2*)(att + (row + 8) * C_ + ecb + nj * 8) =
                __floats2half2_rn(o[mi][nj][2] * inv[mi * 2 + 1],
                                  o[mi][nj][3] * inv[mi * 2 + 1]);
        }
    }
}

// ---------------------------------------------------------------------------
// Launch sequence: prepass -> QKV GEMM -> flash -> proj GEMM
// ---------------------------------------------------------------------------
extern "C" void kernel_launch(void* const* d_in, const int* in_sizes, int n_in,
                              void* d_out, int out_size)
{
    const float* x      = (const float*)d_in[0];
    const float* w_qkv  = (const float*)d_in[1];
    const float* b_qkv  = (const float*)d_in[2];
    const float* w_proj = (const float*)d_in[3];
    const float* b_proj = (const float*)d_in[4];
    float* out = (float*)d_out;

    __half *xh, *wt, *wt2, *qh, *kh, *vh;
    cudaGetSymbolAddress((void**)&xh, g_xh);
    cudaGetSymbolAddress((void**)&wt, g_wt);
    cudaGetSymbolAddress((void**)&wt2, g_wt2);
    cudaGetSymbolAddress((void**)&qh, g_qh);
    cudaGetSymbolAddress((void**)&kh, g_kh);
    cudaGetSymbolAddress((void**)&vh, g_vh);

    cudaFuncSetAttribute(gemm_f16<0>, cudaFuncAttributeMaxDynamicSharedMemorySize, SM_TOTAL);
    cudaFuncSetAttribute(gemm_f16<1>, cudaFuncAttributeMaxDynamicSharedMemorySize, SM_TOTAL);
    cudaFuncSetAttribute(flash_attn, cudaFuncAttributeMaxDynamicSharedMemorySize, FA_TOTAL);

    // 1) fused prepass: x->fp16, w_qkv->W^T fp16, w_proj->W^T fp16
    prepass<<<PRE_TOTAL, 256>>>(x, w_qkv, w_proj, xh, wt, wt2);

    // 2) QKV GEMM -> per-head q (scaled)/k/v fp16
    {
        dim3 grid(N_QKV / 128, M_ROWS / 128);
        gemm_f16<1><<<grid, 256, SM_TOTAL>>>(xh, wt, b_qkv, nullptr,
                                             qh, kh, vh, M_ROWS, N_QKV, C_);
    }
    // 3) flash attention -> fp16 att (reuses xh)
    {
        dim3 grid(T_ / 128, H_, B_);
        flash_attn<<<grid, 128, FA_TOTAL>>>(qh, kh, vh, xh);
    }
    // 4) proj GEMM -> fp32 out
    {
        dim3 grid(C_ / 128, M_ROWS / 128);
        gemm_f16<0><<<grid, 256, SM_TOTAL>>>(xh, wt2, b_proj, out,
                                             nullptr, nullptr, nullptr,
                                             M_ROWS, C_, C_);
    }
}